// round 1
// baseline (speedup 1.0000x reference)
#include <cuda_runtime.h>
#include <math.h>

#define BATCH 32768
#define HID 256
#define NDOF 7
#define NTRIL 21
#define NHEAD 35   // 7 g + 7 Ld + 21 Lt

// ---------------- scratch (device globals; no allocation allowed) -------------
__device__ float g_h0  [BATCH * HID];
__device__ float g_sig0[BATCH * HID];
__device__ float g_h1  [BATCH * HID];
__device__ float g_sig1[BATCH * HID];
__device__ float g_sig2[BATCH * HID];
__device__ float g_D0  [(size_t)BATCH * 7 * HID];
__device__ float g_D1  [(size_t)BATCH * 7 * HID];
__device__ float g_X2  [(size_t)BATCH * 8 * HID];   // vec0 = h2, vec 1..7 = dh2/dq_t
__device__ float g_Yh  [(size_t)BATCH * 8 * NHEAD];

// ---------------- helpers ------------------------------------------------------
__device__ __forceinline__ float sp_f(float x) {          // softplus, jax-style
    return fmaxf(x, 0.0f) + log1pf(expf(-fabsf(x)));
}
__device__ __forceinline__ float sg_f(float x) {          // sigmoid
    return 1.0f / (1.0f + expf(-x));
}

// ---------------- K1: layer0 values -------------------------------------------
// pre0 = W0 q + b0 ; h0 = softplus ; sig0 = sigmoid
__global__ __launch_bounds__(256) void k_layer0(const float* __restrict__ q,
                                                const float* __restrict__ W0,
                                                const float* __restrict__ b0)
{
    __shared__ float qs[32][8];
    const int j  = threadIdx.x;          // hidden unit 0..255
    const int s0 = blockIdx.x * 32;      // sample base
    for (int idx = threadIdx.x; idx < 32 * 7; idx += 256)
        qs[idx / 7][idx % 7] = q[(s0 + idx / 7) * 7 + idx % 7];
    float w[7];
#pragma unroll
    for (int i = 0; i < 7; i++) w[i] = W0[j * 7 + i];
    const float bb = b0[j];
    __syncthreads();
    for (int s = 0; s < 32; s++) {
        float pre = bb;
#pragma unroll
        for (int i = 0; i < 7; i++) pre = fmaf(w[i], qs[s][i], pre);
        const int off = (s0 + s) * HID + j;
        g_h0[off]   = sp_f(pre);
        g_sig0[off] = sg_f(pre);
    }
}

// ---------------- K4: tangent seeds  D0[b][t][k] = sig0[b][k] * W0[k][t] -------
__global__ __launch_bounds__(256) void k_d0(const float* __restrict__ W0)
{
    const int idx = blockIdx.x * 256 + threadIdx.x;   // b*256 + k
    const int k = idx & 255;
    const int b = idx >> 8;
    const float s = g_sig0[idx];
#pragma unroll
    for (int t = 0; t < 7; t++)
        g_D0[(size_t)(b * 7 + t) * HID + k] = s * W0[k * 7 + t];
}

// ---------------- SGEMM: C[M,256] = A[M,256] @ W^T, fused epilogues ------------
// MODE 0: value layer1  : A=g_h0 ; out sp(pre)->g_h1, sig->g_sig1 (bias b1)
// MODE 2: value layer2  : A=g_h1 ; out sp(pre)->g_X2[vec0], sig->g_sig2 (bias b2)
// MODE 1: tangent layer1: A=g_D0 ; out = acc * g_sig1[b] -> g_D1
// MODE 3: tangent layer2: A=g_D1 ; out = acc * g_sig2[b] -> g_X2[vec 1+t]
template <int MODE>
__global__ __launch_bounds__(256, 2) void gemm_k(const float* __restrict__ W,
                                                 const float* __restrict__ bias)
{
    __shared__ float As[8][128];
    __shared__ float Ws[8][128];
    const int bx = blockIdx.x;      // N tile (0/1)
    const int by = blockIdx.y;      // M tile
    const int tid = threadIdx.x;
    const int tx = tid & 15;
    const int ty = tid >> 4;
    const int lrow = tid >> 1;          // 0..127
    const int lk4  = (tid & 1) * 4;     // 0 or 4

    const float* A;
    if      (MODE == 0) A = g_h0;
    else if (MODE == 2) A = g_h1;
    else if (MODE == 1) A = g_D0;
    else                A = g_D1;

    const float* Ap = A + (size_t)(by * 128 + lrow) * HID + lk4;
    const float* Wp = W + (size_t)(bx * 128 + lrow) * HID + lk4;

    float acc[8][8];
#pragma unroll
    for (int i = 0; i < 8; i++)
#pragma unroll
        for (int j = 0; j < 8; j++) acc[i][j] = 0.0f;

    float4 av = *(const float4*)(Ap);
    float4 wv = *(const float4*)(Wp);

    for (int kt = 0; kt < 256; kt += 8) {
        __syncthreads();
        As[lk4 + 0][lrow] = av.x; As[lk4 + 1][lrow] = av.y;
        As[lk4 + 2][lrow] = av.z; As[lk4 + 3][lrow] = av.w;
        Ws[lk4 + 0][lrow] = wv.x; Ws[lk4 + 1][lrow] = wv.y;
        Ws[lk4 + 2][lrow] = wv.z; Ws[lk4 + 3][lrow] = wv.w;
        __syncthreads();
        if (kt + 8 < 256) {                // prefetch next tile
            av = *(const float4*)(Ap + kt + 8);
            wv = *(const float4*)(Wp + kt + 8);
        }
#pragma unroll
        for (int kk = 0; kk < 8; kk++) {
            float ra[8], rb[8];
            *(float4*)(ra)     = *(const float4*)&As[kk][ty * 8];
            *(float4*)(ra + 4) = *(const float4*)&As[kk][ty * 8 + 4];
            *(float4*)(rb)     = *(const float4*)&Ws[kk][tx * 8];
            *(float4*)(rb + 4) = *(const float4*)&Ws[kk][tx * 8 + 4];
#pragma unroll
            for (int i = 0; i < 8; i++)
#pragma unroll
                for (int j = 0; j < 8; j++)
                    acc[i][j] = fmaf(ra[i], rb[j], acc[i][j]);
        }
    }

    const int m0 = by * 128 + ty * 8;
    const int j0 = bx * 128 + tx * 8;
#pragma unroll
    for (int i = 0; i < 8; i++) {
        const int m = m0 + i;
        int mb = 0, mt = 0;
        if (MODE == 1 || MODE == 3) { mb = m / 7; mt = m - mb * 7; }
#pragma unroll
        for (int j = 0; j < 8; j++) {
            const int col = j0 + j;
            const float v = acc[i][j];
            if (MODE == 0) {
                const float pre = v + bias[col];
                g_h1  [(size_t)m * HID + col] = sp_f(pre);
                g_sig1[(size_t)m * HID + col] = sg_f(pre);
            } else if (MODE == 2) {
                const float pre = v + bias[col];
                g_X2  [(size_t)m * 8 * HID + col] = sp_f(pre);
                g_sig2[(size_t)m * HID + col]     = sg_f(pre);
            } else if (MODE == 1) {
                g_D1[(size_t)m * HID + col] = v * g_sig1[(size_t)mb * HID + col];
            } else {
                g_X2[((size_t)mb * 8 + 1 + mt) * HID + col] =
                    v * g_sig2[(size_t)mb * HID + col];
            }
        }
    }
}

// ---------------- K7: heads GEMM  Yh[m][r] = X2[m] . Whead[r] (+bias on value rows)
__global__ __launch_bounds__(256) void k_heads(const float* __restrict__ Wg,
                                               const float* __restrict__ bg,
                                               const float* __restrict__ Wld,
                                               const float* __restrict__ bld,
                                               const float* __restrict__ Wlt,
                                               const float* __restrict__ blt)
{
    __shared__ float wsm[NHEAD][HID];
    __shared__ float bsm[NHEAD];
    const int tid = threadIdx.x;
    float* wf = &wsm[0][0];
    for (int i = tid; i < 7 * HID; i += 256)  wf[i] = Wg[i];
    for (int i = tid; i < 7 * HID; i += 256)  wf[7 * HID + i] = Wld[i];
    for (int i = tid; i < 21 * HID; i += 256) wf[14 * HID + i] = Wlt[i];
    if (tid < 7)  { bsm[tid] = bg[tid]; bsm[7 + tid] = bld[tid]; }
    if (tid < 21) bsm[14 + tid] = blt[tid];
    __syncthreads();

    const int warp = tid >> 5, lane = tid & 31;
    for (int rr = 0; rr < 8; rr++) {
        const int m = blockIdx.x * 64 + warp * 8 + rr;
        const float* xg = g_X2 + (size_t)m * HID;
        float x[8];
        *(float4*)(x)     = *(const float4*)(xg + lane * 8);
        *(float4*)(x + 4) = *(const float4*)(xg + lane * 8 + 4);
        const bool valrow = ((m & 7) == 0);
#pragma unroll
        for (int r = 0; r < NHEAD; r++) {
            float w[8];
            *(float4*)(w)     = *(const float4*)(&wsm[r][lane * 8]);
            *(float4*)(w + 4) = *(const float4*)(&wsm[r][lane * 8 + 4]);
            float p = 0.0f;
#pragma unroll
            for (int u = 0; u < 8; u++) p = fmaf(w[u], x[u], p);
            p += __shfl_xor_sync(0xffffffff, p, 16);
            p += __shfl_xor_sync(0xffffffff, p, 8);
            p += __shfl_xor_sync(0xffffffff, p, 4);
            p += __shfl_xor_sync(0xffffffff, p, 2);
            p += __shfl_xor_sync(0xffffffff, p, 1);
            if (lane == 0)
                g_Yh[(size_t)m * NHEAD + r] = p + (valrow ? bsm[r] : 0.0f);
        }
    }
}

// ---------------- K8: per-sample dynamics --------------------------------------
__global__ __launch_bounds__(128) void k_dyn(const float* __restrict__ qd_g,
                                             const float* __restrict__ qdd_g,
                                             const float* __restrict__ fd,
                                             const float* __restrict__ fc,
                                             const float* __restrict__ fs,
                                             const float* __restrict__ fv,
                                             float* __restrict__ out)
{
    const int b = blockIdx.x * 128 + threadIdx.x;
    if (b >= BATCH) return;
    const int R[21]  = {1,2,2,3,3,3,4,4,4,4,5,5,5,5,5,6,6,6,6,6,6};
    const int Cc[21] = {0,0,1,0,1,2,0,1,2,3,0,1,2,3,4,0,1,2,3,4,5};

    const float* Y = g_Yh + (size_t)b * 8 * NHEAD;
    float qd[7], qdd[7], gv[7], ldr[7], sigd[7];
#pragma unroll
    for (int i = 0; i < 7; i++) {
        qd[i]  = qd_g [b * 7 + i];
        qdd[i] = qdd_g[b * 7 + i];
        gv[i]  = Y[i];
        ldr[i] = Y[7 + i];
    }

    float L[7][7];
#pragma unroll
    for (int i = 0; i < 7; i++)
#pragma unroll
        for (int j = 0; j < 7; j++) L[i][j] = 0.0f;
#pragma unroll
    for (int i = 0; i < 7; i++) {
        L[i][i]  = sp_f(ldr[i]) + 1e-3f;
        sigd[i]  = sg_f(ldr[i]);
    }
#pragma unroll
    for (int p = 0; p < 21; p++) L[R[p]][Cc[p]] = Y[14 + p];

    // a = L^T qd
    float a[7];
#pragma unroll
    for (int j = 0; j < 7; j++) {
        float s = 0.0f;
#pragma unroll
        for (int i = 0; i < 7; i++) if (i >= j) s = fmaf(L[i][j], qd[i], s);
        a[j] = s;
    }

    float Ldt[7][7];
#pragma unroll
    for (int i = 0; i < 7; i++)
#pragma unroll
        for (int j = 0; j < 7; j++) Ldt[i][j] = 0.0f;

    float svec[7];
#pragma unroll
    for (int c = 0; c < 7; c++) {
        const float* Yc = Y + (c + 1) * NHEAD;
        float dL[7][7];
#pragma unroll
        for (int i = 0; i < 7; i++)
#pragma unroll
            for (int j = 0; j < 7; j++) dL[i][j] = 0.0f;
#pragma unroll
        for (int i = 0; i < 7; i++) dL[i][i] = sigd[i] * Yc[7 + i];
#pragma unroll
        for (int p = 0; p < 21; p++) dL[R[p]][Cc[p]] = Yc[14 + p];
#pragma unroll
        for (int i = 0; i < 7; i++)
#pragma unroll
            for (int j = 0; j < 7; j++) if (j <= i)
                Ldt[i][j] = fmaf(qd[c], dL[i][j], Ldt[i][j]);
        float sc = 0.0f;
#pragma unroll
        for (int j = 0; j < 7; j++) {
            float v = 0.0f;
#pragma unroll
            for (int i = 0; i < 7; i++) if (i >= j) v = fmaf(qd[i], dL[i][j], v);
            sc = fmaf(v, a[j], sc);
        }
        svec[c] = 2.0f * sc;
    }

    // b2 = Ldt^T qd
    float b2[7];
#pragma unroll
    for (int j = 0; j < 7; j++) {
        float s = 0.0f;
#pragma unroll
        for (int i = 0; i < 7; i++) if (i >= j) s = fmaf(Ldt[i][j], qd[i], s);
        b2[j] = s;
    }

    float cor[7];
#pragma unroll
    for (int i = 0; i < 7; i++) {
        float s = 0.0f;
#pragma unroll
        for (int j = 0; j < 7; j++) if (j <= i) s = fmaf(L[i][j], b2[j], s);
#pragma unroll
        for (int j = 0; j < 7; j++) if (j <= i) s = fmaf(Ldt[i][j], a[j], s);
        cor[i] = s - 0.5f * svec[i];
    }

    float Hm[7][7];
#pragma unroll
    for (int i = 0; i < 7; i++)
#pragma unroll
        for (int k = 0; k < 7; k++) {
            float s = 0.0f;
#pragma unroll
            for (int j = 0; j < 7; j++) if (j <= i && j <= k)
                s = fmaf(L[i][j], L[k][j], s);
            Hm[i][k] = s;
        }

    float fric[7];
#pragma unroll
    for (int i = 0; i < 7; i++) {
        const float fvc = fmaxf(fv[i], 1e-3f);
        fric[i] = (fc[i] + fs[i] * expf(-qd[i] * qd[i] / fvc)) *
                      tanhf(100.0f * qd[i]) + fd[i] * qd[i];
    }

    float tau[7];
#pragma unroll
    for (int i = 0; i < 7; i++) {
        float s = 0.0f;
#pragma unroll
        for (int k = 0; k < 7; k++) s = fmaf(Hm[i][k], qdd[k], s);
        tau[i] = s + cor[i] + gv[i] + fric[i];
    }

    // outputs: tau | Hm | c | g | tau_fric | Ld_raw   (flattened, concatenated)
    const int Bc = BATCH;
#pragma unroll
    for (int i = 0; i < 7; i++) out[b * 7 + i] = tau[i];
#pragma unroll
    for (int i = 0; i < 7; i++)
#pragma unroll
        for (int k = 0; k < 7; k++) out[7 * Bc + b * 49 + i * 7 + k] = Hm[i][k];
#pragma unroll
    for (int i = 0; i < 7; i++) out[56 * Bc + b * 7 + i] = cor[i];
#pragma unroll
    for (int i = 0; i < 7; i++) out[63 * Bc + b * 7 + i] = gv[i];
#pragma unroll
    for (int i = 0; i < 7; i++) out[70 * Bc + b * 7 + i] = fric[i];
#pragma unroll
    for (int i = 0; i < 7; i++) out[77 * Bc + b * 7 + i] = ldr[i];
}

// ---------------- launch --------------------------------------------------------
extern "C" void kernel_launch(void* const* d_in, const int* in_sizes, int n_in,
                              void* d_out, int out_size)
{
    (void)in_sizes; (void)n_in; (void)out_size;
    const float* q   = (const float*)d_in[0];
    const float* qd  = (const float*)d_in[1];
    const float* qdd = (const float*)d_in[2];
    const float* W0  = (const float*)d_in[3];
    const float* b0  = (const float*)d_in[4];
    const float* W1  = (const float*)d_in[5];
    const float* b1  = (const float*)d_in[6];
    const float* W2  = (const float*)d_in[7];
    const float* b2  = (const float*)d_in[8];
    const float* Wg  = (const float*)d_in[9];
    const float* bg  = (const float*)d_in[10];
    const float* Wld = (const float*)d_in[11];
    const float* bld = (const float*)d_in[12];
    const float* Wlt = (const float*)d_in[13];
    const float* blt = (const float*)d_in[14];
    const float* fd  = (const float*)d_in[15];
    const float* fc  = (const float*)d_in[16];
    const float* fs  = (const float*)d_in[17];
    const float* fv  = (const float*)d_in[18];
    float* out = (float*)d_out;

    k_layer0<<<BATCH / 32, 256>>>(q, W0, b0);
    gemm_k<0><<<dim3(2, BATCH / 128), 256>>>(W1, b1);           // h1, sig1
    gemm_k<2><<<dim3(2, BATCH / 128), 256>>>(W2, b2);           // h2 -> X2, sig2
    k_d0<<<BATCH, 256>>>(W0);                                    // D0 seeds
    gemm_k<1><<<dim3(2, (BATCH * 7) / 128), 256>>>(W1, nullptr); // D1
    gemm_k<3><<<dim3(2, (BATCH * 7) / 128), 256>>>(W2, nullptr); // D2 -> X2
    k_heads<<<(BATCH * 8) / 64, 256>>>(Wg, bg, Wld, bld, Wlt, blt);
    k_dyn<<<(BATCH + 127) / 128, 128>>>(qd, qdd, fd, fc, fs, fv, out);
}

// round 2
// speedup vs baseline: 1.0464x; 1.0464x over previous
#include <cuda_runtime.h>
#include <math.h>

#define BATCH 32768
#define HID 256
#define NDOF 7
#define NTRIL 21
#define NHEAD 35   // 7 g + 7 Ld + 21 Lt

// ---------------- scratch (device globals; no allocation allowed) -------------
__device__ float g_h0  [BATCH * HID];
__device__ float g_sig0[BATCH * HID];
__device__ float g_h1  [BATCH * HID];
__device__ float g_sig1[BATCH * HID];
__device__ float g_sig2[BATCH * HID];
__device__ float g_D0  [(size_t)BATCH * 7 * HID];
__device__ float g_D1  [(size_t)BATCH * 7 * HID];
__device__ float g_X2  [(size_t)BATCH * 8 * HID];   // vec0 = h2, vec 1..7 = dh2/dq_t
__device__ float g_Yh  [(size_t)BATCH * 8 * NHEAD];

// ---------------- helpers ------------------------------------------------------
__device__ __forceinline__ float sp_f(float x) {          // softplus, jax-style
    return fmaxf(x, 0.0f) + log1pf(expf(-fabsf(x)));
}
__device__ __forceinline__ float sg_f(float x) {          // sigmoid
    return 1.0f / (1.0f + expf(-x));
}

// packed fp32x2 FMA (sm_100+): d = a*b + d, lane-wise on 64-bit packed pairs
__device__ __forceinline__ void ffma2(unsigned long long& d,
                                      unsigned long long a,
                                      unsigned long long b) {
    asm("fma.rn.f32x2 %0, %1, %2, %0;" : "+l"(d) : "l"(a), "l"(b));
}
__device__ __forceinline__ unsigned long long dup2(float x) {
    unsigned long long r;
    asm("mov.b64 %0, {%1, %1};" : "=l"(r) : "f"(x));
    return r;
}
__device__ __forceinline__ float2 unpk2(unsigned long long v) {
    float2 r;
    asm("mov.b64 {%0, %1}, %2;" : "=f"(r.x), "=f"(r.y) : "l"(v));
    return r;
}

// ---------------- K1: layer0 values -------------------------------------------
__global__ __launch_bounds__(256) void k_layer0(const float* __restrict__ q,
                                                const float* __restrict__ W0,
                                                const float* __restrict__ b0)
{
    __shared__ float qs[32][8];
    const int j  = threadIdx.x;          // hidden unit 0..255
    const int s0 = blockIdx.x * 32;      // sample base
    for (int idx = threadIdx.x; idx < 32 * 7; idx += 256)
        qs[idx / 7][idx % 7] = q[(s0 + idx / 7) * 7 + idx % 7];
    float w[7];
#pragma unroll
    for (int i = 0; i < 7; i++) w[i] = W0[j * 7 + i];
    const float bb = b0[j];
    __syncthreads();
    for (int s = 0; s < 32; s++) {
        float pre = bb;
#pragma unroll
        for (int i = 0; i < 7; i++) pre = fmaf(w[i], qs[s][i], pre);
        const int off = (s0 + s) * HID + j;
        g_h0[off]   = sp_f(pre);
        g_sig0[off] = sg_f(pre);
    }
}

// ---------------- K4: tangent seeds  D0[b][t][k] = sig0[b][k] * W0[k][t] -------
__global__ __launch_bounds__(256) void k_d0(const float* __restrict__ W0)
{
    const int idx = blockIdx.x * 256 + threadIdx.x;   // b*256 + k
    const int k = idx & 255;
    const int b = idx >> 8;
    const float s = g_sig0[idx];
#pragma unroll
    for (int t = 0; t < 7; t++)
        g_D0[(size_t)(b * 7 + t) * HID + k] = s * W0[k * 7 + t];
}

// ---------------- SGEMM: C[M,256] = A[M,256] @ W^T, fused epilogues ------------
// MODE 0: value layer1  : A=g_h0 ; out sp(pre)->g_h1, sig->g_sig1 (bias b1)
// MODE 2: value layer2  : A=g_h1 ; out sp(pre)->g_X2[vec0], sig->g_sig2 (bias b2)
// MODE 1: tangent layer1: A=g_D0 ; out = acc * g_sig1[b] -> g_D1
// MODE 3: tangent layer2: A=g_D1 ; out = acc * g_sig2[b] -> g_X2[vec 1+t]
template <int MODE>
__global__ __launch_bounds__(256, 2) void gemm_k(const float* __restrict__ W,
                                                 const float* __restrict__ bias)
{
    __shared__ float As[8][128];
    __shared__ float Ws[8][128];
    const int bx = blockIdx.x;      // N tile (0/1)
    const int by = blockIdx.y;      // M tile
    const int tid = threadIdx.x;
    const int tx = tid & 15;
    const int ty = tid >> 4;
    const int lrow = tid >> 1;          // 0..127
    const int lk4  = (tid & 1) * 4;     // 0 or 4

    const float* A;
    if      (MODE == 0) A = g_h0;
    else if (MODE == 2) A = g_h1;
    else if (MODE == 1) A = g_D0;
    else                A = g_D1;

    const float* Ap = A + (size_t)(by * 128 + lrow) * HID + lk4;
    const float* Wp = W + (size_t)(bx * 128 + lrow) * HID + lk4;

    // packed accumulators: acc2[i][jj] holds cols (2jj, 2jj+1) for row i
    unsigned long long acc2[8][4];
#pragma unroll
    for (int i = 0; i < 8; i++)
#pragma unroll
        for (int j = 0; j < 4; j++) acc2[i][j] = 0ULL;

    float4 av = *(const float4*)(Ap);
    float4 wv = *(const float4*)(Wp);

    for (int kt = 0; kt < 256; kt += 8) {
        __syncthreads();
        As[lk4 + 0][lrow] = av.x; As[lk4 + 1][lrow] = av.y;
        As[lk4 + 2][lrow] = av.z; As[lk4 + 3][lrow] = av.w;
        Ws[lk4 + 0][lrow] = wv.x; Ws[lk4 + 1][lrow] = wv.y;
        Ws[lk4 + 2][lrow] = wv.z; Ws[lk4 + 3][lrow] = wv.w;
        __syncthreads();
        if (kt + 8 < 256) {                // prefetch next tile
            av = *(const float4*)(Ap + kt + 8);
            wv = *(const float4*)(Wp + kt + 8);
        }
#pragma unroll
        for (int kk = 0; kk < 8; kk++) {
            float ra[8];
            *(float4*)(ra)     = *(const float4*)&As[kk][ty * 8];
            *(float4*)(ra + 4) = *(const float4*)&As[kk][ty * 8 + 4];
            unsigned long long rb2[4];
            {
                const ulonglong2 t0 = *(const ulonglong2*)&Ws[kk][tx * 8];
                const ulonglong2 t1 = *(const ulonglong2*)&Ws[kk][tx * 8 + 4];
                rb2[0] = t0.x; rb2[1] = t0.y; rb2[2] = t1.x; rb2[3] = t1.y;
            }
#pragma unroll
            for (int i = 0; i < 8; i++) {
                const unsigned long long ai = dup2(ra[i]);
#pragma unroll
                for (int j = 0; j < 4; j++) ffma2(acc2[i][j], ai, rb2[j]);
            }
        }
    }

    const int m0 = by * 128 + ty * 8;
    const int j0 = bx * 128 + tx * 8;
#pragma unroll
    for (int i = 0; i < 8; i++) {
        const int m = m0 + i;
        int mb = 0, mt = 0;
        if (MODE == 1 || MODE == 3) { mb = m / 7; mt = m - mb * 7; }
        float accr[8];
#pragma unroll
        for (int jj = 0; jj < 4; jj++) {
            const float2 p = unpk2(acc2[i][jj]);
            accr[2 * jj] = p.x; accr[2 * jj + 1] = p.y;
        }
#pragma unroll
        for (int j = 0; j < 8; j++) {
            const int col = j0 + j;
            const float v = accr[j];
            if (MODE == 0) {
                const float pre = v + bias[col];
                g_h1  [(size_t)m * HID + col] = sp_f(pre);
                g_sig1[(size_t)m * HID + col] = sg_f(pre);
            } else if (MODE == 2) {
                const float pre = v + bias[col];
                g_X2  [(size_t)m * 8 * HID + col] = sp_f(pre);
                g_sig2[(size_t)m * HID + col]     = sg_f(pre);
            } else if (MODE == 1) {
                g_D1[(size_t)m * HID + col] = v * g_sig1[(size_t)mb * HID + col];
            } else {
                g_X2[((size_t)mb * 8 + 1 + mt) * HID + col] =
                    v * g_sig2[(size_t)mb * HID + col];
            }
        }
    }
}

// ---------------- K7: heads GEMM  Yh[m][r] = X2[m] . Whead[r] (+bias on value rows)
__global__ __launch_bounds__(256) void k_heads(const float* __restrict__ Wg,
                                               const float* __restrict__ bg,
                                               const float* __restrict__ Wld,
                                               const float* __restrict__ bld,
                                               const float* __restrict__ Wlt,
                                               const float* __restrict__ blt)
{
    __shared__ float wsm[NHEAD][HID];
    __shared__ float bsm[NHEAD];
    const int tid = threadIdx.x;
    float* wf = &wsm[0][0];
    for (int i = tid; i < 7 * HID; i += 256)  wf[i] = Wg[i];
    for (int i = tid; i < 7 * HID; i += 256)  wf[7 * HID + i] = Wld[i];
    for (int i = tid; i < 21 * HID; i += 256) wf[14 * HID + i] = Wlt[i];
    if (tid < 7)  { bsm[tid] = bg[tid]; bsm[7 + tid] = bld[tid]; }
    if (tid < 21) bsm[14 + tid] = blt[tid];
    __syncthreads();

    const int warp = tid >> 5, lane = tid & 31;
    for (int rr = 0; rr < 8; rr++) {
        const int m = blockIdx.x * 64 + warp * 8 + rr;
        const float* xg = g_X2 + (size_t)m * HID;
        float x[8];
        *(float4*)(x)     = *(const float4*)(xg + lane * 8);
        *(float4*)(x + 4) = *(const float4*)(xg + lane * 8 + 4);
        const bool valrow = ((m & 7) == 0);
#pragma unroll
        for (int r = 0; r < NHEAD; r++) {
            float w[8];
            *(float4*)(w)     = *(const float4*)(&wsm[r][lane * 8]);
            *(float4*)(w + 4) = *(const float4*)(&wsm[r][lane * 8 + 4]);
            float p = 0.0f;
#pragma unroll
            for (int u = 0; u < 8; u++) p = fmaf(w[u], x[u], p);
            p += __shfl_xor_sync(0xffffffff, p, 16);
            p += __shfl_xor_sync(0xffffffff, p, 8);
            p += __shfl_xor_sync(0xffffffff, p, 4);
            p += __shfl_xor_sync(0xffffffff, p, 2);
            p += __shfl_xor_sync(0xffffffff, p, 1);
            if (lane == 0)
                g_Yh[(size_t)m * NHEAD + r] = p + (valrow ? bsm[r] : 0.0f);
        }
    }
}

// ---------------- K8: per-sample dynamics --------------------------------------
__global__ __launch_bounds__(128) void k_dyn(const float* __restrict__ qd_g,
                                             const float* __restrict__ qdd_g,
                                             const float* __restrict__ fd,
                                             const float* __restrict__ fc,
                                             const float* __restrict__ fs,
                                             const float* __restrict__ fv,
                                             float* __restrict__ out)
{
    const int b = blockIdx.x * 128 + threadIdx.x;
    if (b >= BATCH) return;
    const int R[21]  = {1,2,2,3,3,3,4,4,4,4,5,5,5,5,5,6,6,6,6,6,6};
    const int Cc[21] = {0,0,1,0,1,2,0,1,2,3,0,1,2,3,4,0,1,2,3,4,5};

    const float* Y = g_Yh + (size_t)b * 8 * NHEAD;
    float qd[7], qdd[7], gv[7], ldr[7], sigd[7];
#pragma unroll
    for (int i = 0; i < 7; i++) {
        qd[i]  = qd_g [b * 7 + i];
        qdd[i] = qdd_g[b * 7 + i];
        gv[i]  = Y[i];
        ldr[i] = Y[7 + i];
    }

    float L[7][7];
#pragma unroll
    for (int i = 0; i < 7; i++)
#pragma unroll
        for (int j = 0; j < 7; j++) L[i][j] = 0.0f;
#pragma unroll
    for (int i = 0; i < 7; i++) {
        L[i][i]  = sp_f(ldr[i]) + 1e-3f;
        sigd[i]  = sg_f(ldr[i]);
    }
#pragma unroll
    for (int p = 0; p < 21; p++) L[R[p]][Cc[p]] = Y[14 + p];

    // a = L^T qd
    float a[7];
#pragma unroll
    for (int j = 0; j < 7; j++) {
        float s = 0.0f;
#pragma unroll
        for (int i = 0; i < 7; i++) if (i >= j) s = fmaf(L[i][j], qd[i], s);
        a[j] = s;
    }

    float Ldt[7][7];
#pragma unroll
    for (int i = 0; i < 7; i++)
#pragma unroll
        for (int j = 0; j < 7; j++) Ldt[i][j] = 0.0f;

    float svec[7];
#pragma unroll
    for (int c = 0; c < 7; c++) {
        const float* Yc = Y + (c + 1) * NHEAD;
        float dL[7][7];
#pragma unroll
        for (int i = 0; i < 7; i++)
#pragma unroll
            for (int j = 0; j < 7; j++) dL[i][j] = 0.0f;
#pragma unroll
        for (int i = 0; i < 7; i++) dL[i][i] = sigd[i] * Yc[7 + i];
#pragma unroll
        for (int p = 0; p < 21; p++) dL[R[p]][Cc[p]] = Yc[14 + p];
#pragma unroll
        for (int i = 0; i < 7; i++)
#pragma unroll
            for (int j = 0; j < 7; j++) if (j <= i)
                Ldt[i][j] = fmaf(qd[c], dL[i][j], Ldt[i][j]);
        float sc = 0.0f;
#pragma unroll
        for (int j = 0; j < 7; j++) {
            float v = 0.0f;
#pragma unroll
            for (int i = 0; i < 7; i++) if (i >= j) v = fmaf(qd[i], dL[i][j], v);
            sc = fmaf(v, a[j], sc);
        }
        svec[c] = 2.0f * sc;
    }

    // b2 = Ldt^T qd
    float b2[7];
#pragma unroll
    for (int j = 0; j < 7; j++) {
        float s = 0.0f;
#pragma unroll
        for (int i = 0; i < 7; i++) if (i >= j) s = fmaf(Ldt[i][j], qd[i], s);
        b2[j] = s;
    }

    float cor[7];
#pragma unroll
    for (int i = 0; i < 7; i++) {
        float s = 0.0f;
#pragma unroll
        for (int j = 0; j < 7; j++) if (j <= i) s = fmaf(L[i][j], b2[j], s);
#pragma unroll
        for (int j = 0; j < 7; j++) if (j <= i) s = fmaf(Ldt[i][j], a[j], s);
        cor[i] = s - 0.5f * svec[i];
    }

    float Hm[7][7];
#pragma unroll
    for (int i = 0; i < 7; i++)
#pragma unroll
        for (int k = 0; k < 7; k++) {
            float s = 0.0f;
#pragma unroll
            for (int j = 0; j < 7; j++) if (j <= i && j <= k)
                s = fmaf(L[i][j], L[k][j], s);
            Hm[i][k] = s;
        }

    float fric[7];
#pragma unroll
    for (int i = 0; i < 7; i++) {
        const float fvc = fmaxf(fv[i], 1e-3f);
        fric[i] = (fc[i] + fs[i] * expf(-qd[i] * qd[i] / fvc)) *
                      tanhf(100.0f * qd[i]) + fd[i] * qd[i];
    }

    float tau[7];
#pragma unroll
    for (int i = 0; i < 7; i++) {
        float s = 0.0f;
#pragma unroll
        for (int k = 0; k < 7; k++) s = fmaf(Hm[i][k], qdd[k], s);
        tau[i] = s + cor[i] + gv[i] + fric[i];
    }

    // outputs: tau | Hm | c | g | tau_fric | Ld_raw   (flattened, concatenated)
    const int Bc = BATCH;
#pragma unroll
    for (int i = 0; i < 7; i++) out[b * 7 + i] = tau[i];
#pragma unroll
    for (int i = 0; i < 7; i++)
#pragma unroll
        for (int k = 0; k < 7; k++) out[7 * Bc + b * 49 + i * 7 + k] = Hm[i][k];
#pragma unroll
    for (int i = 0; i < 7; i++) out[56 * Bc + b * 7 + i] = cor[i];
#pragma unroll
    for (int i = 0; i < 7; i++) out[63 * Bc + b * 7 + i] = gv[i];
#pragma unroll
    for (int i = 0; i < 7; i++) out[70 * Bc + b * 7 + i] = fric[i];
#pragma unroll
    for (int i = 0; i < 7; i++) out[77 * Bc + b * 7 + i] = ldr[i];
}

// ---------------- launch --------------------------------------------------------
extern "C" void kernel_launch(void* const* d_in, const int* in_sizes, int n_in,
                              void* d_out, int out_size)
{
    (void)in_sizes; (void)n_in; (void)out_size;
    const float* q   = (const float*)d_in[0];
    const float* qd  = (const float*)d_in[1];
    const float* qdd = (const float*)d_in[2];
    const float* W0  = (const float*)d_in[3];
    const float* b0  = (const float*)d_in[4];
    const float* W1  = (const float*)d_in[5];
    const float* b1  = (const float*)d_in[6];
    const float* W2  = (const float*)d_in[7];
    const float* b2  = (const float*)d_in[8];
    const float* Wg  = (const float*)d_in[9];
    const float* bg  = (const float*)d_in[10];
    const float* Wld = (const float*)d_in[11];
    const float* bld = (const float*)d_in[12];
    const float* Wlt = (const float*)d_in[13];
    const float* blt = (const float*)d_in[14];
    const float* fd  = (const float*)d_in[15];
    const float* fc  = (const float*)d_in[16];
    const float* fs  = (const float*)d_in[17];
    const float* fv  = (const float*)d_in[18];
    float* out = (float*)d_out;

    k_layer0<<<BATCH / 32, 256>>>(q, W0, b0);
    gemm_k<0><<<dim3(2, BATCH / 128), 256>>>(W1, b1);           // h1, sig1
    gemm_k<2><<<dim3(2, BATCH / 128), 256>>>(W2, b2);           // h2 -> X2, sig2
    k_d0<<<BATCH, 256>>>(W0);                                    // D0 seeds
    gemm_k<1><<<dim3(2, (BATCH * 7) / 128), 256>>>(W1, nullptr); // D1
    gemm_k<3><<<dim3(2, (BATCH * 7) / 128), 256>>>(W2, nullptr); // D2 -> X2
    k_heads<<<(BATCH * 8) / 64, 256>>>(Wg, bg, Wld, bld, Wlt, blt);
    k_dyn<<<(BATCH + 127) / 128, 128>>>(qd, qdd, fd, fc, fs, fv, out);
}

// round 3
// speedup vs baseline: 1.4528x; 1.3883x over previous
#include <cuda_runtime.h>
#include <cuda_bf16.h>
#include <math.h>
#include <stdint.h>

#define BATCH 32768
#define HID 256
#define NDOF 7
#define NTRIL 21
#define NHEAD 35   // 7 g + 7 Ld + 21 Lt

typedef __nv_bfloat16 bf16;

// ---------------- scratch (device globals; no allocation allowed) -------------
// activations / tangents stored as bf16 (hi, lo) pairs — same bytes as fp32
__device__ bf16  g_h0h [BATCH * HID];
__device__ bf16  g_h0l [BATCH * HID];
__device__ bf16  g_h1h [BATCH * HID];
__device__ bf16  g_h1l [BATCH * HID];
__device__ bf16  g_D0h [(size_t)BATCH * 7 * HID];
__device__ bf16  g_D0l [(size_t)BATCH * 7 * HID];
__device__ bf16  g_D1h [(size_t)BATCH * 7 * HID];
__device__ bf16  g_D1l [(size_t)BATCH * 7 * HID];
__device__ float g_sig0[BATCH * HID];
__device__ float g_sig1[BATCH * HID];
__device__ float g_sig2[BATCH * HID];
__device__ float g_X2  [(size_t)BATCH * 8 * HID];   // vec0 = h2, vec 1..7 = dh2/dq_t
__device__ float g_Yh  [(size_t)BATCH * 8 * NHEAD];
// weight splits
__device__ bf16  g_W1h[HID * HID];
__device__ bf16  g_W1l[HID * HID];
__device__ bf16  g_W2h[HID * HID];
__device__ bf16  g_W2l[HID * HID];

// ---------------- helpers ------------------------------------------------------
__device__ __forceinline__ float sp_f(float x) {          // softplus, jax-style
    return fmaxf(x, 0.0f) + log1pf(expf(-fabsf(x)));
}
__device__ __forceinline__ float sg_f(float x) {          // sigmoid
    return 1.0f / (1.0f + expf(-x));
}
__device__ __forceinline__ void split_bf(float x, bf16& h, bf16& l) {
    h = __float2bfloat16_rn(x);
    l = __float2bfloat16_rn(x - __bfloat162float(h));
}
__device__ __forceinline__ void mma16816(float c[4], const uint32_t a[4],
                                         uint32_t b0, uint32_t b1) {
    asm volatile(
        "mma.sync.aligned.m16n8k16.row.col.f32.bf16.bf16.f32 "
        "{%0,%1,%2,%3}, {%4,%5,%6,%7}, {%8,%9}, {%0,%1,%2,%3};"
        : "+f"(c[0]), "+f"(c[1]), "+f"(c[2]), "+f"(c[3])
        : "r"(a[0]), "r"(a[1]), "r"(a[2]), "r"(a[3]), "r"(b0), "r"(b1));
}

// ---------------- K0: weight hi/lo split ---------------------------------------
__global__ __launch_bounds__(256) void k_wsplit(const float* __restrict__ W1,
                                                const float* __restrict__ W2)
{
    const int i = blockIdx.x * 256 + threadIdx.x;   // 0 .. 65535
    split_bf(W1[i], g_W1h[i], g_W1l[i]);
    split_bf(W2[i], g_W2h[i], g_W2l[i]);
}

// ---------------- K1: layer0 values -------------------------------------------
__global__ __launch_bounds__(256) void k_layer0(const float* __restrict__ q,
                                                const float* __restrict__ W0,
                                                const float* __restrict__ b0)
{
    __shared__ float qs[32][8];
    const int j  = threadIdx.x;          // hidden unit 0..255
    const int s0 = blockIdx.x * 32;      // sample base
    for (int idx = threadIdx.x; idx < 32 * 7; idx += 256)
        qs[idx / 7][idx % 7] = q[(s0 + idx / 7) * 7 + idx % 7];
    float w[7];
#pragma unroll
    for (int i = 0; i < 7; i++) w[i] = W0[j * 7 + i];
    const float bb = b0[j];
    __syncthreads();
    for (int s = 0; s < 32; s++) {
        float pre = bb;
#pragma unroll
        for (int i = 0; i < 7; i++) pre = fmaf(w[i], qs[s][i], pre);
        const int off = (s0 + s) * HID + j;
        split_bf(sp_f(pre), g_h0h[off], g_h0l[off]);
        g_sig0[off] = sg_f(pre);
    }
}

// ---------------- K4: tangent seeds  D0[b][t][k] = sig0[b][k] * W0[k][t] -------
__global__ __launch_bounds__(256) void k_d0(const float* __restrict__ W0)
{
    const int idx = blockIdx.x * 256 + threadIdx.x;   // b*256 + k
    const int k = idx & 255;
    const int b = idx >> 8;
    const float s = g_sig0[idx];
#pragma unroll
    for (int t = 0; t < 7; t++) {
        const float v = s * W0[k * 7 + t];
        const size_t o = (size_t)(b * 7 + t) * HID + k;
        split_bf(v, g_D0h[o], g_D0l[o]);
    }
}

// ---------------- tensor-core GEMM: C[M,256] = A @ W^T, bf16x3, fused epilogue -
// MODE 0: A=h0  B=W1 : pre=acc+b1 -> h1 (hi/lo), sig1
// MODE 2: A=h1  B=W2 : pre=acc+b2 -> X2 vec0 (fp32), sig2
// MODE 1: A=D0  B=W1 : acc*sig1 -> D1 (hi/lo)
// MODE 3: A=D1  B=W2 : acc*sig2 -> X2 vec 1+t (fp32)
#define SMS 40   // smem row stride (bf16 elems) — conflict-free fragment loads
template <int MODE>
__global__ __launch_bounds__(256) void mma_gemm(const float* __restrict__ bias)
{
    __shared__ bf16 sAh[128][SMS], sAl[128][SMS], sBh[128][SMS], sBl[128][SMS];

    const int tid  = threadIdx.x;
    const int warp = tid >> 5, lane = tid & 31;
    const int wm = (warp >> 1) * 32;    // 4 warps along M
    const int wn = (warp & 1) * 64;     // 2 warps along N
    const int g  = lane >> 2, t4 = lane & 3;

    const int m_base = blockIdx.y * 128;
    const int n_base = blockIdx.x * 128;

    const bf16 *Ah, *Al, *Bh, *Bl;
    if      (MODE == 0) { Ah = g_h0h; Al = g_h0l; Bh = g_W1h; Bl = g_W1l; }
    else if (MODE == 2) { Ah = g_h1h; Al = g_h1l; Bh = g_W2h; Bl = g_W2l; }
    else if (MODE == 1) { Ah = g_D0h; Al = g_D0l; Bh = g_W1h; Bl = g_W1l; }
    else                { Ah = g_D1h; Al = g_D1l; Bh = g_W2h; Bl = g_W2l; }

    float acc[2][8][4];
#pragma unroll
    for (int a = 0; a < 2; a++)
#pragma unroll
        for (int b = 0; b < 8; b++)
#pragma unroll
            for (int c = 0; c < 4; c++) acc[a][b][c] = 0.0f;

    const int lrow = tid >> 1;            // 0..127 (load row)
    const int lcv  = (tid & 1) * 2;       // uint4 index 0 or 2

    for (int kt = 0; kt < 256; kt += 32) {
        __syncthreads();
        // each thread loads 2 consecutive uint4 (16 bf16) per array
        {
            const size_t ga = (size_t)(m_base + lrow) * HID + kt + lcv * 8;
            const size_t gb = (size_t)(n_base + lrow) * HID + kt + lcv * 8;
            *(uint4*)&sAh[lrow][lcv * 8]       = *(const uint4*)&Ah[ga];
            *(uint4*)&sAh[lrow][lcv * 8 + 8]   = *(const uint4*)&Ah[ga + 8];
            *(uint4*)&sAl[lrow][lcv * 8]       = *(const uint4*)&Al[ga];
            *(uint4*)&sAl[lrow][lcv * 8 + 8]   = *(const uint4*)&Al[ga + 8];
            *(uint4*)&sBh[lrow][lcv * 8]       = *(const uint4*)&Bh[gb];
            *(uint4*)&sBh[lrow][lcv * 8 + 8]   = *(const uint4*)&Bh[gb + 8];
            *(uint4*)&sBl[lrow][lcv * 8]       = *(const uint4*)&Bl[gb];
            *(uint4*)&sBl[lrow][lcv * 8 + 8]   = *(const uint4*)&Bl[gb + 8];
        }
        __syncthreads();

#pragma unroll
        for (int ks = 0; ks < 2; ks++) {
            const int k0 = ks * 16;
            uint32_t ah[2][4], al[2][4];
#pragma unroll
            for (int mi = 0; mi < 2; mi++) {
                const int r0 = wm + mi * 16 + g;
                ah[mi][0] = *(const uint32_t*)&sAh[r0][k0 + t4 * 2];
                ah[mi][1] = *(const uint32_t*)&sAh[r0 + 8][k0 + t4 * 2];
                ah[mi][2] = *(const uint32_t*)&sAh[r0][k0 + t4 * 2 + 8];
                ah[mi][3] = *(const uint32_t*)&sAh[r0 + 8][k0 + t4 * 2 + 8];
                al[mi][0] = *(const uint32_t*)&sAl[r0][k0 + t4 * 2];
                al[mi][1] = *(const uint32_t*)&sAl[r0 + 8][k0 + t4 * 2];
                al[mi][2] = *(const uint32_t*)&sAl[r0][k0 + t4 * 2 + 8];
                al[mi][3] = *(const uint32_t*)&sAl[r0 + 8][k0 + t4 * 2 + 8];
            }
#pragma unroll
            for (int nj = 0; nj < 8; nj++) {
                const int c0 = wn + nj * 8 + g;
                const uint32_t bh0 = *(const uint32_t*)&sBh[c0][k0 + t4 * 2];
                const uint32_t bh1 = *(const uint32_t*)&sBh[c0][k0 + t4 * 2 + 8];
                const uint32_t bl0 = *(const uint32_t*)&sBl[c0][k0 + t4 * 2];
                const uint32_t bl1 = *(const uint32_t*)&sBl[c0][k0 + t4 * 2 + 8];
#pragma unroll
                for (int mi = 0; mi < 2; mi++) {
                    mma16816(acc[mi][nj], ah[mi], bh0, bh1);
                    mma16816(acc[mi][nj], al[mi], bh0, bh1);
                    mma16816(acc[mi][nj], ah[mi], bl0, bl1);
                }
            }
        }
    }

    // ---------------- epilogue -------------------------------------------------
#pragma unroll
    for (int mi = 0; mi < 2; mi++) {
#pragma unroll
        for (int half = 0; half < 2; half++) {
            const int m = m_base + wm + mi * 16 + g + half * 8;
            int mb = 0, mt = 0;
            if (MODE == 1 || MODE == 3) { mb = m / 7; mt = m - mb * 7; }
#pragma unroll
            for (int nj = 0; nj < 8; nj++) {
                const int col = n_base + wn + nj * 8 + t4 * 2;
#pragma unroll
                for (int e = 0; e < 2; e++) {
                    const float v = acc[mi][nj][half * 2 + e];
                    const int cc = col + e;
                    if (MODE == 0) {
                        const float pre = v + bias[cc];
                        const size_t o = (size_t)m * HID + cc;
                        split_bf(sp_f(pre), g_h1h[o], g_h1l[o]);
                        g_sig1[o] = sg_f(pre);
                    } else if (MODE == 2) {
                        const float pre = v + bias[cc];
                        g_X2[(size_t)m * 8 * HID + cc] = sp_f(pre);
                        g_sig2[(size_t)m * HID + cc]   = sg_f(pre);
                    } else if (MODE == 1) {
                        const float d = v * g_sig1[(size_t)mb * HID + cc];
                        const size_t o = (size_t)m * HID + cc;
                        split_bf(d, g_D1h[o], g_D1l[o]);
                    } else {
                        g_X2[((size_t)mb * 8 + 1 + mt) * HID + cc] =
                            v * g_sig2[(size_t)mb * HID + cc];
                    }
                }
            }
        }
    }
}

// ---------------- K7: heads GEMM  Yh[m][r] = X2[m] . Whead[r] (+bias on value rows)
__global__ __launch_bounds__(256) void k_heads(const float* __restrict__ Wg,
                                               const float* __restrict__ bg,
                                               const float* __restrict__ Wld,
                                               const float* __restrict__ bld,
                                               const float* __restrict__ Wlt,
                                               const float* __restrict__ blt)
{
    __shared__ float wsm[NHEAD][HID];
    __shared__ float bsm[NHEAD];
    const int tid = threadIdx.x;
    float* wf = &wsm[0][0];
    for (int i = tid; i < 7 * HID; i += 256)  wf[i] = Wg[i];
    for (int i = tid; i < 7 * HID; i += 256)  wf[7 * HID + i] = Wld[i];
    for (int i = tid; i < 21 * HID; i += 256) wf[14 * HID + i] = Wlt[i];
    if (tid < 7)  { bsm[tid] = bg[tid]; bsm[7 + tid] = bld[tid]; }
    if (tid < 21) bsm[14 + tid] = blt[tid];
    __syncthreads();

    const int warp = tid >> 5, lane = tid & 31;
    for (int rr = 0; rr < 8; rr++) {
        const int m = blockIdx.x * 64 + warp * 8 + rr;
        const float* xg = g_X2 + (size_t)m * HID;
        float x[8];
        *(float4*)(x)     = *(const float4*)(xg + lane * 8);
        *(float4*)(x + 4) = *(const float4*)(xg + lane * 8 + 4);
        const bool valrow = ((m & 7) == 0);
#pragma unroll
        for (int r = 0; r < NHEAD; r++) {
            float w[8];
            *(float4*)(w)     = *(const float4*)(&wsm[r][lane * 8]);
            *(float4*)(w + 4) = *(const float4*)(&wsm[r][lane * 8 + 4]);
            float p = 0.0f;
#pragma unroll
            for (int u = 0; u < 8; u++) p = fmaf(w[u], x[u], p);
            p += __shfl_xor_sync(0xffffffff, p, 16);
            p += __shfl_xor_sync(0xffffffff, p, 8);
            p += __shfl_xor_sync(0xffffffff, p, 4);
            p += __shfl_xor_sync(0xffffffff, p, 2);
            p += __shfl_xor_sync(0xffffffff, p, 1);
            if (lane == 0)
                g_Yh[(size_t)m * NHEAD + r] = p + (valrow ? bsm[r] : 0.0f);
        }
    }
}

// ---------------- K8: per-sample dynamics --------------------------------------
__global__ __launch_bounds__(128) void k_dyn(const float* __restrict__ qd_g,
                                             const float* __restrict__ qdd_g,
                                             const float* __restrict__ fd,
                                             const float* __restrict__ fc,
                                             const float* __restrict__ fs,
                                             const float* __restrict__ fv,
                                             float* __restrict__ out)
{
    const int b = blockIdx.x * 128 + threadIdx.x;
    if (b >= BATCH) return;
    const int R[21]  = {1,2,2,3,3,3,4,4,4,4,5,5,5,5,5,6,6,6,6,6,6};
    const int Cc[21] = {0,0,1,0,1,2,0,1,2,3,0,1,2,3,4,0,1,2,3,4,5};

    const float* Y = g_Yh + (size_t)b * 8 * NHEAD;
    float qd[7], qdd[7], gv[7], ldr[7], sigd[7];
#pragma unroll
    for (int i = 0; i < 7; i++) {
        qd[i]  = qd_g [b * 7 + i];
        qdd[i] = qdd_g[b * 7 + i];
        gv[i]  = Y[i];
        ldr[i] = Y[7 + i];
    }

    float L[7][7];
#pragma unroll
    for (int i = 0; i < 7; i++)
#pragma unroll
        for (int j = 0; j < 7; j++) L[i][j] = 0.0f;
#pragma unroll
    for (int i = 0; i < 7; i++) {
        L[i][i]  = sp_f(ldr[i]) + 1e-3f;
        sigd[i]  = sg_f(ldr[i]);
    }
#pragma unroll
    for (int p = 0; p < 21; p++) L[R[p]][Cc[p]] = Y[14 + p];

    // a = L^T qd
    float a[7];
#pragma unroll
    for (int j = 0; j < 7; j++) {
        float s = 0.0f;
#pragma unroll
        for (int i = 0; i < 7; i++) if (i >= j) s = fmaf(L[i][j], qd[i], s);
        a[j] = s;
    }

    float Ldt[7][7];
#pragma unroll
    for (int i = 0; i < 7; i++)
#pragma unroll
        for (int j = 0; j < 7; j++) Ldt[i][j] = 0.0f;

    float svec[7];
#pragma unroll
    for (int c = 0; c < 7; c++) {
        const float* Yc = Y + (c + 1) * NHEAD;
        float dL[7][7];
#pragma unroll
        for (int i = 0; i < 7; i++)
#pragma unroll
            for (int j = 0; j < 7; j++) dL[i][j] = 0.0f;
#pragma unroll
        for (int i = 0; i < 7; i++) dL[i][i] = sigd[i] * Yc[7 + i];
#pragma unroll
        for (int p = 0; p < 21; p++) dL[R[p]][Cc[p]] = Yc[14 + p];
#pragma unroll
        for (int i = 0; i < 7; i++)
#pragma unroll
            for (int j = 0; j < 7; j++) if (j <= i)
                Ldt[i][j] = fmaf(qd[c], dL[i][j], Ldt[i][j]);
        float sc = 0.0f;
#pragma unroll
        for (int j = 0; j < 7; j++) {
            float v = 0.0f;
#pragma unroll
            for (int i = 0; i < 7; i++) if (i >= j) v = fmaf(qd[i], dL[i][j], v);
            sc = fmaf(v, a[j], sc);
        }
        svec[c] = 2.0f * sc;
    }

    // b2 = Ldt^T qd
    float b2[7];
#pragma unroll
    for (int j = 0; j < 7; j++) {
        float s = 0.0f;
#pragma unroll
        for (int i = 0; i < 7; i++) if (i >= j) s = fmaf(Ldt[i][j], qd[i], s);
        b2[j] = s;
    }

    float cor[7];
#pragma unroll
    for (int i = 0; i < 7; i++) {
        float s = 0.0f;
#pragma unroll
        for (int j = 0; j < 7; j++) if (j <= i) s = fmaf(L[i][j], b2[j], s);
#pragma unroll
        for (int j = 0; j < 7; j++) if (j <= i) s = fmaf(Ldt[i][j], a[j], s);
        cor[i] = s - 0.5f * svec[i];
    }

    float Hm[7][7];
#pragma unroll
    for (int i = 0; i < 7; i++)
#pragma unroll
        for (int k = 0; k < 7; k++) {
            float s = 0.0f;
#pragma unroll
            for (int j = 0; j < 7; j++) if (j <= i && j <= k)
                s = fmaf(L[i][j], L[k][j], s);
            Hm[i][k] = s;
        }

    float fric[7];
#pragma unroll
    for (int i = 0; i < 7; i++) {
        const float fvc = fmaxf(fv[i], 1e-3f);
        fric[i] = (fc[i] + fs[i] * expf(-qd[i] * qd[i] / fvc)) *
                      tanhf(100.0f * qd[i]) + fd[i] * qd[i];
    }

    float tau[7];
#pragma unroll
    for (int i = 0; i < 7; i++) {
        float s = 0.0f;
#pragma unroll
        for (int k = 0; k < 7; k++) s = fmaf(Hm[i][k], qdd[k], s);
        tau[i] = s + cor[i] + gv[i] + fric[i];
    }

    // outputs: tau | Hm | c | g | tau_fric | Ld_raw   (flattened, concatenated)
    const int Bc = BATCH;
#pragma unroll
    for (int i = 0; i < 7; i++) out[b * 7 + i] = tau[i];
#pragma unroll
    for (int i = 0; i < 7; i++)
#pragma unroll
        for (int k = 0; k < 7; k++) out[7 * Bc + b * 49 + i * 7 + k] = Hm[i][k];
#pragma unroll
    for (int i = 0; i < 7; i++) out[56 * Bc + b * 7 + i] = cor[i];
#pragma unroll
    for (int i = 0; i < 7; i++) out[63 * Bc + b * 7 + i] = gv[i];
#pragma unroll
    for (int i = 0; i < 7; i++) out[70 * Bc + b * 7 + i] = fric[i];
#pragma unroll
    for (int i = 0; i < 7; i++) out[77 * Bc + b * 7 + i] = ldr[i];
}

// ---------------- launch --------------------------------------------------------
extern "C" void kernel_launch(void* const* d_in, const int* in_sizes, int n_in,
                              void* d_out, int out_size)
{
    (void)in_sizes; (void)n_in; (void)out_size;
    const float* q   = (const float*)d_in[0];
    const float* qd  = (const float*)d_in[1];
    const float* qdd = (const float*)d_in[2];
    const float* W0  = (const float*)d_in[3];
    const float* b0  = (const float*)d_in[4];
    const float* W1  = (const float*)d_in[5];
    const float* b1  = (const float*)d_in[6];
    const float* W2  = (const float*)d_in[7];
    const float* b2  = (const float*)d_in[8];
    const float* Wg  = (const float*)d_in[9];
    const float* bg  = (const float*)d_in[10];
    const float* Wld = (const float*)d_in[11];
    const float* bld = (const float*)d_in[12];
    const float* Wlt = (const float*)d_in[13];
    const float* blt = (const float*)d_in[14];
    const float* fd  = (const float*)d_in[15];
    const float* fc  = (const float*)d_in[16];
    const float* fs  = (const float*)d_in[17];
    const float* fv  = (const float*)d_in[18];
    float* out = (float*)d_out;

    k_wsplit<<<HID * HID / 256, 256>>>(W1, W2);
    k_layer0<<<BATCH / 32, 256>>>(q, W0, b0);
    k_d0<<<BATCH, 256>>>(W0);                                     // D0 seeds
    mma_gemm<0><<<dim3(2, BATCH / 128), 256>>>(b1);               // h1, sig1
    mma_gemm<1><<<dim3(2, (BATCH * 7) / 128), 256>>>(nullptr);    // D1
    mma_gemm<2><<<dim3(2, BATCH / 128), 256>>>(b2);               // h2 -> X2, sig2
    mma_gemm<3><<<dim3(2, (BATCH * 7) / 128), 256>>>(nullptr);    // D2 -> X2
    k_heads<<<(BATCH * 8) / 64, 256>>>(Wg, bg, Wld, bld, Wlt, blt);
    k_dyn<<<(BATCH + 127) / 128, 128>>>(qd, qdd, fd, fc, fs, fv, out);
}

// round 4
// speedup vs baseline: 1.6149x; 1.1116x over previous
#include <cuda_runtime.h>
#include <cuda_bf16.h>
#include <math.h>
#include <stdint.h>

#define BATCH 32768
#define HID 256
#define NDOF 7
#define NTRIL 21
#define NHEAD 35   // 7 g + 7 Ld + 21 Lt

typedef __nv_bfloat16 bf16;

// ---------------- scratch (device globals; no allocation allowed) -------------
__device__ bf16  g_h0h [BATCH * HID];
__device__ bf16  g_h0l [BATCH * HID];
__device__ bf16  g_h1h [BATCH * HID];
__device__ bf16  g_h1l [BATCH * HID];
__device__ bf16  g_D0h [(size_t)BATCH * 7 * HID];
__device__ bf16  g_D0l [(size_t)BATCH * 7 * HID];
__device__ bf16  g_D1h [(size_t)BATCH * 7 * HID];
__device__ bf16  g_D1l [(size_t)BATCH * 7 * HID];
__device__ float g_sig0[BATCH * HID];
__device__ float g_sig1[BATCH * HID];
__device__ float g_sig2[BATCH * HID];
__device__ float g_X2  [(size_t)BATCH * 8 * HID];   // vec0 = h2, vec 1..7 = dh2/dq_t
__device__ float g_Yh  [(size_t)BATCH * 8 * NHEAD];
__device__ bf16  g_W1h[HID * HID];
__device__ bf16  g_W1l[HID * HID];
__device__ bf16  g_W2h[HID * HID];
__device__ bf16  g_W2l[HID * HID];

// ---------------- helpers ------------------------------------------------------
__device__ __forceinline__ float sp_f(float x) {
    return fmaxf(x, 0.0f) + log1pf(expf(-fabsf(x)));
}
__device__ __forceinline__ float sg_f(float x) {
    return 1.0f / (1.0f + expf(-x));
}
__device__ __forceinline__ void split_bf(float x, bf16& h, bf16& l) {
    h = __float2bfloat16_rn(x);
    l = __float2bfloat16_rn(x - __bfloat162float(h));
}
__device__ __forceinline__ void mma16816(float c[4], const uint32_t a[4],
                                         uint32_t b0, uint32_t b1) {
    asm volatile(
        "mma.sync.aligned.m16n8k16.row.col.f32.bf16.bf16.f32 "
        "{%0,%1,%2,%3}, {%4,%5,%6,%7}, {%8,%9}, {%0,%1,%2,%3};"
        : "+f"(c[0]), "+f"(c[1]), "+f"(c[2]), "+f"(c[3])
        : "r"(a[0]), "r"(a[1]), "r"(a[2]), "r"(a[3]), "r"(b0), "r"(b1));
}
__device__ __forceinline__ void ldsm4(uint32_t r[4], uint32_t addr) {
    asm volatile("ldmatrix.sync.aligned.m8n8.x4.shared.b16 {%0,%1,%2,%3}, [%4];"
                 : "=r"(r[0]), "=r"(r[1]), "=r"(r[2]), "=r"(r[3]) : "r"(addr));
}
__device__ __forceinline__ uint32_t smem_u32(const void* p) {
    uint32_t a;
    asm("{ .reg .u64 t; cvta.to.shared.u64 t, %1; cvt.u32.u64 %0, t; }"
        : "=r"(a) : "l"(p));
    return a;
}
__device__ __forceinline__ void cpa16(uint32_t s, const void* g) {
    asm volatile("cp.async.cg.shared.global [%0], [%1], 16;" :: "r"(s), "l"(g));
}

// ---------------- K0: weight hi/lo split ---------------------------------------
__global__ __launch_bounds__(256) void k_wsplit(const float* __restrict__ W1,
                                                const float* __restrict__ W2)
{
    const int i = blockIdx.x * 256 + threadIdx.x;
    split_bf(W1[i], g_W1h[i], g_W1l[i]);
    split_bf(W2[i], g_W2h[i], g_W2l[i]);
}

// ---------------- K1: layer0 values -------------------------------------------
__global__ __launch_bounds__(256) void k_layer0(const float* __restrict__ q,
                                                const float* __restrict__ W0,
                                                const float* __restrict__ b0)
{
    __shared__ float qs[32][8];
    const int j  = threadIdx.x;
    const int s0 = blockIdx.x * 32;
    for (int idx = threadIdx.x; idx < 32 * 7; idx += 256)
        qs[idx / 7][idx % 7] = q[(s0 + idx / 7) * 7 + idx % 7];
    float w[7];
#pragma unroll
    for (int i = 0; i < 7; i++) w[i] = W0[j * 7 + i];
    const float bb = b0[j];
    __syncthreads();
    for (int s = 0; s < 32; s++) {
        float pre = bb;
#pragma unroll
        for (int i = 0; i < 7; i++) pre = fmaf(w[i], qs[s][i], pre);
        const int off = (s0 + s) * HID + j;
        split_bf(sp_f(pre), g_h0h[off], g_h0l[off]);
        g_sig0[off] = sg_f(pre);
    }
}

// ---------------- K4: tangent seeds  D0[b][t][k] = sig0[b][k] * W0[k][t] -------
__global__ __launch_bounds__(256) void k_d0(const float* __restrict__ W0)
{
    const int idx = blockIdx.x * 256 + threadIdx.x;
    const int k = idx & 255;
    const int b = idx >> 8;
    const float s = g_sig0[idx];
#pragma unroll
    for (int t = 0; t < 7; t++) {
        const float v = s * W0[k * 7 + t];
        const size_t o = (size_t)(b * 7 + t) * HID + k;
        split_bf(v, g_D0h[o], g_D0l[o]);
    }
}

// ---------------- tensor-core GEMM: C[M,256] = A @ W^T, bf16x3 -----------------
// smem layout per stage (bf16 elems, row stride 40):
//   Ah @ 0, Al @ 5120, Bh @ 10240, Bl @ 15360 ; stage size 20480 elems (40 KB)
#define SMS 40
#define ASZB 10240            // bytes per array (128*40*2)
#define STGB 40960            // bytes per stage
#define SMEM_TOT (2 * STGB)   // 80 KB dynamic

template <int MODE>
__global__ __launch_bounds__(256, 2) void mma_gemm(const float* __restrict__ bias)
{
    extern __shared__ __align__(16) bf16 smdyn[];
    const uint32_t smb = smem_u32(smdyn);

    const int tid  = threadIdx.x;
    const int warp = tid >> 5, lane = tid & 31;
    const int wm = (warp >> 1) * 32;    // 4 warps along M
    const int wn = (warp & 1) * 64;     // 2 warps along N
    const int g  = lane >> 2, t4 = lane & 3;

    const int m_base = blockIdx.y * 128;
    const int n_base = blockIdx.x * 128;

    const bf16 *Ah, *Al, *Bh, *Bl;
    if      (MODE == 0) { Ah = g_h0h; Al = g_h0l; Bh = g_W1h; Bl = g_W1l; }
    else if (MODE == 2) { Ah = g_h1h; Al = g_h1l; Bh = g_W2h; Bl = g_W2l; }
    else if (MODE == 1) { Ah = g_D0h; Al = g_D0l; Bh = g_W1h; Bl = g_W1l; }
    else                { Ah = g_D1h; Al = g_D1l; Bh = g_W2h; Bl = g_W2l; }

    // prefetch addressing: each thread loads 2x16B per array
    const int prow = tid >> 1;
    const int pc   = (tid & 1) * 16;             // elem offset within 32-wide k tile
    const uint32_t pdst = (uint32_t)(prow * SMS + pc) * 2;
    const size_t   pga  = (size_t)(m_base + prow) * HID + pc;
    const size_t   pgb  = (size_t)(n_base + prow) * HID + pc;

    // fragment addressing (byte offsets within a stage)
    const uint32_t a_off = (uint32_t)(((wm + (lane & 15)) * SMS) + ((lane >> 4) << 3)) * 2;
    const uint32_t b_off = (uint32_t)(((wn + ((lane >> 4) << 3) + (lane & 7)) * SMS)
                                      + (((lane >> 3) & 1) << 3)) * 2;

    float acc[2][8][4];
#pragma unroll
    for (int a = 0; a < 2; a++)
#pragma unroll
        for (int b = 0; b < 8; b++)
#pragma unroll
            for (int c = 0; c < 4; c++) acc[a][b][c] = 0.0f;

#define PREFETCH(STAGE, KT)                                                     \
    {                                                                           \
        const uint32_t sb = smb + (STAGE) * STGB + pdst;                        \
        cpa16(sb,                 Ah + pga + (KT));                             \
        cpa16(sb + 16,            Ah + pga + (KT) + 8);                         \
        cpa16(sb + ASZB,          Al + pga + (KT));                             \
        cpa16(sb + ASZB + 16,     Al + pga + (KT) + 8);                         \
        cpa16(sb + 2 * ASZB,      Bh + pgb + (KT));                             \
        cpa16(sb + 2 * ASZB + 16, Bh + pgb + (KT) + 8);                         \
        cpa16(sb + 3 * ASZB,      Bl + pgb + (KT));                             \
        cpa16(sb + 3 * ASZB + 16, Bl + pgb + (KT) + 8);                         \
        asm volatile("cp.async.commit_group;");                                 \
    }

    PREFETCH(0, 0)

#pragma unroll
    for (int it = 0; it < 8; it++) {
        if (it < 7) {
            PREFETCH((it + 1) & 1, (it + 1) * 32)
            asm volatile("cp.async.wait_group 1;");
        } else {
            asm volatile("cp.async.wait_group 0;");
        }
        __syncthreads();

        const uint32_t sbase = smb + (it & 1) * STGB;
#pragma unroll
        for (int ks = 0; ks < 2; ks++) {
            const uint32_t kso = ks * 32;     // 16 elems * 2B
            uint32_t ah[2][4], al[2][4];
            ldsm4(ah[0], sbase + a_off + kso);
            ldsm4(ah[1], sbase + a_off + kso + 16 * SMS * 2);
            ldsm4(al[0], sbase + ASZB + a_off + kso);
            ldsm4(al[1], sbase + ASZB + a_off + kso + 16 * SMS * 2);
#pragma unroll
            for (int njp = 0; njp < 4; njp++) {
                uint32_t bh[4], bl[4];
                ldsm4(bh, sbase + 2 * ASZB + b_off + njp * (16 * SMS * 2) + kso);
                ldsm4(bl, sbase + 3 * ASZB + b_off + njp * (16 * SMS * 2) + kso);
#pragma unroll
                for (int mi = 0; mi < 2; mi++) {
#pragma unroll
                    for (int s = 0; s < 2; s++) {
                        float* C = acc[mi][njp * 2 + s];
                        mma16816(C, ah[mi], bh[2 * s], bh[2 * s + 1]);
                        mma16816(C, al[mi], bh[2 * s], bh[2 * s + 1]);
                        mma16816(C, ah[mi], bl[2 * s], bl[2 * s + 1]);
                    }
                }
            }
        }
        __syncthreads();
    }
#undef PREFETCH

    // ---------------- epilogue -------------------------------------------------
#pragma unroll
    for (int mi = 0; mi < 2; mi++) {
#pragma unroll
        for (int half = 0; half < 2; half++) {
            const int m = m_base + wm + mi * 16 + g + half * 8;
            int mb = 0, mt = 0;
            if (MODE == 1 || MODE == 3) { mb = m / 7; mt = m - mb * 7; }
#pragma unroll
            for (int nj = 0; nj < 8; nj++) {
                const int col = n_base + wn + nj * 8 + t4 * 2;
#pragma unroll
                for (int e = 0; e < 2; e++) {
                    const float v = acc[mi][nj][half * 2 + e];
                    const int cc = col + e;
                    if (MODE == 0) {
                        const float pre = v + bias[cc];
                        const size_t o = (size_t)m * HID + cc;
                        split_bf(sp_f(pre), g_h1h[o], g_h1l[o]);
                        g_sig1[o] = sg_f(pre);
                    } else if (MODE == 2) {
                        const float pre = v + bias[cc];
                        g_X2[(size_t)m * 8 * HID + cc] = sp_f(pre);
                        g_sig2[(size_t)m * HID + cc]   = sg_f(pre);
                    } else if (MODE == 1) {
                        const float d = v * g_sig1[(size_t)mb * HID + cc];
                        const size_t o = (size_t)m * HID + cc;
                        split_bf(d, g_D1h[o], g_D1l[o]);
                    } else {
                        g_X2[((size_t)mb * 8 + 1 + mt) * HID + cc] =
                            v * g_sig2[(size_t)mb * HID + cc];
                    }
                }
            }
        }
    }
}

// ---------------- K7: heads GEMM ------------------------------------------------
__global__ __launch_bounds__(256) void k_heads(const float* __restrict__ Wg,
                                               const float* __restrict__ bg,
                                               const float* __restrict__ Wld,
                                               const float* __restrict__ bld,
                                               const float* __restrict__ Wlt,
                                               const float* __restrict__ blt)
{
    __shared__ float wsm[NHEAD][HID];
    __shared__ float bsm[NHEAD];
    const int tid = threadIdx.x;
    float* wf = &wsm[0][0];
    for (int i = tid; i < 7 * HID; i += 256)  wf[i] = Wg[i];
    for (int i = tid; i < 7 * HID; i += 256)  wf[7 * HID + i] = Wld[i];
    for (int i = tid; i < 21 * HID; i += 256) wf[14 * HID + i] = Wlt[i];
    if (tid < 7)  { bsm[tid] = bg[tid]; bsm[7 + tid] = bld[tid]; }
    if (tid < 21) bsm[14 + tid] = blt[tid];
    __syncthreads();

    const int warp = tid >> 5, lane = tid & 31;
    for (int rr = 0; rr < 8; rr++) {
        const int m = blockIdx.x * 64 + warp * 8 + rr;
        const float* xg = g_X2 + (size_t)m * HID;
        float x[8];
        *(float4*)(x)     = *(const float4*)(xg + lane * 8);
        *(float4*)(x + 4) = *(const float4*)(xg + lane * 8 + 4);
        const bool valrow = ((m & 7) == 0);
#pragma unroll
        for (int r = 0; r < NHEAD; r++) {
            float w[8];
            *(float4*)(w)     = *(const float4*)(&wsm[r][lane * 8]);
            *(float4*)(w + 4) = *(const float4*)(&wsm[r][lane * 8 + 4]);
            float p = 0.0f;
#pragma unroll
            for (int u = 0; u < 8; u++) p = fmaf(w[u], x[u], p);
            p += __shfl_xor_sync(0xffffffff, p, 16);
            p += __shfl_xor_sync(0xffffffff, p, 8);
            p += __shfl_xor_sync(0xffffffff, p, 4);
            p += __shfl_xor_sync(0xffffffff, p, 2);
            p += __shfl_xor_sync(0xffffffff, p, 1);
            if (lane == 0)
                g_Yh[(size_t)m * NHEAD + r] = p + (valrow ? bsm[r] : 0.0f);
        }
    }
}

// ---------------- K8: per-sample dynamics --------------------------------------
__global__ __launch_bounds__(128) void k_dyn(const float* __restrict__ qd_g,
                                             const float* __restrict__ qdd_g,
                                             const float* __restrict__ fd,
                                             const float* __restrict__ fc,
                                             const float* __restrict__ fs,
                                             const float* __restrict__ fv,
                                             float* __restrict__ out)
{
    const int b = blockIdx.x * 128 + threadIdx.x;
    if (b >= BATCH) return;
    const int R[21]  = {1,2,2,3,3,3,4,4,4,4,5,5,5,5,5,6,6,6,6,6,6};
    const int Cc[21] = {0,0,1,0,1,2,0,1,2,3,0,1,2,3,4,0,1,2,3,4,5};

    const float* Y = g_Yh + (size_t)b * 8 * NHEAD;
    float qd[7], qdd[7], gv[7], ldr[7], sigd[7];
#pragma unroll
    for (int i = 0; i < 7; i++) {
        qd[i]  = qd_g [b * 7 + i];
        qdd[i] = qdd_g[b * 7 + i];
        gv[i]  = Y[i];
        ldr[i] = Y[7 + i];
    }

    float L[7][7];
#pragma unroll
    for (int i = 0; i < 7; i++)
#pragma unroll
        for (int j = 0; j < 7; j++) L[i][j] = 0.0f;
#pragma unroll
    for (int i = 0; i < 7; i++) {
        L[i][i]  = sp_f(ldr[i]) + 1e-3f;
        sigd[i]  = sg_f(ldr[i]);
    }
#pragma unroll
    for (int p = 0; p < 21; p++) L[R[p]][Cc[p]] = Y[14 + p];

    float a[7];
#pragma unroll
    for (int j = 0; j < 7; j++) {
        float s = 0.0f;
#pragma unroll
        for (int i = 0; i < 7; i++) if (i >= j) s = fmaf(L[i][j], qd[i], s);
        a[j] = s;
    }

    float Ldt[7][7];
#pragma unroll
    for (int i = 0; i < 7; i++)
#pragma unroll
        for (int j = 0; j < 7; j++) Ldt[i][j] = 0.0f;

    float svec[7];
#pragma unroll
    for (int c = 0; c < 7; c++) {
        const float* Yc = Y + (c + 1) * NHEAD;
        float dL[7][7];
#pragma unroll
        for (int i = 0; i < 7; i++)
#pragma unroll
            for (int j = 0; j < 7; j++) dL[i][j] = 0.0f;
#pragma unroll
        for (int i = 0; i < 7; i++) dL[i][i] = sigd[i] * Yc[7 + i];
#pragma unroll
        for (int p = 0; p < 21; p++) dL[R[p]][Cc[p]] = Yc[14 + p];
#pragma unroll
        for (int i = 0; i < 7; i++)
#pragma unroll
            for (int j = 0; j < 7; j++) if (j <= i)
                Ldt[i][j] = fmaf(qd[c], dL[i][j], Ldt[i][j]);
        float sc = 0.0f;
#pragma unroll
        for (int j = 0; j < 7; j++) {
            float v = 0.0f;
#pragma unroll
            for (int i = 0; i < 7; i++) if (i >= j) v = fmaf(qd[i], dL[i][j], v);
            sc = fmaf(v, a[j], sc);
        }
        svec[c] = 2.0f * sc;
    }

    float b2[7];
#pragma unroll
    for (int j = 0; j < 7; j++) {
        float s = 0.0f;
#pragma unroll
        for (int i = 0; i < 7; i++) if (i >= j) s = fmaf(Ldt[i][j], qd[i], s);
        b2[j] = s;
    }

    float cor[7];
#pragma unroll
    for (int i = 0; i < 7; i++) {
        float s = 0.0f;
#pragma unroll
        for (int j = 0; j < 7; j++) if (j <= i) s = fmaf(L[i][j], b2[j], s);
#pragma unroll
        for (int j = 0; j < 7; j++) if (j <= i) s = fmaf(Ldt[i][j], a[j], s);
        cor[i] = s - 0.5f * svec[i];
    }

    float Hm[7][7];
#pragma unroll
    for (int i = 0; i < 7; i++)
#pragma unroll
        for (int k = 0; k < 7; k++) {
            float s = 0.0f;
#pragma unroll
            for (int j = 0; j < 7; j++) if (j <= i && j <= k)
                s = fmaf(L[i][j], L[k][j], s);
            Hm[i][k] = s;
        }

    float fric[7];
#pragma unroll
    for (int i = 0; i < 7; i++) {
        const float fvc = fmaxf(fv[i], 1e-3f);
        fric[i] = (fc[i] + fs[i] * expf(-qd[i] * qd[i] / fvc)) *
                      tanhf(100.0f * qd[i]) + fd[i] * qd[i];
    }

    float tau[7];
#pragma unroll
    for (int i = 0; i < 7; i++) {
        float s = 0.0f;
#pragma unroll
        for (int k = 0; k < 7; k++) s = fmaf(Hm[i][k], qdd[k], s);
        tau[i] = s + cor[i] + gv[i] + fric[i];
    }

    const int Bc = BATCH;
#pragma unroll
    for (int i = 0; i < 7; i++) out[b * 7 + i] = tau[i];
#pragma unroll
    for (int i = 0; i < 7; i++)
#pragma unroll
        for (int k = 0; k < 7; k++) out[7 * Bc + b * 49 + i * 7 + k] = Hm[i][k];
#pragma unroll
    for (int i = 0; i < 7; i++) out[56 * Bc + b * 7 + i] = cor[i];
#pragma unroll
    for (int i = 0; i < 7; i++) out[63 * Bc + b * 7 + i] = gv[i];
#pragma unroll
    for (int i = 0; i < 7; i++) out[70 * Bc + b * 7 + i] = fric[i];
#pragma unroll
    for (int i = 0; i < 7; i++) out[77 * Bc + b * 7 + i] = ldr[i];
}

// ---------------- launch --------------------------------------------------------
extern "C" void kernel_launch(void* const* d_in, const int* in_sizes, int n_in,
                              void* d_out, int out_size)
{
    (void)in_sizes; (void)n_in; (void)out_size;
    const float* q   = (const float*)d_in[0];
    const float* qd  = (const float*)d_in[1];
    const float* qdd = (const float*)d_in[2];
    const float* W0  = (const float*)d_in[3];
    const float* b0  = (const float*)d_in[4];
    const float* W1  = (const float*)d_in[5];
    const float* b1  = (const float*)d_in[6];
    const float* W2  = (const float*)d_in[7];
    const float* b2  = (const float*)d_in[8];
    const float* Wg  = (const float*)d_in[9];
    const float* bg  = (const float*)d_in[10];
    const float* Wld = (const float*)d_in[11];
    const float* bld = (const float*)d_in[12];
    const float* Wlt = (const float*)d_in[13];
    const float* blt = (const float*)d_in[14];
    const float* fd  = (const float*)d_in[15];
    const float* fc  = (const float*)d_in[16];
    const float* fs  = (const float*)d_in[17];
    const float* fv  = (const float*)d_in[18];
    float* out = (float*)d_out;

    // raise dynamic-smem cap (host-side attribute; not a stream op, capture-safe)
    cudaFuncSetAttribute(mma_gemm<0>, cudaFuncAttributeMaxDynamicSharedMemorySize, SMEM_TOT);
    cudaFuncSetAttribute(mma_gemm<1>, cudaFuncAttributeMaxDynamicSharedMemorySize, SMEM_TOT);
    cudaFuncSetAttribute(mma_gemm<2>, cudaFuncAttributeMaxDynamicSharedMemorySize, SMEM_TOT);
    cudaFuncSetAttribute(mma_gemm<3>, cudaFuncAttributeMaxDynamicSharedMemorySize, SMEM_TOT);

    k_wsplit<<<HID * HID / 256, 256>>>(W1, W2);
    k_layer0<<<BATCH / 32, 256>>>(q, W0, b0);
    k_d0<<<BATCH, 256>>>(W0);
    mma_gemm<0><<<dim3(2, BATCH / 128), 256, SMEM_TOT>>>(b1);
    mma_gemm<1><<<dim3(2, (BATCH * 7) / 128), 256, SMEM_TOT>>>(nullptr);
    mma_gemm<2><<<dim3(2, BATCH / 128), 256, SMEM_TOT>>>(b2);
    mma_gemm<3><<<dim3(2, (BATCH * 7) / 128), 256, SMEM_TOT>>>(nullptr);
    k_heads<<<(BATCH * 8) / 64, 256>>>(Wg, bg, Wld, bld, Wlt, blt);
    k_dyn<<<(BATCH + 127) / 128, 128>>>(qd, qdd, fd, fc, fs, fv, out);
}

// round 6
// speedup vs baseline: 1.9961x; 1.2360x over previous
#include <cuda_runtime.h>
#include <cuda_fp16.h>
#include <math.h>
#include <stdint.h>

#define BATCH 32768
#define HID 256
#define NDOF 7
#define NTRIL 21
#define NHEAD 35   // 7 g + 7 Ld + 21 Lt

typedef __half fp16;

// ---------------- scratch (device globals; no allocation allowed) -------------
__device__ fp16  g_h0h [BATCH * HID];
__device__ fp16  g_h0l [BATCH * HID];
__device__ fp16  g_h1h [BATCH * HID];
__device__ fp16  g_h1l [BATCH * HID];
__device__ fp16  g_D0h [(size_t)BATCH * 7 * HID];   // tangent: hi only (1-term)
__device__ fp16  g_D1h [(size_t)BATCH * 7 * HID];
__device__ float g_sig0[BATCH * HID];
__device__ float g_sig1[BATCH * HID];
__device__ float g_sig2[BATCH * HID];
__device__ float g_X2  [(size_t)BATCH * 8 * HID];   // vec0 = h2, vec 1..7 = dh2/dq_t
__device__ float g_Yh  [(size_t)BATCH * 8 * NHEAD];
__device__ fp16  g_W1h[HID * HID];
__device__ fp16  g_W1l[HID * HID];
__device__ fp16  g_W2h[HID * HID];
__device__ fp16  g_W2l[HID * HID];

// ---------------- helpers ------------------------------------------------------
__device__ __forceinline__ float sp_f(float x) {
    return fmaxf(x, 0.0f) + log1pf(expf(-fabsf(x)));
}
__device__ __forceinline__ float sg_f(float x) {
    return 1.0f / (1.0f + expf(-x));
}
__device__ __forceinline__ void split_h(float x, fp16& h, fp16& l) {
    h = __float2half_rn(x);
    l = __float2half_rn(x - __half2float(h));
}
__device__ __forceinline__ void mma16816(float c[4], const uint32_t a[4],
                                         uint32_t b0, uint32_t b1) {
    asm volatile(
        "mma.sync.aligned.m16n8k16.row.col.f32.f16.f16.f32 "
        "{%0,%1,%2,%3}, {%4,%5,%6,%7}, {%8,%9}, {%0,%1,%2,%3};"
        : "+f"(c[0]), "+f"(c[1]), "+f"(c[2]), "+f"(c[3])
        : "r"(a[0]), "r"(a[1]), "r"(a[2]), "r"(a[3]), "r"(b0), "r"(b1));
}
__device__ __forceinline__ void ldsm4(uint32_t r[4], uint32_t addr) {
    asm volatile("ldmatrix.sync.aligned.m8n8.x4.shared.b16 {%0,%1,%2,%3}, [%4];"
                 : "=r"(r[0]), "=r"(r[1]), "=r"(r[2]), "=r"(r[3]) : "r"(addr));
}
__device__ __forceinline__ uint32_t smem_u32(const void* p) {
    uint32_t a;
    asm("{ .reg .u64 t; cvta.to.shared.u64 t, %1; cvt.u32.u64 %0, t; }"
        : "=r"(a) : "l"(p));
    return a;
}
__device__ __forceinline__ void cpa16(uint32_t s, const void* g) {
    asm volatile("cp.async.cg.shared.global [%0], [%1], 16;" :: "r"(s), "l"(g));
}

// ---------------- K0: weight hi/lo split ---------------------------------------
__global__ __launch_bounds__(256) void k_wsplit(const float* __restrict__ W1,
                                                const float* __restrict__ W2)
{
    const int i = blockIdx.x * 256 + threadIdx.x;
    split_h(W1[i], g_W1h[i], g_W1l[i]);
    split_h(W2[i], g_W2h[i], g_W2l[i]);
}

// ---------------- K1: layer0 values -------------------------------------------
__global__ __launch_bounds__(256) void k_layer0(const float* __restrict__ q,
                                                const float* __restrict__ W0,
                                                const float* __restrict__ b0)
{
    __shared__ float qs[32][8];
    const int j  = threadIdx.x;
    const int s0 = blockIdx.x * 32;
    for (int idx = threadIdx.x; idx < 32 * 7; idx += 256)
        qs[idx / 7][idx % 7] = q[(s0 + idx / 7) * 7 + idx % 7];
    float w[7];
#pragma unroll
    for (int i = 0; i < 7; i++) w[i] = W0[j * 7 + i];
    const float bb = b0[j];
    __syncthreads();
    for (int s = 0; s < 32; s++) {
        float pre = bb;
#pragma unroll
        for (int i = 0; i < 7; i++) pre = fmaf(w[i], qs[s][i], pre);
        const int off = (s0 + s) * HID + j;
        split_h(sp_f(pre), g_h0h[off], g_h0l[off]);
        g_sig0[off] = sg_f(pre);
    }
}

// ---------------- K4: tangent seeds  D0[b][t][k] = sig0[b][k] * W0[k][t] -------
__global__ __launch_bounds__(256) void k_d0(const float* __restrict__ W0)
{
    const int idx = blockIdx.x * 256 + threadIdx.x;
    const int k = idx & 255;
    const int b = idx >> 8;
    const float s = g_sig0[idx];
#pragma unroll
    for (int t = 0; t < 7; t++)
        g_D0h[(size_t)(b * 7 + t) * HID + k] = __float2half_rn(s * W0[k * 7 + t]);
}

// ---------------- VALUE GEMM (3-term fp16): C[M,256] = A @ W^T ------------------
#define SMS 40
#define ASZB 10240            // bytes per array (128*40*2)
#define STGB 40960            // bytes per stage
#define SMEM_TOT (2 * STGB)   // 80 KB dynamic

template <int MODE>       // 0: layer1  2: layer2
__global__ __launch_bounds__(256, 2) void mma_gemm(const float* __restrict__ bias)
{
    extern __shared__ __align__(16) fp16 smdyn[];
    const uint32_t smb = smem_u32(smdyn);

    const int tid  = threadIdx.x;
    const int warp = tid >> 5, lane = tid & 31;
    const int wm = (warp >> 1) * 32;
    const int wn = (warp & 1) * 64;
    const int g  = lane >> 2, t4 = lane & 3;

    const int m_base = blockIdx.y * 128;
    const int n_base = blockIdx.x * 128;

    const fp16 *Ah, *Al, *Bh, *Bl;
    if (MODE == 0) { Ah = g_h0h; Al = g_h0l; Bh = g_W1h; Bl = g_W1l; }
    else           { Ah = g_h1h; Al = g_h1l; Bh = g_W2h; Bl = g_W2l; }

    const int prow = tid >> 1;
    const int pc   = (tid & 1) * 16;
    const uint32_t pdst = (uint32_t)(prow * SMS + pc) * 2;
    const size_t   pga  = (size_t)(m_base + prow) * HID + pc;
    const size_t   pgb  = (size_t)(n_base + prow) * HID + pc;

    const uint32_t a_off = (uint32_t)(((wm + (lane & 15)) * SMS) + ((lane >> 4) << 3)) * 2;
    const uint32_t b_off = (uint32_t)(((wn + ((lane >> 4) << 3) + (lane & 7)) * SMS)
                                      + (((lane >> 3) & 1) << 3)) * 2;

    float acc[2][8][4];
#pragma unroll
    for (int a = 0; a < 2; a++)
#pragma unroll
        for (int b = 0; b < 8; b++)
#pragma unroll
            for (int c = 0; c < 4; c++) acc[a][b][c] = 0.0f;

#define PREFETCH(STAGE, KT)                                                     \
    {                                                                           \
        const uint32_t sb = smb + (STAGE) * STGB + pdst;                        \
        cpa16(sb,                 Ah + pga + (KT));                             \
        cpa16(sb + 16,            Ah + pga + (KT) + 8);                         \
        cpa16(sb + ASZB,          Al + pga + (KT));                             \
        cpa16(sb + ASZB + 16,     Al + pga + (KT) + 8);                         \
        cpa16(sb + 2 * ASZB,      Bh + pgb + (KT));                             \
        cpa16(sb + 2 * ASZB + 16, Bh + pgb + (KT) + 8);                         \
        cpa16(sb + 3 * ASZB,      Bl + pgb + (KT));                             \
        cpa16(sb + 3 * ASZB + 16, Bl + pgb + (KT) + 8);                         \
        asm volatile("cp.async.commit_group;");                                 \
    }

    PREFETCH(0, 0)

#pragma unroll
    for (int it = 0; it < 8; it++) {
        if (it < 7) {
            PREFETCH((it + 1) & 1, (it + 1) * 32)
            asm volatile("cp.async.wait_group 1;");
        } else {
            asm volatile("cp.async.wait_group 0;");
        }
        __syncthreads();

        const uint32_t sbase = smb + (it & 1) * STGB;
#pragma unroll
        for (int ks = 0; ks < 2; ks++) {
            const uint32_t kso = ks * 32;
            uint32_t ah[2][4], al[2][4];
            ldsm4(ah[0], sbase + a_off + kso);
            ldsm4(ah[1], sbase + a_off + kso + 16 * SMS * 2);
            ldsm4(al[0], sbase + ASZB + a_off + kso);
            ldsm4(al[1], sbase + ASZB + a_off + kso + 16 * SMS * 2);
#pragma unroll
            for (int njp = 0; njp < 4; njp++) {
                uint32_t bh[4], bl[4];
                ldsm4(bh, sbase + 2 * ASZB + b_off + njp * (16 * SMS * 2) + kso);
                ldsm4(bl, sbase + 3 * ASZB + b_off + njp * (16 * SMS * 2) + kso);
#pragma unroll
                for (int mi = 0; mi < 2; mi++) {
#pragma unroll
                    for (int s = 0; s < 2; s++) {
                        float* C = acc[mi][njp * 2 + s];
                        mma16816(C, ah[mi], bh[2 * s], bh[2 * s + 1]);
                        mma16816(C, al[mi], bh[2 * s], bh[2 * s + 1]);
                        mma16816(C, ah[mi], bl[2 * s], bl[2 * s + 1]);
                    }
                }
            }
        }
        __syncthreads();
    }
#undef PREFETCH

#pragma unroll
    for (int mi = 0; mi < 2; mi++) {
#pragma unroll
        for (int half = 0; half < 2; half++) {
            const int m = m_base + wm + mi * 16 + g + half * 8;
#pragma unroll
            for (int nj = 0; nj < 8; nj++) {
                const int col = n_base + wn + nj * 8 + t4 * 2;
#pragma unroll
                for (int e = 0; e < 2; e++) {
                    const float v = acc[mi][nj][half * 2 + e];
                    const int cc = col + e;
                    const float pre = v + bias[cc];
                    if (MODE == 0) {
                        const size_t o = (size_t)m * HID + cc;
                        split_h(sp_f(pre), g_h1h[o], g_h1l[o]);
                        g_sig1[o] = sg_f(pre);
                    } else {
                        g_X2[(size_t)m * 8 * HID + cc] = sp_f(pre);
                        g_sig2[(size_t)m * HID + cc]   = sg_f(pre);
                    }
                }
            }
        }
    }
}

// ---------------- TANGENT GEMM (1-term fp16): C[M,256] = D @ W^T ---------------
template <int MODE>       // 1: layer1 (D0->D1, scale sig1)  3: layer2 (D1->X2, scale sig2)
__global__ __launch_bounds__(256, 2) void tan_gemm()
{
    __shared__ __align__(16) fp16 sm[2][2][128 * SMS];   // [stage][A/B]

    const int tid  = threadIdx.x;
    const int warp = tid >> 5, lane = tid & 31;
    const int wm = (warp >> 1) * 32;
    const int wn = (warp & 1) * 64;
    const int g  = lane >> 2, t4 = lane & 3;

    const int m_base = blockIdx.y * 128;
    const int n_base = blockIdx.x * 128;

    const fp16* Dh = (MODE == 1) ? g_D0h : g_D1h;
    const fp16* Wh = (MODE == 1) ? g_W1h : g_W2h;

    const int prow = tid >> 1;
    const int pc   = (tid & 1) * 16;
    const uint32_t pdst = (uint32_t)(prow * SMS + pc) * 2;
    const size_t   pga  = (size_t)(m_base + prow) * HID + pc;
    const size_t   pgb  = (size_t)(n_base + prow) * HID + pc;

    const uint32_t a_off = (uint32_t)(((wm + (lane & 15)) * SMS) + ((lane >> 4) << 3)) * 2;
    const uint32_t b_off = (uint32_t)(((wn + ((lane >> 4) << 3) + (lane & 7)) * SMS)
                                      + (((lane >> 3) & 1) << 3)) * 2;

    float acc[2][8][4];
#pragma unroll
    for (int a = 0; a < 2; a++)
#pragma unroll
        for (int b = 0; b < 8; b++)
#pragma unroll
            for (int c = 0; c < 4; c++) acc[a][b][c] = 0.0f;

#define TPREF(STAGE, KT)                                                        \
    {                                                                           \
        const uint32_t sa = smem_u32(&sm[STAGE][0][0]) + pdst;                  \
        const uint32_t sb = smem_u32(&sm[STAGE][1][0]) + pdst;                  \
        cpa16(sa,      Dh + pga + (KT));                                        \
        cpa16(sa + 16, Dh + pga + (KT) + 8);                                    \
        cpa16(sb,      Wh + pgb + (KT));                                        \
        cpa16(sb + 16, Wh + pgb + (KT) + 8);                                    \
        asm volatile("cp.async.commit_group;");                                 \
    }

    TPREF(0, 0)

#pragma unroll
    for (int it = 0; it < 8; it++) {
        if (it < 7) {
            TPREF((it + 1) & 1, (it + 1) * 32)
            asm volatile("cp.async.wait_group 1;");
        } else {
            asm volatile("cp.async.wait_group 0;");
        }
        __syncthreads();

        const uint32_t sA = smem_u32(&sm[it & 1][0][0]);
        const uint32_t sB = smem_u32(&sm[it & 1][1][0]);
#pragma unroll
        for (int ks = 0; ks < 2; ks++) {
            const uint32_t kso = ks * 32;
            uint32_t ah[2][4];
            ldsm4(ah[0], sA + a_off + kso);
            ldsm4(ah[1], sA + a_off + kso + 16 * SMS * 2);
#pragma unroll
            for (int njp = 0; njp < 4; njp++) {
                uint32_t bh[4];
                ldsm4(bh, sB + b_off + njp * (16 * SMS * 2) + kso);
#pragma unroll
                for (int mi = 0; mi < 2; mi++) {
#pragma unroll
                    for (int s = 0; s < 2; s++)
                        mma16816(acc[mi][njp * 2 + s], ah[mi],
                                 bh[2 * s], bh[2 * s + 1]);
                }
            }
        }
        __syncthreads();
    }
#undef TPREF

#pragma unroll
    for (int mi = 0; mi < 2; mi++) {
#pragma unroll
        for (int half = 0; half < 2; half++) {
            const int m = m_base + wm + mi * 16 + g + half * 8;
            const int mb = m / 7, mt = m - mb * 7;
#pragma unroll
            for (int nj = 0; nj < 8; nj++) {
                const int col = n_base + wn + nj * 8 + t4 * 2;
#pragma unroll
                for (int e = 0; e < 2; e++) {
                    const float v = acc[mi][nj][half * 2 + e];
                    const int cc = col + e;
                    if (MODE == 1) {
                        const float d = v * g_sig1[(size_t)mb * HID + cc];
                        g_D1h[(size_t)m * HID + cc] = __float2half_rn(d);
                    } else {
                        g_X2[((size_t)mb * 8 + 1 + mt) * HID + cc] =
                            v * g_sig2[(size_t)mb * HID + cc];
                    }
                }
            }
        }
    }
}

// ---------------- K7: heads GEMM ------------------------------------------------
__global__ __launch_bounds__(256) void k_heads(const float* __restrict__ Wg,
                                               const float* __restrict__ bg,
                                               const float* __restrict__ Wld,
                                               const float* __restrict__ bld,
                                               const float* __restrict__ Wlt,
                                               const float* __restrict__ blt)
{
    __shared__ float wsm[NHEAD][HID];
    __shared__ float bsm[NHEAD];
    const int tid = threadIdx.x;
    float* wf = &wsm[0][0];
    for (int i = tid; i < 7 * HID; i += 256)  wf[i] = Wg[i];
    for (int i = tid; i < 7 * HID; i += 256)  wf[7 * HID + i] = Wld[i];
    for (int i = tid; i < 21 * HID; i += 256) wf[14 * HID + i] = Wlt[i];
    if (tid < 7)  { bsm[tid] = bg[tid]; bsm[7 + tid] = bld[tid]; }
    if (tid < 21) bsm[14 + tid] = blt[tid];
    __syncthreads();

    const int warp = tid >> 5, lane = tid & 31;
    for (int rr = 0; rr < 8; rr++) {
        const int m = blockIdx.x * 64 + warp * 8 + rr;
        const float* xg = g_X2 + (size_t)m * HID;
        float x[8];
        *(float4*)(x)     = *(const float4*)(xg + lane * 8);
        *(float4*)(x + 4) = *(const float4*)(xg + lane * 8 + 4);
        const bool valrow = ((m & 7) == 0);
#pragma unroll
        for (int r = 0; r < NHEAD; r++) {
            float w[8];
            *(float4*)(w)     = *(const float4*)(&wsm[r][lane * 8]);
            *(float4*)(w + 4) = *(const float4*)(&wsm[r][lane * 8 + 4]);
            float p = 0.0f;
#pragma unroll
            for (int u = 0; u < 8; u++) p = fmaf(w[u], x[u], p);
            p += __shfl_xor_sync(0xffffffff, p, 16);
            p += __shfl_xor_sync(0xffffffff, p, 8);
            p += __shfl_xor_sync(0xffffffff, p, 4);
            p += __shfl_xor_sync(0xffffffff, p, 2);
            p += __shfl_xor_sync(0xffffffff, p, 1);
            if (lane == 0)
                g_Yh[(size_t)m * NHEAD + r] = p + (valrow ? bsm[r] : 0.0f);
        }
    }
}

// ---------------- K8: per-sample dynamics --------------------------------------
__global__ __launch_bounds__(128) void k_dyn(const float* __restrict__ qd_g,
                                             const float* __restrict__ qdd_g,
                                             const float* __restrict__ fd,
                                             const float* __restrict__ fc,
                                             const float* __restrict__ fs,
                                             const float* __restrict__ fv,
                                             float* __restrict__ out)
{
    const int b = blockIdx.x * 128 + threadIdx.x;
    if (b >= BATCH) return;
    const int R[21]  = {1,2,2,3,3,3,4,4,4,4,5,5,5,5,5,6,6,6,6,6,6};
    const int Cc[21] = {0,0,1,0,1,2,0,1,2,3,0,1,2,3,4,0,1,2,3,4,5};

    const float* Y = g_Yh + (size_t)b * 8 * NHEAD;
    float qd[7], qdd[7], gv[7], ldr[7], sigd[7];
#pragma unroll
    for (int i = 0; i < 7; i++) {
        qd[i]  = qd_g [b * 7 + i];
        qdd[i] = qdd_g[b * 7 + i];
        gv[i]  = Y[i];
        ldr[i] = Y[7 + i];
    }

    float L[7][7];
#pragma unroll
    for (int i = 0; i < 7; i++)
#pragma unroll
        for (int j = 0; j < 7; j++) L[i][j] = 0.0f;
#pragma unroll
    for (int i = 0; i < 7; i++) {
        L[i][i]  = sp_f(ldr[i]) + 1e-3f;
        sigd[i]  = sg_f(ldr[i]);
    }
#pragma unroll
    for (int p = 0; p < 21; p++) L[R[p]][Cc[p]] = Y[14 + p];

    float a[7];
#pragma unroll
    for (int j = 0; j < 7; j++) {
        float s = 0.0f;
#pragma unroll
        for (int i = 0; i < 7; i++) if (i >= j) s = fmaf(L[i][j], qd[i], s);
        a[j] = s;
    }

    float Ldt[7][7];
#pragma unroll
    for (int i = 0; i < 7; i++)
#pragma unroll
        for (int j = 0; j < 7; j++) Ldt[i][j] = 0.0f;

    float svec[7];
#pragma unroll
    for (int c = 0; c < 7; c++) {
        const float* Yc = Y + (c + 1) * NHEAD;
        float dL[7][7];
#pragma unroll
        for (int i = 0; i < 7; i++)
#pragma unroll
            for (int j = 0; j < 7; j++) dL[i][j] = 0.0f;
#pragma unroll
        for (int i = 0; i < 7; i++) dL[i][i] = sigd[i] * Yc[7 + i];
#pragma unroll
        for (int p = 0; p < 21; p++) dL[R[p]][Cc[p]] = Yc[14 + p];
#pragma unroll
        for (int i = 0; i < 7; i++)
#pragma unroll
            for (int j = 0; j < 7; j++) if (j <= i)
                Ldt[i][j] = fmaf(qd[c], dL[i][j], Ldt[i][j]);
        float sc = 0.0f;
#pragma unroll
        for (int j = 0; j < 7; j++) {
            float v = 0.0f;
#pragma unroll
            for (int i = 0; i < 7; i++) if (i >= j) v = fmaf(qd[i], dL[i][j], v);
            sc = fmaf(v, a[j], sc);
        }
        svec[c] = 2.0f * sc;
    }

    float b2[7];
#pragma unroll
    for (int j = 0; j < 7; j++) {
        float s = 0.0f;
#pragma unroll
        for (int i = 0; i < 7; i++) if (i >= j) s = fmaf(Ldt[i][j], qd[i], s);
        b2[j] = s;
    }

    float cor[7];
#pragma unroll
    for (int i = 0; i < 7; i++) {
        float s = 0.0f;
#pragma unroll
        for (int j = 0; j < 7; j++) if (j <= i) s = fmaf(L[i][j], b2[j], s);
#pragma unroll
        for (int j = 0; j < 7; j++) if (j <= i) s = fmaf(Ldt[i][j], a[j], s);
        cor[i] = s - 0.5f * svec[i];
    }

    float Hm[7][7];
#pragma unroll
    for (int i = 0; i < 7; i++)
#pragma unroll
        for (int k = 0; k < 7; k++) {
            float s = 0.0f;
#pragma unroll
            for (int j = 0; j < 7; j++) if (j <= i && j <= k)
                s = fmaf(L[i][j], L[k][j], s);
            Hm[i][k] = s;
        }

    float fric[7];
#pragma unroll
    for (int i = 0; i < 7; i++) {
        const float fvc = fmaxf(fv[i], 1e-3f);
        fric[i] = (fc[i] + fs[i] * expf(-qd[i] * qd[i] / fvc)) *
                      tanhf(100.0f * qd[i]) + fd[i] * qd[i];
    }

    float tau[7];
#pragma unroll
    for (int i = 0; i < 7; i++) {
        float s = 0.0f;
#pragma unroll
        for (int k = 0; k < 7; k++) s = fmaf(Hm[i][k], qdd[k], s);
        tau[i] = s + cor[i] + gv[i] + fric[i];
    }

    const int Bc = BATCH;
#pragma unroll
    for (int i = 0; i < 7; i++) out[b * 7 + i] = tau[i];
#pragma unroll
    for (int i = 0; i < 7; i++)
#pragma unroll
        for (int k = 0; k < 7; k++) out[7 * Bc + b * 49 + i * 7 + k] = Hm[i][k];
#pragma unroll
    for (int i = 0; i < 7; i++) out[56 * Bc + b * 7 + i] = cor[i];
#pragma unroll
    for (int i = 0; i < 7; i++) out[63 * Bc + b * 7 + i] = gv[i];
#pragma unroll
    for (int i = 0; i < 7; i++) out[70 * Bc + b * 7 + i] = fric[i];
#pragma unroll
    for (int i = 0; i < 7; i++) out[77 * Bc + b * 7 + i] = ldr[i];
}

// ---------------- launch --------------------------------------------------------
extern "C" void kernel_launch(void* const* d_in, const int* in_sizes, int n_in,
                              void* d_out, int out_size)
{
    (void)in_sizes; (void)n_in; (void)out_size;
    const float* q   = (const float*)d_in[0];
    const float* qd  = (const float*)d_in[1];
    const float* qdd = (const float*)d_in[2];
    const float* W0  = (const float*)d_in[3];
    const float* b0  = (const float*)d_in[4];
    const float* W1  = (const float*)d_in[5];
    const float* b1  = (const float*)d_in[6];
    const float* W2  = (const float*)d_in[7];
    const float* b2  = (const float*)d_in[8];
    const float* Wg  = (const float*)d_in[9];
    const float* bg  = (const float*)d_in[10];
    const float* Wld = (const float*)d_in[11];
    const float* bld = (const float*)d_in[12];
    const float* Wlt = (const float*)d_in[13];
    const float* blt = (const float*)d_in[14];
    const float* fd  = (const float*)d_in[15];
    const float* fc  = (const float*)d_in[16];
    const float* fs  = (const float*)d_in[17];
    const float* fv  = (const float*)d_in[18];
    float* out = (float*)d_out;

    cudaFuncSetAttribute(mma_gemm<0>, cudaFuncAttributeMaxDynamicSharedMemorySize, SMEM_TOT);
    cudaFuncSetAttribute(mma_gemm<2>, cudaFuncAttributeMaxDynamicSharedMemorySize, SMEM_TOT);

    k_wsplit<<<HID * HID / 256, 256>>>(W1, W2);
    k_layer0<<<BATCH / 32, 256>>>(q, W0, b0);
    k_d0<<<BATCH, 256>>>(W0);
    mma_gemm<0><<<dim3(2, BATCH / 128), 256, SMEM_TOT>>>(b1);        // h1, sig1
    tan_gemm<1><<<dim3(2, (BATCH * 7) / 128), 256>>>();              // D1
    mma_gemm<2><<<dim3(2, BATCH / 128), 256, SMEM_TOT>>>(b2);        // h2, sig2
    tan_gemm<3><<<dim3(2, (BATCH * 7) / 128), 256>>>();              // X2 tangents
    k_heads<<<(BATCH * 8) / 64, 256>>>(Wg, bg, Wld, bld, Wlt, blt);
    k_dyn<<<(BATCH + 127) / 128, 128>>>(qd, qdd, fd, fc, fs, fv, out);
}

// round 7
// speedup vs baseline: 2.9744x; 1.4901x over previous
#include <cuda_runtime.h>
#include <cuda_fp16.h>
#include <math.h>
#include <stdint.h>

#define BATCH 32768
#define HID 256
#define NDOF 7
#define NTRIL 21
#define NHEAD 35   // 7 g + 7 Ld + 21 Lt

typedef __half fp16;

// ---------------- scratch (device globals; no allocation allowed) -------------
__device__ fp16  g_h0h [BATCH * HID];
__device__ fp16  g_h0l [BATCH * HID];
__device__ fp16  g_h1h [BATCH * HID];
__device__ fp16  g_h1l [BATCH * HID];
__device__ fp16  g_D0h [(size_t)BATCH * 7 * HID];   // tangent: hi only (1-term)
__device__ fp16  g_D1h [(size_t)BATCH * 7 * HID];
__device__ float g_sig0[BATCH * HID];
__device__ float g_sig1[BATCH * HID];
__device__ float g_sig2[BATCH * HID];
__device__ fp16  g_X2h [(size_t)BATCH * 8 * HID];   // vec0 = h2, vec 1..7 = dh2/dq_t
__device__ fp16  g_X2l [(size_t)BATCH * 8 * HID];
__device__ float g_Yh  [(size_t)BATCH * 8 * NHEAD];
__device__ fp16  g_W1h[HID * HID];
__device__ fp16  g_W1l[HID * HID];
__device__ fp16  g_W2h[HID * HID];
__device__ fp16  g_W2l[HID * HID];
__device__ fp16  g_WHh[64 * HID];                   // padded head weights (35->64)
__device__ fp16  g_WHl[64 * HID];
__device__ float g_bH [64];

// ---------------- helpers ------------------------------------------------------
__device__ __forceinline__ float sp_f(float x) {
    return fmaxf(x, 0.0f) + log1pf(expf(-fabsf(x)));
}
__device__ __forceinline__ float sg_f(float x) {
    return 1.0f / (1.0f + expf(-x));
}
__device__ __forceinline__ void split_h(float x, fp16& h, fp16& l) {
    h = __float2half_rn(x);
    l = __float2half_rn(x - __half2float(h));
}
__device__ __forceinline__ void mma16816(float c[4], const uint32_t a[4],
                                         uint32_t b0, uint32_t b1) {
    asm volatile(
        "mma.sync.aligned.m16n8k16.row.col.f32.f16.f16.f32 "
        "{%0,%1,%2,%3}, {%4,%5,%6,%7}, {%8,%9}, {%0,%1,%2,%3};"
        : "+f"(c[0]), "+f"(c[1]), "+f"(c[2]), "+f"(c[3])
        : "r"(a[0]), "r"(a[1]), "r"(a[2]), "r"(a[3]), "r"(b0), "r"(b1));
}
__device__ __forceinline__ void ldsm4(uint32_t r[4], uint32_t addr) {
    asm volatile("ldmatrix.sync.aligned.m8n8.x4.shared.b16 {%0,%1,%2,%3}, [%4];"
                 : "=r"(r[0]), "=r"(r[1]), "=r"(r[2]), "=r"(r[3]) : "r"(addr));
}
__device__ __forceinline__ uint32_t smem_u32(const void* p) {
    uint32_t a;
    asm("{ .reg .u64 t; cvta.to.shared.u64 t, %1; cvt.u32.u64 %0, t; }"
        : "=r"(a) : "l"(p));
    return a;
}
__device__ __forceinline__ void cpa16(uint32_t s, const void* g) {
    asm volatile("cp.async.cg.shared.global [%0], [%1], 16;" :: "r"(s), "l"(g));
}

// ---------------- K0a: W1/W2 hi/lo split ---------------------------------------
__global__ __launch_bounds__(256) void k_wsplit(const float* __restrict__ W1,
                                                const float* __restrict__ W2)
{
    const int i = blockIdx.x * 256 + threadIdx.x;
    split_h(W1[i], g_W1h[i], g_W1l[i]);
    split_h(W2[i], g_W2h[i], g_W2l[i]);
}

// ---------------- K0b: padded head weights + bias ------------------------------
__global__ __launch_bounds__(256) void k_whead(const float* __restrict__ Wg,
                                               const float* __restrict__ bg,
                                               const float* __restrict__ Wld,
                                               const float* __restrict__ bld,
                                               const float* __restrict__ Wlt,
                                               const float* __restrict__ blt)
{
    const int i = blockIdx.x * 256 + threadIdx.x;   // 0..16383
    const int r = i >> 8, k = i & 255;
    float v = 0.0f;
    if      (r < 7)  v = Wg [r * HID + k];
    else if (r < 14) v = Wld[(r - 7) * HID + k];
    else if (r < 35) v = Wlt[(r - 14) * HID + k];
    split_h(v, g_WHh[i], g_WHl[i]);
    if (i < 64) {
        float b = 0.0f;
        if      (i < 7)  b = bg [i];
        else if (i < 14) b = bld[i - 7];
        else if (i < 35) b = blt[i - 14];
        g_bH[i] = b;
    }
}

// ---------------- K1: layer0 values -------------------------------------------
__global__ __launch_bounds__(256) void k_layer0(const float* __restrict__ q,
                                                const float* __restrict__ W0,
                                                const float* __restrict__ b0)
{
    __shared__ float qs[32][8];
    const int j  = threadIdx.x;
    const int s0 = blockIdx.x * 32;
    for (int idx = threadIdx.x; idx < 32 * 7; idx += 256)
        qs[idx / 7][idx % 7] = q[(s0 + idx / 7) * 7 + idx % 7];
    float w[7];
#pragma unroll
    for (int i = 0; i < 7; i++) w[i] = W0[j * 7 + i];
    const float bb = b0[j];
    __syncthreads();
    for (int s = 0; s < 32; s++) {
        float pre = bb;
#pragma unroll
        for (int i = 0; i < 7; i++) pre = fmaf(w[i], qs[s][i], pre);
        const int off = (s0 + s) * HID + j;
        split_h(sp_f(pre), g_h0h[off], g_h0l[off]);
        g_sig0[off] = sg_f(pre);
    }
}

// ---------------- K4: tangent seeds  D0[b][t][k] = sig0[b][k] * W0[k][t] -------
__global__ __launch_bounds__(256) void k_d0(const float* __restrict__ W0)
{
    const int idx = blockIdx.x * 256 + threadIdx.x;
    const int k = idx & 255;
    const int b = idx >> 8;
    const float s = g_sig0[idx];
#pragma unroll
    for (int t = 0; t < 7; t++)
        g_D0h[(size_t)(b * 7 + t) * HID + k] = __float2half_rn(s * W0[k * 7 + t]);
}

// ---------------- VALUE GEMM (3-term fp16): C[M,256] = A @ W^T ------------------
#define SMS 40
#define ASZB 10240            // bytes per array (128*40*2)
#define STGB 40960            // bytes per stage
#define SMEM_TOT (2 * STGB)   // 80 KB dynamic

template <int MODE>       // 0: layer1  2: layer2
__global__ __launch_bounds__(256, 2) void mma_gemm(const float* __restrict__ bias)
{
    extern __shared__ __align__(16) fp16 smdyn[];
    const uint32_t smb = smem_u32(smdyn);

    const int tid  = threadIdx.x;
    const int warp = tid >> 5, lane = tid & 31;
    const int wm = (warp >> 1) * 32;
    const int wn = (warp & 1) * 64;
    const int g  = lane >> 2, t4 = lane & 3;

    const int m_base = blockIdx.y * 128;
    const int n_base = blockIdx.x * 128;

    const fp16 *Ah, *Al, *Bh, *Bl;
    if (MODE == 0) { Ah = g_h0h; Al = g_h0l; Bh = g_W1h; Bl = g_W1l; }
    else           { Ah = g_h1h; Al = g_h1l; Bh = g_W2h; Bl = g_W2l; }

    const int prow = tid >> 1;
    const int pc   = (tid & 1) * 16;
    const uint32_t pdst = (uint32_t)(prow * SMS + pc) * 2;
    const size_t   pga  = (size_t)(m_base + prow) * HID + pc;
    const size_t   pgb  = (size_t)(n_base + prow) * HID + pc;

    const uint32_t a_off = (uint32_t)(((wm + (lane & 15)) * SMS) + ((lane >> 4) << 3)) * 2;
    const uint32_t b_off = (uint32_t)(((wn + ((lane >> 4) << 3) + (lane & 7)) * SMS)
                                      + (((lane >> 3) & 1) << 3)) * 2;

    float acc[2][8][4];
#pragma unroll
    for (int a = 0; a < 2; a++)
#pragma unroll
        for (int b = 0; b < 8; b++)
#pragma unroll
            for (int c = 0; c < 4; c++) acc[a][b][c] = 0.0f;

#define PREFETCH(STAGE, KT)                                                     \
    {                                                                           \
        const uint32_t sb = smb + (STAGE) * STGB + pdst;                        \
        cpa16(sb,                 Ah + pga + (KT));                             \
        cpa16(sb + 16,            Ah + pga + (KT) + 8);                         \
        cpa16(sb + ASZB,          Al + pga + (KT));                             \
        cpa16(sb + ASZB + 16,     Al + pga + (KT) + 8);                         \
        cpa16(sb + 2 * ASZB,      Bh + pgb + (KT));                             \
        cpa16(sb + 2 * ASZB + 16, Bh + pgb + (KT) + 8);                         \
        cpa16(sb + 3 * ASZB,      Bl + pgb + (KT));                             \
        cpa16(sb + 3 * ASZB + 16, Bl + pgb + (KT) + 8);                         \
        asm volatile("cp.async.commit_group;");                                 \
    }

    PREFETCH(0, 0)

#pragma unroll
    for (int it = 0; it < 8; it++) {
        if (it < 7) {
            PREFETCH((it + 1) & 1, (it + 1) * 32)
            asm volatile("cp.async.wait_group 1;");
        } else {
            asm volatile("cp.async.wait_group 0;");
        }
        __syncthreads();

        const uint32_t sbase = smb + (it & 1) * STGB;
#pragma unroll
        for (int ks = 0; ks < 2; ks++) {
            const uint32_t kso = ks * 32;
            uint32_t ah[2][4], al[2][4];
            ldsm4(ah[0], sbase + a_off + kso);
            ldsm4(ah[1], sbase + a_off + kso + 16 * SMS * 2);
            ldsm4(al[0], sbase + ASZB + a_off + kso);
            ldsm4(al[1], sbase + ASZB + a_off + kso + 16 * SMS * 2);
#pragma unroll
            for (int njp = 0; njp < 4; njp++) {
                uint32_t bh[4], bl[4];
                ldsm4(bh, sbase + 2 * ASZB + b_off + njp * (16 * SMS * 2) + kso);
                ldsm4(bl, sbase + 3 * ASZB + b_off + njp * (16 * SMS * 2) + kso);
#pragma unroll
                for (int mi = 0; mi < 2; mi++) {
#pragma unroll
                    for (int s = 0; s < 2; s++) {
                        float* C = acc[mi][njp * 2 + s];
                        mma16816(C, ah[mi], bh[2 * s], bh[2 * s + 1]);
                        mma16816(C, al[mi], bh[2 * s], bh[2 * s + 1]);
                        mma16816(C, ah[mi], bl[2 * s], bl[2 * s + 1]);
                    }
                }
            }
        }
        __syncthreads();
    }
#undef PREFETCH

#pragma unroll
    for (int mi = 0; mi < 2; mi++) {
#pragma unroll
        for (int half = 0; half < 2; half++) {
            const int m = m_base + wm + mi * 16 + g + half * 8;
#pragma unroll
            for (int nj = 0; nj < 8; nj++) {
                const int col = n_base + wn + nj * 8 + t4 * 2;
#pragma unroll
                for (int e = 0; e < 2; e++) {
                    const float v = acc[mi][nj][half * 2 + e];
                    const int cc = col + e;
                    const float pre = v + bias[cc];
                    if (MODE == 0) {
                        const size_t o = (size_t)m * HID + cc;
                        split_h(sp_f(pre), g_h1h[o], g_h1l[o]);
                        g_sig1[o] = sg_f(pre);
                    } else {
                        const size_t o2 = (size_t)m * 8 * HID + cc;
                        split_h(sp_f(pre), g_X2h[o2], g_X2l[o2]);
                        g_sig2[(size_t)m * HID + cc] = sg_f(pre);
                    }
                }
            }
        }
    }
}

// ---------------- TANGENT GEMM (1-term fp16): C[M,256] = D @ W^T ---------------
template <int MODE>       // 1: D0->D1 (scale sig1)  3: D1->X2 (scale sig2)
__global__ __launch_bounds__(256, 2) void tan_gemm()
{
    __shared__ __align__(16) fp16 sm[2][2][128 * SMS];   // [stage][A/B]

    const int tid  = threadIdx.x;
    const int warp = tid >> 5, lane = tid & 31;
    const int wm = (warp >> 1) * 32;
    const int wn = (warp & 1) * 64;
    const int g  = lane >> 2, t4 = lane & 3;

    const int m_base = blockIdx.y * 128;
    const int n_base = blockIdx.x * 128;

    const fp16* Dh = (MODE == 1) ? g_D0h : g_D1h;
    const fp16* Wh = (MODE == 1) ? g_W1h : g_W2h;

    const int prow = tid >> 1;
    const int pc   = (tid & 1) * 16;
    const uint32_t pdst = (uint32_t)(prow * SMS + pc) * 2;
    const size_t   pga  = (size_t)(m_base + prow) * HID + pc;
    const size_t   pgb  = (size_t)(n_base + prow) * HID + pc;

    const uint32_t a_off = (uint32_t)(((wm + (lane & 15)) * SMS) + ((lane >> 4) << 3)) * 2;
    const uint32_t b_off = (uint32_t)(((wn + ((lane >> 4) << 3) + (lane & 7)) * SMS)
                                      + (((lane >> 3) & 1) << 3)) * 2;

    float acc[2][8][4];
#pragma unroll
    for (int a = 0; a < 2; a++)
#pragma unroll
        for (int b = 0; b < 8; b++)
#pragma unroll
            for (int c = 0; c < 4; c++) acc[a][b][c] = 0.0f;

#define TPREF(STAGE, KT)                                                        \
    {                                                                           \
        const uint32_t sa = smem_u32(&sm[STAGE][0][0]) + pdst;                  \
        const uint32_t sb = smem_u32(&sm[STAGE][1][0]) + pdst;                  \
        cpa16(sa,      Dh + pga + (KT));                                        \
        cpa16(sa + 16, Dh + pga + (KT) + 8);                                    \
        cpa16(sb,      Wh + pgb + (KT));                                        \
        cpa16(sb + 16, Wh + pgb + (KT) + 8);                                    \
        asm volatile("cp.async.commit_group;");                                 \
    }

    TPREF(0, 0)

#pragma unroll
    for (int it = 0; it < 8; it++) {
        if (it < 7) {
            TPREF((it + 1) & 1, (it + 1) * 32)
            asm volatile("cp.async.wait_group 1;");
        } else {
            asm volatile("cp.async.wait_group 0;");
        }
        __syncthreads();

        const uint32_t sA = smem_u32(&sm[it & 1][0][0]);
        const uint32_t sB = smem_u32(&sm[it & 1][1][0]);
#pragma unroll
        for (int ks = 0; ks < 2; ks++) {
            const uint32_t kso = ks * 32;
            uint32_t ah[2][4];
            ldsm4(ah[0], sA + a_off + kso);
            ldsm4(ah[1], sA + a_off + kso + 16 * SMS * 2);
#pragma unroll
            for (int njp = 0; njp < 4; njp++) {
                uint32_t bh[4];
                ldsm4(bh, sB + b_off + njp * (16 * SMS * 2) + kso);
#pragma unroll
                for (int mi = 0; mi < 2; mi++) {
#pragma unroll
                    for (int s = 0; s < 2; s++)
                        mma16816(acc[mi][njp * 2 + s], ah[mi],
                                 bh[2 * s], bh[2 * s + 1]);
                }
            }
        }
        __syncthreads();
    }
#undef TPREF

#pragma unroll
    for (int mi = 0; mi < 2; mi++) {
#pragma unroll
        for (int half = 0; half < 2; half++) {
            const int m = m_base + wm + mi * 16 + g + half * 8;
            const int mb = m / 7, mt = m - mb * 7;
#pragma unroll
            for (int nj = 0; nj < 8; nj++) {
                const int col = n_base + wn + nj * 8 + t4 * 2;
#pragma unroll
                for (int e = 0; e < 2; e++) {
                    const float v = acc[mi][nj][half * 2 + e];
                    const int cc = col + e;
                    if (MODE == 1) {
                        const float d = v * g_sig1[(size_t)mb * HID + cc];
                        g_D1h[(size_t)m * HID + cc] = __float2half_rn(d);
                    } else {
                        const size_t o2 = ((size_t)mb * 8 + 1 + mt) * HID + cc;
                        split_h(v * g_sig2[(size_t)mb * HID + cc],
                                g_X2h[o2], g_X2l[o2]);
                    }
                }
            }
        }
    }
}

// ---------------- heads GEMM via mma: Yh[M,35] = X2[M,256] @ WH^T --------------
#define HA 10240u              // A array bytes (128*40*2)
#define HB 5120u               // B array bytes (64*40*2)
#define HSTG (2 * HA + 2 * HB) // 30720
#define HSM (2 * HSTG)         // 61440 dynamic

__global__ __launch_bounds__(256, 2) void heads_mma()
{
    extern __shared__ __align__(16) fp16 smh[];
    const uint32_t smb = smem_u32(smh);

    const int tid  = threadIdx.x;
    const int warp = tid >> 5, lane = tid & 31;
    const int wm = (warp >> 1) * 32;    // 4 warps along M
    const int wn = (warp & 1) * 32;     // 2 warps along N (64 total)
    const int g  = lane >> 2, t4 = lane & 3;
    const size_t m_base = (size_t)blockIdx.x * 128;

    const uint32_t a_off = (uint32_t)(((wm + (lane & 15)) * SMS) + ((lane >> 4) << 3)) * 2;
    const uint32_t b_off = (uint32_t)(((wn + ((lane >> 4) << 3) + (lane & 7)) * SMS)
                                      + (((lane >> 3) & 1) << 3)) * 2;

    float acc[2][4][4];
#pragma unroll
    for (int a = 0; a < 2; a++)
#pragma unroll
        for (int b = 0; b < 4; b++)
#pragma unroll
            for (int c = 0; c < 4; c++) acc[a][b][c] = 0.0f;

#define HPREF(STAGE, KT)                                                        \
    {                                                                           \
        const uint32_t sb = smb + (STAGE) * HSTG;                               \
        _Pragma("unroll")                                                       \
        for (int kk = 0; kk < 2; kk++) {                                        \
            const int u = tid + kk * 256;                                       \
            const int r = u >> 2, qq = u & 3;                                   \
            const uint32_t d = sb + (uint32_t)(r * 80 + qq * 16);               \
            const size_t so = (m_base + r) * HID + (KT) + qq * 8;               \
            cpa16(d,      g_X2h + so);                                          \
            cpa16(d + HA, g_X2l + so);                                          \
        }                                                                       \
        {                                                                       \
            const int r = tid >> 2, qq = tid & 3;                               \
            const uint32_t d = sb + 2 * HA + (uint32_t)(r * 80 + qq * 16);      \
            const size_t so = (size_t)r * HID + (KT) + qq * 8;                  \
            cpa16(d,      g_WHh + so);                                          \
            cpa16(d + HB, g_WHl + so);                                          \
        }                                                                       \
        asm volatile("cp.async.commit_group;");                                 \
    }

    HPREF(0, 0)

#pragma unroll
    for (int it = 0; it < 8; it++) {
        if (it < 7) {
            HPREF((it + 1) & 1, (it + 1) * 32)
            asm volatile("cp.async.wait_group 1;");
        } else {
            asm volatile("cp.async.wait_group 0;");
        }
        __syncthreads();

        const uint32_t sb = smb + (it & 1) * HSTG;
#pragma unroll
        for (int ks = 0; ks < 2; ks++) {
            const uint32_t kso = ks * 32;
            uint32_t ah[2][4], al[2][4];
            ldsm4(ah[0], sb + a_off + kso);
            ldsm4(ah[1], sb + a_off + kso + 16 * SMS * 2);
            ldsm4(al[0], sb + HA + a_off + kso);
            ldsm4(al[1], sb + HA + a_off + kso + 16 * SMS * 2);
#pragma unroll
            for (int njp = 0; njp < 2; njp++) {
                uint32_t bh[4], bl[4];
                ldsm4(bh, sb + 2 * HA + b_off + njp * (16 * SMS * 2) + kso);
                ldsm4(bl, sb + 2 * HA + HB + b_off + njp * (16 * SMS * 2) + kso);
#pragma unroll
                for (int mi = 0; mi < 2; mi++) {
#pragma unroll
                    for (int s = 0; s < 2; s++) {
                        float* C = acc[mi][njp * 2 + s];
                        mma16816(C, ah[mi], bh[2 * s], bh[2 * s + 1]);
                        mma16816(C, al[mi], bh[2 * s], bh[2 * s + 1]);
                        mma16816(C, ah[mi], bl[2 * s], bl[2 * s + 1]);
                    }
                }
            }
        }
        __syncthreads();
    }
#undef HPREF

#pragma unroll
    for (int mi = 0; mi < 2; mi++) {
#pragma unroll
        for (int half = 0; half < 2; half++) {
            const size_t m = m_base + wm + mi * 16 + g + half * 8;
            const bool valrow = ((m & 7) == 0);
#pragma unroll
            for (int nj = 0; nj < 4; nj++) {
                const int col = wn + nj * 8 + t4 * 2;
#pragma unroll
                for (int e = 0; e < 2; e++) {
                    const int r = col + e;
                    if (r < NHEAD) {
                        const float v = acc[mi][nj][half * 2 + e]
                                      + (valrow ? g_bH[r] : 0.0f);
                        g_Yh[m * NHEAD + r] = v;
                    }
                }
            }
        }
    }
}

// ---------------- K8: per-sample dynamics (flat triangular) --------------------
#define POS(i, j) ((i) * ((i) + 1) / 2 + (j))

__global__ __launch_bounds__(128) void k_dyn(const float* __restrict__ qd_g,
                                             const float* __restrict__ qdd_g,
                                             const float* __restrict__ fd,
                                             const float* __restrict__ fc,
                                             const float* __restrict__ fs,
                                             const float* __restrict__ fv,
                                             float* __restrict__ out)
{
    const int b = blockIdx.x * 128 + threadIdx.x;
    if (b >= BATCH) return;
    const int R[21]  = {1,2,2,3,3,3,4,4,4,4,5,5,5,5,5,6,6,6,6,6,6};
    const int Cc[21] = {0,0,1,0,1,2,0,1,2,3,0,1,2,3,4,0,1,2,3,4,5};

    const float* Y = g_Yh + (size_t)b * 8 * NHEAD;
    float qd[7], qdd[7], gv[7], ldr[7], sigd[7];
#pragma unroll
    for (int i = 0; i < 7; i++) {
        qd[i]  = qd_g [b * 7 + i];
        qdd[i] = qdd_g[b * 7 + i];
        gv[i]  = Y[i];
        ldr[i] = Y[7 + i];
    }

    float Lf[28];
#pragma unroll
    for (int i = 0; i < 7; i++) {
        Lf[POS(i, i)] = sp_f(ldr[i]) + 1e-3f;
        sigd[i] = sg_f(ldr[i]);
    }
#pragma unroll
    for (int p = 0; p < 21; p++) Lf[POS(R[p], Cc[p])] = Y[14 + p];

    // a = L^T qd
    float a[7];
#pragma unroll
    for (int j = 0; j < 7; j++) {
        float s = 0.0f;
#pragma unroll
        for (int i = 0; i < 7; i++) if (i >= j) s = fmaf(Lf[POS(i, j)], qd[i], s);
        a[j] = s;
    }

    float Ldt[28];
#pragma unroll
    for (int f = 0; f < 28; f++) Ldt[f] = 0.0f;

    float svec[7];
#pragma unroll
    for (int c = 0; c < 7; c++) {
        const float* Yc = Y + (c + 1) * NHEAD;
        float dLf[28];
#pragma unroll
        for (int i = 0; i < 7; i++) dLf[POS(i, i)] = sigd[i] * Yc[7 + i];
#pragma unroll
        for (int p = 0; p < 21; p++) dLf[POS(R[p], Cc[p])] = Yc[14 + p];
#pragma unroll
        for (int f = 0; f < 28; f++) Ldt[f] = fmaf(qd[c], dLf[f], Ldt[f]);
        float sc = 0.0f;
#pragma unroll
        for (int j = 0; j < 7; j++) {
            float v = 0.0f;
#pragma unroll
            for (int i = 0; i < 7; i++) if (i >= j) v = fmaf(qd[i], dLf[POS(i, j)], v);
            sc = fmaf(v, a[j], sc);
        }
        svec[c] = 2.0f * sc;
    }

    // b2 = Ldt^T qd
    float b2[7];
#pragma unroll
    for (int j = 0; j < 7; j++) {
        float s = 0.0f;
#pragma unroll
        for (int i = 0; i < 7; i++) if (i >= j) s = fmaf(Ldt[POS(i, j)], qd[i], s);
        b2[j] = s;
    }

    float cor[7];
#pragma unroll
    for (int i = 0; i < 7; i++) {
        float s = 0.0f;
#pragma unroll
        for (int j = 0; j < 7; j++) if (j <= i) s = fmaf(Lf[POS(i, j)], b2[j], s);
#pragma unroll
        for (int j = 0; j < 7; j++) if (j <= i) s = fmaf(Ldt[POS(i, j)], a[j], s);
        cor[i] = s - 0.5f * svec[i];
    }

    // Hm lower triangle (symmetric)
    float Hmf[28];
#pragma unroll
    for (int i = 0; i < 7; i++)
#pragma unroll
        for (int k = 0; k < 7; k++) if (k <= i) {
            float s = 0.0f;
#pragma unroll
            for (int j = 0; j < 7; j++) if (j <= k)
                s = fmaf(Lf[POS(i, j)], Lf[POS(k, j)], s);
            Hmf[POS(i, k)] = s;
        }

    float fric[7];
#pragma unroll
    for (int i = 0; i < 7; i++) {
        const float fvc = fmaxf(fv[i], 1e-3f);
        fric[i] = (fc[i] + fs[i] * expf(-qd[i] * qd[i] / fvc)) *
                      tanhf(100.0f * qd[i]) + fd[i] * qd[i];
    }

    float tau[7];
#pragma unroll
    for (int i = 0; i < 7; i++) {
        float s = 0.0f;
#pragma unroll
        for (int k = 0; k < 7; k++) {
            const float h = (k <= i) ? Hmf[POS(i, k)] : Hmf[POS(k, i)];
            s = fmaf(h, qdd[k], s);
        }
        tau[i] = s + cor[i] + gv[i] + fric[i];
    }

    const int Bc = BATCH;
#pragma unroll
    for (int i = 0; i < 7; i++) out[b * 7 + i] = tau[i];
#pragma unroll
    for (int i = 0; i < 7; i++)
#pragma unroll
        for (int k = 0; k < 7; k++)
            out[7 * Bc + b * 49 + i * 7 + k] =
                (k <= i) ? Hmf[POS(i, k)] : Hmf[POS(k, i)];
#pragma unroll
    for (int i = 0; i < 7; i++) out[56 * Bc + b * 7 + i] = cor[i];
#pragma unroll
    for (int i = 0; i < 7; i++) out[63 * Bc + b * 7 + i] = gv[i];
#pragma unroll
    for (int i = 0; i < 7; i++) out[70 * Bc + b * 7 + i] = fric[i];
#pragma unroll
    for (int i = 0; i < 7; i++) out[77 * Bc + b * 7 + i] = ldr[i];
}

// ---------------- launch --------------------------------------------------------
extern "C" void kernel_launch(void* const* d_in, const int* in_sizes, int n_in,
                              void* d_out, int out_size)
{
    (void)in_sizes; (void)n_in; (void)out_size;
    const float* q   = (const float*)d_in[0];
    const float* qd  = (const float*)d_in[1];
    const float* qdd = (const float*)d_in[2];
    const float* W0  = (const float*)d_in[3];
    const float* b0  = (const float*)d_in[4];
    const float* W1  = (const float*)d_in[5];
    const float* b1  = (const float*)d_in[6];
    const float* W2  = (const float*)d_in[7];
    const float* b2  = (const float*)d_in[8];
    const float* Wg  = (const float*)d_in[9];
    const float* bg  = (const float*)d_in[10];
    const float* Wld = (const float*)d_in[11];
    const float* bld = (const float*)d_in[12];
    const float* Wlt = (const float*)d_in[13];
    const float* blt = (const float*)d_in[14];
    const float* fd  = (const float*)d_in[15];
    const float* fc  = (const float*)d_in[16];
    const float* fs  = (const float*)d_in[17];
    const float* fv  = (const float*)d_in[18];
    float* out = (float*)d_out;

    cudaFuncSetAttribute(mma_gemm<0>, cudaFuncAttributeMaxDynamicSharedMemorySize, SMEM_TOT);
    cudaFuncSetAttribute(mma_gemm<2>, cudaFuncAttributeMaxDynamicSharedMemorySize, SMEM_TOT);
    cudaFuncSetAttribute(heads_mma, cudaFuncAttributeMaxDynamicSharedMemorySize, HSM);

    k_wsplit<<<HID * HID / 256, 256>>>(W1, W2);
    k_whead<<<64, 256>>>(Wg, bg, Wld, bld, Wlt, blt);
    k_layer0<<<BATCH / 32, 256>>>(q, W0, b0);
    k_d0<<<BATCH, 256>>>(W0);
    mma_gemm<0><<<dim3(2, BATCH / 128), 256, SMEM_TOT>>>(b1);        // h1, sig1
    tan_gemm<1><<<dim3(2, (BATCH * 7) / 128), 256>>>();              // D1
    mma_gemm<2><<<dim3(2, BATCH / 128), 256, SMEM_TOT>>>(b2);        // h2, sig2
    tan_gemm<3><<<dim3(2, (BATCH * 7) / 128), 256>>>();              // X2 tangents
    heads_mma<<<(BATCH * 8) / 128, 256, HSM>>>();                    // Yh
    k_dyn<<<(BATCH + 127) / 128, 128>>>(qd, qdd, fd, fc, fs, fv, out);
}

// round 8
// speedup vs baseline: 3.4984x; 1.1762x over previous
#include <cuda_runtime.h>
#include <cuda_fp16.h>
#include <math.h>
#include <stdint.h>

#define BATCH 32768
#define HID 256
#define NDOF 7
#define NTRIL 21
#define NHEAD 35   // 7 g + 7 Ld + 21 Lt

typedef __half fp16;

// ---------------- scratch (device globals; no allocation allowed) -------------
__device__ fp16  g_h0h [BATCH * HID];
__device__ fp16  g_h0l [BATCH * HID];
__device__ fp16  g_h1h [BATCH * HID];
__device__ fp16  g_h1l [BATCH * HID];
__device__ fp16  g_D0h [(size_t)BATCH * 7 * HID];   // tangent: hi only (1-term)
__device__ fp16  g_D1h [(size_t)BATCH * 7 * HID];
__device__ fp16  g_T2  [(size_t)BATCH * 7 * HID];   // layer2 tangents (hi only)
__device__ float g_sig1[BATCH * HID];
__device__ float g_sig2[BATCH * HID];
__device__ fp16  g_X2h [BATCH * HID];               // value h2 (hi/lo)
__device__ fp16  g_X2l [BATCH * HID];
__device__ float g_Yh  [(size_t)BATCH * 8 * NHEAD];
__device__ fp16  g_W1h[HID * HID];
__device__ fp16  g_W1l[HID * HID];
__device__ fp16  g_W2h[HID * HID];
__device__ fp16  g_W2l[HID * HID];
__device__ fp16  g_WHh[64 * HID];                   // padded head weights (35->64)
__device__ fp16  g_WHl[64 * HID];
__device__ float g_bH [64];

// ---------------- helpers ------------------------------------------------------
__device__ __forceinline__ float sp_f(float x) {
    return fmaxf(x, 0.0f) + log1pf(expf(-fabsf(x)));
}
__device__ __forceinline__ float sg_f(float x) {
    return 1.0f / (1.0f + expf(-x));
}
__device__ __forceinline__ void split_h(float x, fp16& h, fp16& l) {
    h = __float2half_rn(x);
    l = __float2half_rn(x - __half2float(h));
}
__device__ __forceinline__ void mma16816(float c[4], const uint32_t a[4],
                                         uint32_t b0, uint32_t b1) {
    asm volatile(
        "mma.sync.aligned.m16n8k16.row.col.f32.f16.f16.f32 "
        "{%0,%1,%2,%3}, {%4,%5,%6,%7}, {%8,%9}, {%0,%1,%2,%3};"
        : "+f"(c[0]), "+f"(c[1]), "+f"(c[2]), "+f"(c[3])
        : "r"(a[0]), "r"(a[1]), "r"(a[2]), "r"(a[3]), "r"(b0), "r"(b1));
}
__device__ __forceinline__ void ldsm4(uint32_t r[4], uint32_t addr) {
    asm volatile("ldmatrix.sync.aligned.m8n8.x4.shared.b16 {%0,%1,%2,%3}, [%4];"
                 : "=r"(r[0]), "=r"(r[1]), "=r"(r[2]), "=r"(r[3]) : "r"(addr));
}
__device__ __forceinline__ uint32_t smem_u32(const void* p) {
    uint32_t a;
    asm("{ .reg .u64 t; cvta.to.shared.u64 t, %1; cvt.u32.u64 %0, t; }"
        : "=r"(a) : "l"(p));
    return a;
}
__device__ __forceinline__ void cpa16(uint32_t s, const void* g) {
    asm volatile("cp.async.cg.shared.global [%0], [%1], 16;" :: "r"(s), "l"(g));
}

// ---------------- K0a: W1/W2 hi/lo split ---------------------------------------
__global__ __launch_bounds__(256) void k_wsplit(const float* __restrict__ W1,
                                                const float* __restrict__ W2)
{
    const int i = blockIdx.x * 256 + threadIdx.x;
    split_h(W1[i], g_W1h[i], g_W1l[i]);
    split_h(W2[i], g_W2h[i], g_W2l[i]);
}

// ---------------- K0b: padded head weights + bias ------------------------------
__global__ __launch_bounds__(256) void k_whead(const float* __restrict__ Wg,
                                               const float* __restrict__ bg,
                                               const float* __restrict__ Wld,
                                               const float* __restrict__ bld,
                                               const float* __restrict__ Wlt,
                                               const float* __restrict__ blt)
{
    const int i = blockIdx.x * 256 + threadIdx.x;   // 0..16383
    const int r = i >> 8, k = i & 255;
    float v = 0.0f;
    if      (r < 7)  v = Wg [r * HID + k];
    else if (r < 14) v = Wld[(r - 7) * HID + k];
    else if (r < 35) v = Wlt[(r - 14) * HID + k];
    split_h(v, g_WHh[i], g_WHl[i]);
    if (i < 64) {
        float b = 0.0f;
        if      (i < 7)  b = bg [i];
        else if (i < 14) b = bld[i - 7];
        else if (i < 35) b = blt[i - 14];
        g_bH[i] = b;
    }
}

// ---------------- K1: layer0 values + tangent seeds (fused) --------------------
__global__ __launch_bounds__(256) void k_layer0(const float* __restrict__ q,
                                                const float* __restrict__ W0,
                                                const float* __restrict__ b0)
{
    __shared__ float qs[32][8];
    const int j  = threadIdx.x;
    const int s0 = blockIdx.x * 32;
    for (int idx = threadIdx.x; idx < 32 * 7; idx += 256)
        qs[idx / 7][idx % 7] = q[(s0 + idx / 7) * 7 + idx % 7];
    float w[7];
#pragma unroll
    for (int i = 0; i < 7; i++) w[i] = W0[j * 7 + i];
    const float bb = b0[j];
    __syncthreads();
    for (int s = 0; s < 32; s++) {
        float pre = bb;
#pragma unroll
        for (int i = 0; i < 7; i++) pre = fmaf(w[i], qs[s][i], pre);
        const int b = s0 + s;
        const int off = b * HID + j;
        split_h(sp_f(pre), g_h0h[off], g_h0l[off]);
        const float sg = sg_f(pre);
#pragma unroll
        for (int t = 0; t < 7; t++)      // D0[b][t][j] = sig0*W0[j][t]
            g_D0h[(size_t)(b * 7 + t) * HID + j] = __float2half_rn(sg * w[t]);
    }
}

// ---------------- VALUE GEMM (3-term fp16): C[M,256] = A @ W^T ------------------
#define SMS 40
#define ASZB 10240            // bytes per array (128*40*2)
#define STGB 40960            // bytes per stage
#define SMEM_TOT (2 * STGB)   // 80 KB dynamic

template <int MODE>       // 0: layer1  2: layer2
__global__ __launch_bounds__(256, 2) void mma_gemm(const float* __restrict__ bias)
{
    extern __shared__ __align__(16) fp16 smdyn[];
    const uint32_t smb = smem_u32(smdyn);

    const int tid  = threadIdx.x;
    const int warp = tid >> 5, lane = tid & 31;
    const int wm = (warp >> 1) * 32;
    const int wn = (warp & 1) * 64;
    const int g  = lane >> 2, t4 = lane & 3;

    const int m_base = blockIdx.y * 128;
    const int n_base = blockIdx.x * 128;

    const fp16 *Ah, *Al, *Bh, *Bl;
    if (MODE == 0) { Ah = g_h0h; Al = g_h0l; Bh = g_W1h; Bl = g_W1l; }
    else           { Ah = g_h1h; Al = g_h1l; Bh = g_W2h; Bl = g_W2l; }

    const int prow = tid >> 1;
    const int pc   = (tid & 1) * 16;
    const uint32_t pdst = (uint32_t)(prow * SMS + pc) * 2;
    const size_t   pga  = (size_t)(m_base + prow) * HID + pc;
    const size_t   pgb  = (size_t)(n_base + prow) * HID + pc;

    const uint32_t a_off = (uint32_t)(((wm + (lane & 15)) * SMS) + ((lane >> 4) << 3)) * 2;
    const uint32_t b_off = (uint32_t)(((wn + ((lane >> 4) << 3) + (lane & 7)) * SMS)
                                      + (((lane >> 3) & 1) << 3)) * 2;

    float acc[2][8][4];
#pragma unroll
    for (int a = 0; a < 2; a++)
#pragma unroll
        for (int b = 0; b < 8; b++)
#pragma unroll
            for (int c = 0; c < 4; c++) acc[a][b][c] = 0.0f;

#define PREFETCH(STAGE, KT)                                                     \
    {                                                                           \
        const uint32_t sb = smb + (STAGE) * STGB + pdst;                        \
        cpa16(sb,                 Ah + pga + (KT));                             \
        cpa16(sb + 16,            Ah + pga + (KT) + 8);                         \
        cpa16(sb + ASZB,          Al + pga + (KT));                             \
        cpa16(sb + ASZB + 16,     Al + pga + (KT) + 8);                         \
        cpa16(sb + 2 * ASZB,      Bh + pgb + (KT));                             \
        cpa16(sb + 2 * ASZB + 16, Bh + pgb + (KT) + 8);                         \
        cpa16(sb + 3 * ASZB,      Bl + pgb + (KT));                             \
        cpa16(sb + 3 * ASZB + 16, Bl + pgb + (KT) + 8);                         \
        asm volatile("cp.async.commit_group;");                                 \
    }

    PREFETCH(0, 0)

#pragma unroll
    for (int it = 0; it < 8; it++) {
        if (it < 7) {
            PREFETCH((it + 1) & 1, (it + 1) * 32)
            asm volatile("cp.async.wait_group 1;");
        } else {
            asm volatile("cp.async.wait_group 0;");
        }
        __syncthreads();

        const uint32_t sbase = smb + (it & 1) * STGB;
#pragma unroll
        for (int ks = 0; ks < 2; ks++) {
            const uint32_t kso = ks * 32;
            uint32_t ah[2][4], al[2][4];
            ldsm4(ah[0], sbase + a_off + kso);
            ldsm4(ah[1], sbase + a_off + kso + 16 * SMS * 2);
            ldsm4(al[0], sbase + ASZB + a_off + kso);
            ldsm4(al[1], sbase + ASZB + a_off + kso + 16 * SMS * 2);
#pragma unroll
            for (int njp = 0; njp < 4; njp++) {
                uint32_t bh[4], bl[4];
                ldsm4(bh, sbase + 2 * ASZB + b_off + njp * (16 * SMS * 2) + kso);
                ldsm4(bl, sbase + 3 * ASZB + b_off + njp * (16 * SMS * 2) + kso);
#pragma unroll
                for (int mi = 0; mi < 2; mi++) {
#pragma unroll
                    for (int s = 0; s < 2; s++) {
                        float* C = acc[mi][njp * 2 + s];
                        mma16816(C, ah[mi], bh[2 * s], bh[2 * s + 1]);
                        mma16816(C, al[mi], bh[2 * s], bh[2 * s + 1]);
                        mma16816(C, ah[mi], bl[2 * s], bl[2 * s + 1]);
                    }
                }
            }
        }
        __syncthreads();
    }
#undef PREFETCH

#pragma unroll
    for (int mi = 0; mi < 2; mi++) {
#pragma unroll
        for (int half = 0; half < 2; half++) {
            const int m = m_base + wm + mi * 16 + g + half * 8;
#pragma unroll
            for (int nj = 0; nj < 8; nj++) {
                const int col = n_base + wn + nj * 8 + t4 * 2;
#pragma unroll
                for (int e = 0; e < 2; e++) {
                    const float v = acc[mi][nj][half * 2 + e];
                    const int cc = col + e;
                    const float pre = v + bias[cc];
                    const size_t o = (size_t)m * HID + cc;
                    if (MODE == 0) {
                        split_h(sp_f(pre), g_h1h[o], g_h1l[o]);
                        g_sig1[o] = sg_f(pre);
                    } else {
                        split_h(sp_f(pre), g_X2h[o], g_X2l[o]);
                        g_sig2[o] = sg_f(pre);
                    }
                }
            }
        }
    }
}

// ---------------- TANGENT GEMM (1-term fp16): C[M,256] = D @ W^T ---------------
template <int MODE>       // 1: D0->D1 (scale sig1)  3: D1->T2 (scale sig2)
__global__ __launch_bounds__(256, 2) void tan_gemm()
{
    __shared__ __align__(16) fp16 sm[2][2][128 * SMS];   // [stage][A/B]

    const int tid  = threadIdx.x;
    const int warp = tid >> 5, lane = tid & 31;
    const int wm = (warp >> 1) * 32;
    const int wn = (warp & 1) * 64;
    const int g  = lane >> 2, t4 = lane & 3;

    const int m_base = blockIdx.y * 128;
    const int n_base = blockIdx.x * 128;

    const fp16* Dh = (MODE == 1) ? g_D0h : g_D1h;
    const fp16* Wh = (MODE == 1) ? g_W1h : g_W2h;

    const int prow = tid >> 1;
    const int pc   = (tid & 1) * 16;
    const uint32_t pdst = (uint32_t)(prow * SMS + pc) * 2;
    const size_t   pga  = (size_t)(m_base + prow) * HID + pc;
    const size_t   pgb  = (size_t)(n_base + prow) * HID + pc;

    const uint32_t a_off = (uint32_t)(((wm + (lane & 15)) * SMS) + ((lane >> 4) << 3)) * 2;
    const uint32_t b_off = (uint32_t)(((wn + ((lane >> 4) << 3) + (lane & 7)) * SMS)
                                      + (((lane >> 3) & 1) << 3)) * 2;

    float acc[2][8][4];
#pragma unroll
    for (int a = 0; a < 2; a++)
#pragma unroll
        for (int b = 0; b < 8; b++)
#pragma unroll
            for (int c = 0; c < 4; c++) acc[a][b][c] = 0.0f;

#define TPREF(STAGE, KT)                                                        \
    {                                                                           \
        const uint32_t sa = smem_u32(&sm[STAGE][0][0]) + pdst;                  \
        const uint32_t sb = smem_u32(&sm[STAGE][1][0]) + pdst;                  \
        cpa16(sa,      Dh + pga + (KT));                                        \
        cpa16(sa + 16, Dh + pga + (KT) + 8);                                    \
        cpa16(sb,      Wh + pgb + (KT));                                        \
        cpa16(sb + 16, Wh + pgb + (KT) + 8);                                    \
        asm volatile("cp.async.commit_group;");                                 \
    }

    TPREF(0, 0)

#pragma unroll
    for (int it = 0; it < 8; it++) {
        if (it < 7) {
            TPREF((it + 1) & 1, (it + 1) * 32)
            asm volatile("cp.async.wait_group 1;");
        } else {
            asm volatile("cp.async.wait_group 0;");
        }
        __syncthreads();

        const uint32_t sA = smem_u32(&sm[it & 1][0][0]);
        const uint32_t sB = smem_u32(&sm[it & 1][1][0]);
#pragma unroll
        for (int ks = 0; ks < 2; ks++) {
            const uint32_t kso = ks * 32;
            uint32_t ah[2][4];
            ldsm4(ah[0], sA + a_off + kso);
            ldsm4(ah[1], sA + a_off + kso + 16 * SMS * 2);
#pragma unroll
            for (int njp = 0; njp < 4; njp++) {
                uint32_t bh[4];
                ldsm4(bh, sB + b_off + njp * (16 * SMS * 2) + kso);
#pragma unroll
                for (int mi = 0; mi < 2; mi++) {
#pragma unroll
                    for (int s = 0; s < 2; s++)
                        mma16816(acc[mi][njp * 2 + s], ah[mi],
                                 bh[2 * s], bh[2 * s + 1]);
                }
            }
        }
        __syncthreads();
    }
#undef TPREF

#pragma unroll
    for (int mi = 0; mi < 2; mi++) {
#pragma unroll
        for (int half = 0; half < 2; half++) {
            const int m = m_base + wm + mi * 16 + g + half * 8;
            const int mb = m / 7;
#pragma unroll
            for (int nj = 0; nj < 8; nj++) {
                const int col = n_base + wn + nj * 8 + t4 * 2;
#pragma unroll
                for (int e = 0; e < 2; e++) {
                    const float v = acc[mi][nj][half * 2 + e];
                    const int cc = col + e;
                    if (MODE == 1) {
                        const float d = v * g_sig1[(size_t)mb * HID + cc];
                        g_D1h[(size_t)m * HID + cc] = __float2half_rn(d);
                    } else {
                        const float d = v * g_sig2[(size_t)mb * HID + cc];
                        g_T2[(size_t)m * HID + cc] = __float2half_rn(d);
                    }
                }
            }
        }
    }
}

// ---------------- value heads (3-term): Yv[B,35] = X2 @ WH^T -------------------
#define HA 10240u              // A array bytes (128*40*2)
#define HB 5120u               // B array bytes (64*40*2)
#define HSTG (2 * HA + 2 * HB) // 30720
#define HSM (2 * HSTG)         // 61440 dynamic

__global__ __launch_bounds__(256, 2) void vheads_mma()
{
    extern __shared__ __align__(16) fp16 smh[];
    const uint32_t smb = smem_u32(smh);

    const int tid  = threadIdx.x;
    const int warp = tid >> 5, lane = tid & 31;
    const int wm = (warp >> 1) * 32;
    const int wn = (warp & 1) * 32;
    const int g  = lane >> 2, t4 = lane & 3;
    const size_t m_base = (size_t)blockIdx.x * 128;

    const uint32_t a_off = (uint32_t)(((wm + (lane & 15)) * SMS) + ((lane >> 4) << 3)) * 2;
    const uint32_t b_off = (uint32_t)(((wn + ((lane >> 4) << 3) + (lane & 7)) * SMS)
                                      + (((lane >> 3) & 1) << 3)) * 2;

    float acc[2][4][4];
#pragma unroll
    for (int a = 0; a < 2; a++)
#pragma unroll
        for (int b = 0; b < 4; b++)
#pragma unroll
            for (int c = 0; c < 4; c++) acc[a][b][c] = 0.0f;

#define HPREF(STAGE, KT)                                                        \
    {                                                                           \
        const uint32_t sb = smb + (STAGE) * HSTG;                               \
        _Pragma("unroll")                                                       \
        for (int kk = 0; kk < 2; kk++) {                                        \
            const int u = tid + kk * 256;                                       \
            const int r = u >> 2, qq = u & 3;                                   \
            const uint32_t d = sb + (uint32_t)(r * 80 + qq * 16);               \
            const size_t so = (m_base + r) * HID + (KT) + qq * 8;               \
            cpa16(d,      g_X2h + so);                                          \
            cpa16(d + HA, g_X2l + so);                                          \
        }                                                                       \
        {                                                                       \
            const int r = tid >> 2, qq = tid & 3;                               \
            const uint32_t d = sb + 2 * HA + (uint32_t)(r * 80 + qq * 16);      \
            const size_t so = (size_t)r * HID + (KT) + qq * 8;                  \
            cpa16(d,      g_WHh + so);                                          \
            cpa16(d + HB, g_WHl + so);                                          \
        }                                                                       \
        asm volatile("cp.async.commit_group;");                                 \
    }

    HPREF(0, 0)

#pragma unroll
    for (int it = 0; it < 8; it++) {
        if (it < 7) {
            HPREF((it + 1) & 1, (it + 1) * 32)
            asm volatile("cp.async.wait_group 1;");
        } else {
            asm volatile("cp.async.wait_group 0;");
        }
        __syncthreads();

        const uint32_t sb = smb + (it & 1) * HSTG;
#pragma unroll
        for (int ks = 0; ks < 2; ks++) {
            const uint32_t kso = ks * 32;
            uint32_t ah[2][4], al[2][4];
            ldsm4(ah[0], sb + a_off + kso);
            ldsm4(ah[1], sb + a_off + kso + 16 * SMS * 2);
            ldsm4(al[0], sb + HA + a_off + kso);
            ldsm4(al[1], sb + HA + a_off + kso + 16 * SMS * 2);
#pragma unroll
            for (int njp = 0; njp < 2; njp++) {
                uint32_t bh[4], bl[4];
                ldsm4(bh, sb + 2 * HA + b_off + njp * (16 * SMS * 2) + kso);
                ldsm4(bl, sb + 2 * HA + HB + b_off + njp * (16 * SMS * 2) + kso);
#pragma unroll
                for (int mi = 0; mi < 2; mi++) {
#pragma unroll
                    for (int s = 0; s < 2; s++) {
                        float* C = acc[mi][njp * 2 + s];
                        mma16816(C, ah[mi], bh[2 * s], bh[2 * s + 1]);
                        mma16816(C, al[mi], bh[2 * s], bh[2 * s + 1]);
                        mma16816(C, ah[mi], bl[2 * s], bl[2 * s + 1]);
                    }
                }
            }
        }
        __syncthreads();
    }
#undef HPREF

#pragma unroll
    for (int mi = 0; mi < 2; mi++) {
#pragma unroll
        for (int half = 0; half < 2; half++) {
            const size_t m = m_base + wm + mi * 16 + g + half * 8;   // sample
#pragma unroll
            for (int nj = 0; nj < 4; nj++) {
                const int col = wn + nj * 8 + t4 * 2;
#pragma unroll
                for (int e = 0; e < 2; e++) {
                    const int r = col + e;
                    if (r < NHEAD)
                        g_Yh[m * (8 * NHEAD) + r] =
                            acc[mi][nj][half * 2 + e] + g_bH[r];
                }
            }
        }
    }
}

// ---------------- tangent heads (1-term): Yt[B*7,35] = T2 @ WHh^T --------------
__global__ __launch_bounds__(256, 2) void theads_mma()
{
    __shared__ __align__(16) fp16 smt[2][(2 * HA + 2 * HB) / 2 / 2];  // reuse sizing: A 10240B + B 5120B per stage
    const uint32_t smb = smem_u32(&smt[0][0]);
    const uint32_t TSTG = HA + HB;      // 15360 bytes per stage

    const int tid  = threadIdx.x;
    const int warp = tid >> 5, lane = tid & 31;
    const int wm = (warp >> 1) * 32;
    const int wn = (warp & 1) * 32;
    const int g  = lane >> 2, t4 = lane & 3;
    const size_t m_base = (size_t)blockIdx.x * 128;

    const uint32_t a_off = (uint32_t)(((wm + (lane & 15)) * SMS) + ((lane >> 4) << 3)) * 2;
    const uint32_t b_off = (uint32_t)(((wn + ((lane >> 4) << 3) + (lane & 7)) * SMS)
                                      + (((lane >> 3) & 1) << 3)) * 2;

    float acc[2][4][4];
#pragma unroll
    for (int a = 0; a < 2; a++)
#pragma unroll
        for (int b = 0; b < 4; b++)
#pragma unroll
            for (int c = 0; c < 4; c++) acc[a][b][c] = 0.0f;

#define TPREF2(STAGE, KT)                                                       \
    {                                                                           \
        const uint32_t sb = smb + (STAGE) * TSTG;                               \
        _Pragma("unroll")                                                       \
        for (int kk = 0; kk < 2; kk++) {                                        \
            const int u = tid + kk * 256;                                       \
            const int r = u >> 2, qq = u & 3;                                   \
            cpa16(sb + (uint32_t)(r * 80 + qq * 16),                            \
                  g_T2 + (m_base + r) * HID + (KT) + qq * 8);                   \
        }                                                                       \
        {                                                                       \
            const int r = tid >> 2, qq = tid & 3;                               \
            cpa16(sb + HA + (uint32_t)(r * 80 + qq * 16),                       \
                  g_WHh + (size_t)r * HID + (KT) + qq * 8);                     \
        }                                                                       \
        asm volatile("cp.async.commit_group;");                                 \
    }

    TPREF2(0, 0)

#pragma unroll
    for (int it = 0; it < 8; it++) {
        if (it < 7) {
            TPREF2((it + 1) & 1, (it + 1) * 32)
            asm volatile("cp.async.wait_group 1;");
        } else {
            asm volatile("cp.async.wait_group 0;");
        }
        __syncthreads();

        const uint32_t sb = smb + (it & 1) * TSTG;
#pragma unroll
        for (int ks = 0; ks < 2; ks++) {
            const uint32_t kso = ks * 32;
            uint32_t ah[2][4];
            ldsm4(ah[0], sb + a_off + kso);
            ldsm4(ah[1], sb + a_off + kso + 16 * SMS * 2);
#pragma unroll
            for (int njp = 0; njp < 2; njp++) {
                uint32_t bh[4];
                ldsm4(bh, sb + HA + b_off + njp * (16 * SMS * 2) + kso);
#pragma unroll
                for (int mi = 0; mi < 2; mi++) {
#pragma unroll
                    for (int s = 0; s < 2; s++)
                        mma16816(acc[mi][njp * 2 + s], ah[mi],
                                 bh[2 * s], bh[2 * s + 1]);
                }
            }
        }
        __syncthreads();
    }
#undef TPREF2

#pragma unroll
    for (int mi = 0; mi < 2; mi++) {
#pragma unroll
        for (int half = 0; half < 2; half++) {
            const size_t m = m_base + wm + mi * 16 + g + half * 8;   // b*7+t
            const size_t b = m / 7;
            const int    t = (int)(m - b * 7);
#pragma unroll
            for (int nj = 0; nj < 4; nj++) {
                const int col = wn + nj * 8 + t4 * 2;
#pragma unroll
                for (int e = 0; e < 2; e++) {
                    const int r = col + e;
                    if (r < NHEAD)
                        g_Yh[b * (8 * NHEAD) + (1 + t) * NHEAD + r] =
                            acc[mi][nj][half * 2 + e];
                }
            }
        }
    }
}

// ---------------- K8: per-sample dynamics (flat triangular) --------------------
#define POS(i, j) ((i) * ((i) + 1) / 2 + (j))

__global__ __launch_bounds__(128) void k_dyn(const float* __restrict__ qd_g,
                                             const float* __restrict__ qdd_g,
                                             const float* __restrict__ fd,
                                             const float* __restrict__ fc,
                                             const float* __restrict__ fs,
                                             const float* __restrict__ fv,
                                             float* __restrict__ out)
{
    const int b = blockIdx.x * 128 + threadIdx.x;
    if (b >= BATCH) return;
    const int R[21]  = {1,2,2,3,3,3,4,4,4,4,5,5,5,5,5,6,6,6,6,6,6};
    const int Cc[21] = {0,0,1,0,1,2,0,1,2,3,0,1,2,3,4,0,1,2,3,4,5};

    const float* Y = g_Yh + (size_t)b * 8 * NHEAD;
    float qd[7], qdd[7], gv[7], ldr[7], sigd[7];
#pragma unroll
    for (int i = 0; i < 7; i++) {
        qd[i]  = qd_g [b * 7 + i];
        qdd[i] = qdd_g[b * 7 + i];
        gv[i]  = Y[i];
        ldr[i] = Y[7 + i];
    }

    float Lf[28];
#pragma unroll
    for (int i = 0; i < 7; i++) {
        Lf[POS(i, i)] = sp_f(ldr[i]) + 1e-3f;
        sigd[i] = sg_f(ldr[i]);
    }
#pragma unroll
    for (int p = 0; p < 21; p++) Lf[POS(R[p], Cc[p])] = Y[14 + p];

    float a[7];
#pragma unroll
    for (int j = 0; j < 7; j++) {
        float s = 0.0f;
#pragma unroll
        for (int i = 0; i < 7; i++) if (i >= j) s = fmaf(Lf[POS(i, j)], qd[i], s);
        a[j] = s;
    }

    float Ldt[28];
#pragma unroll
    for (int f = 0; f < 28; f++) Ldt[f] = 0.0f;

    float svec[7];
#pragma unroll
    for (int c = 0; c < 7; c++) {
        const float* Yc = Y + (c + 1) * NHEAD;
        float dLf[28];
#pragma unroll
        for (int i = 0; i < 7; i++) dLf[POS(i, i)] = sigd[i] * Yc[7 + i];
#pragma unroll
        for (int p = 0; p < 21; p++) dLf[POS(R[p], Cc[p])] = Yc[14 + p];
#pragma unroll
        for (int f = 0; f < 28; f++) Ldt[f] = fmaf(qd[c], dLf[f], Ldt[f]);
        float sc = 0.0f;
#pragma unroll
        for (int j = 0; j < 7; j++) {
            float v = 0.0f;
#pragma unroll
            for (int i = 0; i < 7; i++) if (i >= j) v = fmaf(qd[i], dLf[POS(i, j)], v);
            sc = fmaf(v, a[j], sc);
        }
        svec[c] = 2.0f * sc;
    }

    float b2[7];
#pragma unroll
    for (int j = 0; j < 7; j++) {
        float s = 0.0f;
#pragma unroll
        for (int i = 0; i < 7; i++) if (i >= j) s = fmaf(Ldt[POS(i, j)], qd[i], s);
        b2[j] = s;
    }

    float cor[7];
#pragma unroll
    for (int i = 0; i < 7; i++) {
        float s = 0.0f;
#pragma unroll
        for (int j = 0; j < 7; j++) if (j <= i) s = fmaf(Lf[POS(i, j)], b2[j], s);
#pragma unroll
        for (int j = 0; j < 7; j++) if (j <= i) s = fmaf(Ldt[POS(i, j)], a[j], s);
        cor[i] = s - 0.5f * svec[i];
    }

    float Hmf[28];
#pragma unroll
    for (int i = 0; i < 7; i++)
#pragma unroll
        for (int k = 0; k < 7; k++) if (k <= i) {
            float s = 0.0f;
#pragma unroll
            for (int j = 0; j < 7; j++) if (j <= k)
                s = fmaf(Lf[POS(i, j)], Lf[POS(k, j)], s);
            Hmf[POS(i, k)] = s;
        }

    float fric[7];
#pragma unroll
    for (int i = 0; i < 7; i++) {
        const float fvc = fmaxf(fv[i], 1e-3f);
        fric[i] = (fc[i] + fs[i] * expf(-qd[i] * qd[i] / fvc)) *
                      tanhf(100.0f * qd[i]) + fd[i] * qd[i];
    }

    float tau[7];
#pragma unroll
    for (int i = 0; i < 7; i++) {
        float s = 0.0f;
#pragma unroll
        for (int k = 0; k < 7; k++) {
            const float h = (k <= i) ? Hmf[POS(i, k)] : Hmf[POS(k, i)];
            s = fmaf(h, qdd[k], s);
        }
        tau[i] = s + cor[i] + gv[i] + fric[i];
    }

    const int Bc = BATCH;
#pragma unroll
    for (int i = 0; i < 7; i++) out[b * 7 + i] = tau[i];
#pragma unroll
    for (int i = 0; i < 7; i++)
#pragma unroll
        for (int k = 0; k < 7; k++)
            out[7 * Bc + b * 49 + i * 7 + k] =
                (k <= i) ? Hmf[POS(i, k)] : Hmf[POS(k, i)];
#pragma unroll
    for (int i = 0; i < 7; i++) out[56 * Bc + b * 7 + i] = cor[i];
#pragma unroll
    for (int i = 0; i < 7; i++) out[63 * Bc + b * 7 + i] = gv[i];
#pragma unroll
    for (int i = 0; i < 7; i++) out[70 * Bc + b * 7 + i] = fric[i];
#pragma unroll
    for (int i = 0; i < 7; i++) out[77 * Bc + b * 7 + i] = ldr[i];
}

// ---------------- launch --------------------------------------------------------
extern "C" void kernel_launch(void* const* d_in, const int* in_sizes, int n_in,
                              void* d_out, int out_size)
{
    (void)in_sizes; (void)n_in; (void)out_size;
    const float* q   = (const float*)d_in[0];
    const float* qd  = (const float*)d_in[1];
    const float* qdd = (const float*)d_in[2];
    const float* W0  = (const float*)d_in[3];
    const float* b0  = (const float*)d_in[4];
    const float* W1  = (const float*)d_in[5];
    const float* b1  = (const float*)d_in[6];
    const float* W2  = (const float*)d_in[7];
    const float* b2  = (const float*)d_in[8];
    const float* Wg  = (const float*)d_in[9];
    const float* bg  = (const float*)d_in[10];
    const float* Wld = (const float*)d_in[11];
    const float* bld = (const float*)d_in[12];
    const float* Wlt = (const float*)d_in[13];
    const float* blt = (const float*)d_in[14];
    const float* fd  = (const float*)d_in[15];
    const float* fc  = (const float*)d_in[16];
    const float* fs  = (const float*)d_in[17];
    const float* fv  = (const float*)d_in[18];
    float* out = (float*)d_out;

    cudaFuncSetAttribute(mma_gemm<0>, cudaFuncAttributeMaxDynamicSharedMemorySize, SMEM_TOT);
    cudaFuncSetAttribute(mma_gemm<2>, cudaFuncAttributeMaxDynamicSharedMemorySize, SMEM_TOT);
    cudaFuncSetAttribute(vheads_mma, cudaFuncAttributeMaxDynamicSharedMemorySize, HSM);

    k_wsplit<<<HID * HID / 256, 256>>>(W1, W2);
    k_whead<<<64, 256>>>(Wg, bg, Wld, bld, Wlt, blt);
    k_layer0<<<BATCH / 32, 256>>>(q, W0, b0);                        // h0 + D0
    mma_gemm<0><<<dim3(2, BATCH / 128), 256, SMEM_TOT>>>(b1);        // h1, sig1
    tan_gemm<1><<<dim3(2, (BATCH * 7) / 128), 256>>>();              // D1
    mma_gemm<2><<<dim3(2, BATCH / 128), 256, SMEM_TOT>>>(b2);        // X2, sig2
    tan_gemm<3><<<dim3(2, (BATCH * 7) / 128), 256>>>();              // T2
    vheads_mma<<<BATCH / 128, 256, HSM>>>();                         // value Yh
    theads_mma<<<(BATCH * 7) / 128, 256>>>();                        // tangent Yh
    k_dyn<<<(BATCH + 127) / 128, 128>>>(qd, qdd, fd, fc, fs, fv, out);
}

// round 9
// speedup vs baseline: 3.7571x; 1.0740x over previous
#include <cuda_runtime.h>
#include <cuda_fp16.h>
#include <math.h>
#include <stdint.h>

#define BATCH 32768
#define HID 256
#define NDOF 7
#define NTRIL 21
#define NHEAD 35   // 7 g + 7 Ld + 21 Lt

typedef __half fp16;

// ---------------- scratch (device globals; no allocation allowed) -------------
__device__ fp16  g_h0h [BATCH * HID];
__device__ fp16  g_h0l [BATCH * HID];
__device__ fp16  g_h1h [BATCH * HID];
__device__ fp16  g_h1l [BATCH * HID];
__device__ fp16  g_D0h [(size_t)BATCH * 7 * HID];   // tangent: hi only (1-term)
__device__ fp16  g_D1h [(size_t)BATCH * 7 * HID];
__device__ fp16  g_T2  [(size_t)BATCH * 7 * HID];   // layer2 tangents (hi only)
__device__ float g_sig1[BATCH * HID];
__device__ float g_sig2[BATCH * HID];
__device__ fp16  g_X2h [BATCH * HID];               // value h2 (hi/lo)
__device__ fp16  g_X2l [BATCH * HID];
__device__ float g_Yh  [(size_t)BATCH * 8 * NHEAD];
__device__ fp16  g_W1h[HID * HID];
__device__ fp16  g_W1l[HID * HID];
__device__ fp16  g_W2h[HID * HID];
__device__ fp16  g_W2l[HID * HID];
__device__ fp16  g_WHh[64 * HID];                   // padded head weights (35->64)
__device__ fp16  g_WHl[64 * HID];
__device__ float g_bH [64];

// ---------------- helpers ------------------------------------------------------
__device__ __forceinline__ float sp_f(float x) {
    return fmaxf(x, 0.0f) + log1pf(expf(-fabsf(x)));
}
__device__ __forceinline__ float sg_f(float x) {
    return 1.0f / (1.0f + expf(-x));
}
__device__ __forceinline__ void split_h(float x, fp16& h, fp16& l) {
    h = __float2half_rn(x);
    l = __float2half_rn(x - __half2float(h));
}
__device__ __forceinline__ void mma16816(float c[4], const uint32_t a[4],
                                         uint32_t b0, uint32_t b1) {
    asm volatile(
        "mma.sync.aligned.m16n8k16.row.col.f32.f16.f16.f32 "
        "{%0,%1,%2,%3}, {%4,%5,%6,%7}, {%8,%9}, {%0,%1,%2,%3};"
        : "+f"(c[0]), "+f"(c[1]), "+f"(c[2]), "+f"(c[3])
        : "r"(a[0]), "r"(a[1]), "r"(a[2]), "r"(a[3]), "r"(b0), "r"(b1));
}
__device__ __forceinline__ void ldsm4(uint32_t r[4], uint32_t addr) {
    asm volatile("ldmatrix.sync.aligned.m8n8.x4.shared.b16 {%0,%1,%2,%3}, [%4];"
                 : "=r"(r[0]), "=r"(r[1]), "=r"(r[2]), "=r"(r[3]) : "r"(addr));
}
__device__ __forceinline__ uint32_t smem_u32(const void* p) {
    uint32_t a;
    asm("{ .reg .u64 t; cvta.to.shared.u64 t, %1; cvt.u32.u64 %0, t; }"
        : "=r"(a) : "l"(p));
    return a;
}
__device__ __forceinline__ void cpa16(uint32_t s, const void* g) {
    asm volatile("cp.async.cg.shared.global [%0], [%1], 16;" :: "r"(s), "l"(g));
}

// ---------------- K0a: W1/W2 hi/lo split ---------------------------------------
__global__ __launch_bounds__(256) void k_wsplit(const float* __restrict__ W1,
                                                const float* __restrict__ W2)
{
    const int i = blockIdx.x * 256 + threadIdx.x;
    split_h(W1[i], g_W1h[i], g_W1l[i]);
    split_h(W2[i], g_W2h[i], g_W2l[i]);
}

// ---------------- K0b: padded head weights + bias ------------------------------
__global__ __launch_bounds__(256) void k_whead(const float* __restrict__ Wg,
                                               const float* __restrict__ bg,
                                               const float* __restrict__ Wld,
                                               const float* __restrict__ bld,
                                               const float* __restrict__ Wlt,
                                               const float* __restrict__ blt)
{
    const int i = blockIdx.x * 256 + threadIdx.x;   // 0..16383
    const int r = i >> 8, k = i & 255;
    float v = 0.0f;
    if      (r < 7)  v = Wg [r * HID + k];
    else if (r < 14) v = Wld[(r - 7) * HID + k];
    else if (r < 35) v = Wlt[(r - 14) * HID + k];
    split_h(v, g_WHh[i], g_WHl[i]);
    if (i < 64) {
        float b = 0.0f;
        if      (i < 7)  b = bg [i];
        else if (i < 14) b = bld[i - 7];
        else if (i < 35) b = blt[i - 14];
        g_bH[i] = b;
    }
}

// ---------------- K1: layer0 values + tangent seeds (fused) --------------------
__global__ __launch_bounds__(256) void k_layer0(const float* __restrict__ q,
                                                const float* __restrict__ W0,
                                                const float* __restrict__ b0)
{
    __shared__ float qs[32][8];
    const int j  = threadIdx.x;
    const int s0 = blockIdx.x * 32;
    for (int idx = threadIdx.x; idx < 32 * 7; idx += 256)
        qs[idx / 7][idx % 7] = q[(s0 + idx / 7) * 7 + idx % 7];
    float w[7];
#pragma unroll
    for (int i = 0; i < 7; i++) w[i] = W0[j * 7 + i];
    const float bb = b0[j];
    __syncthreads();
    for (int s = 0; s < 32; s++) {
        float pre = bb;
#pragma unroll
        for (int i = 0; i < 7; i++) pre = fmaf(w[i], qs[s][i], pre);
        const int b = s0 + s;
        const int off = b * HID + j;
        split_h(sp_f(pre), g_h0h[off], g_h0l[off]);
        const float sg = sg_f(pre);
#pragma unroll
        for (int t = 0; t < 7; t++)
            g_D0h[(size_t)(b * 7 + t) * HID + j] = __float2half_rn(sg * w[t]);
    }
}

// ---------------- VALUE GEMM (3-term fp16): C[M,256] = A @ W^T ------------------
#define SMS 40
#define ASZB 10240            // bytes per array (128*40*2)
#define STGB 40960            // bytes per stage
#define SMEM_TOT (2 * STGB)   // 80 KB dynamic

template <int MODE>       // 0: layer1  2: layer2
__global__ __launch_bounds__(256, 2) void mma_gemm(const float* __restrict__ bias)
{
    extern __shared__ __align__(16) fp16 smdyn[];
    const uint32_t smb = smem_u32(smdyn);

    const int tid  = threadIdx.x;
    const int warp = tid >> 5, lane = tid & 31;
    const int wm = (warp >> 1) * 32;
    const int wn = (warp & 1) * 64;
    const int g  = lane >> 2, t4 = lane & 3;

    const int m_base = blockIdx.y * 128;
    const int n_base = blockIdx.x * 128;

    const fp16 *Ah, *Al, *Bh, *Bl;
    if (MODE == 0) { Ah = g_h0h; Al = g_h0l; Bh = g_W1h; Bl = g_W1l; }
    else           { Ah = g_h1h; Al = g_h1l; Bh = g_W2h; Bl = g_W2l; }

    const int prow = tid >> 1;
    const int pc   = (tid & 1) * 16;
    const uint32_t pdst = (uint32_t)(prow * SMS + pc) * 2;
    const size_t   pga  = (size_t)(m_base + prow) * HID + pc;
    const size_t   pgb  = (size_t)(n_base + prow) * HID + pc;

    const uint32_t a_off = (uint32_t)(((wm + (lane & 15)) * SMS) + ((lane >> 4) << 3)) * 2;
    const uint32_t b_off = (uint32_t)(((wn + ((lane >> 4) << 3) + (lane & 7)) * SMS)
                                      + (((lane >> 3) & 1) << 3)) * 2;

    float acc[2][8][4];
#pragma unroll
    for (int a = 0; a < 2; a++)
#pragma unroll
        for (int b = 0; b < 8; b++)
#pragma unroll
            for (int c = 0; c < 4; c++) acc[a][b][c] = 0.0f;

#define PREFETCH(STAGE, KT)                                                     \
    {                                                                           \
        const uint32_t sb = smb + (STAGE) * STGB + pdst;                        \
        cpa16(sb,                 Ah + pga + (KT));                             \
        cpa16(sb + 16,            Ah + pga + (KT) + 8);                         \
        cpa16(sb + ASZB,          Al + pga + (KT));                             \
        cpa16(sb + ASZB + 16,     Al + pga + (KT) + 8);                         \
        cpa16(sb + 2 * ASZB,      Bh + pgb + (KT));                             \
        cpa16(sb + 2 * ASZB + 16, Bh + pgb + (KT) + 8);                         \
        cpa16(sb + 3 * ASZB,      Bl + pgb + (KT));                             \
        cpa16(sb + 3 * ASZB + 16, Bl + pgb + (KT) + 8);                         \
        asm volatile("cp.async.commit_group;");                                 \
    }

    PREFETCH(0, 0)

#pragma unroll
    for (int it = 0; it < 8; it++) {
        if (it < 7) {
            PREFETCH((it + 1) & 1, (it + 1) * 32)
            asm volatile("cp.async.wait_group 1;");
        } else {
            asm volatile("cp.async.wait_group 0;");
        }
        __syncthreads();

        const uint32_t sbase = smb + (it & 1) * STGB;
#pragma unroll
        for (int ks = 0; ks < 2; ks++) {
            const uint32_t kso = ks * 32;
            uint32_t ah[2][4], al[2][4];
            ldsm4(ah[0], sbase + a_off + kso);
            ldsm4(ah[1], sbase + a_off + kso + 16 * SMS * 2);
            ldsm4(al[0], sbase + ASZB + a_off + kso);
            ldsm4(al[1], sbase + ASZB + a_off + kso + 16 * SMS * 2);
#pragma unroll
            for (int njp = 0; njp < 4; njp++) {
                uint32_t bh[4], bl[4];
                ldsm4(bh, sbase + 2 * ASZB + b_off + njp * (16 * SMS * 2) + kso);
                ldsm4(bl, sbase + 3 * ASZB + b_off + njp * (16 * SMS * 2) + kso);
#pragma unroll
                for (int mi = 0; mi < 2; mi++) {
#pragma unroll
                    for (int s = 0; s < 2; s++) {
                        float* C = acc[mi][njp * 2 + s];
                        mma16816(C, ah[mi], bh[2 * s], bh[2 * s + 1]);
                        mma16816(C, al[mi], bh[2 * s], bh[2 * s + 1]);
                        mma16816(C, ah[mi], bl[2 * s], bl[2 * s + 1]);
                    }
                }
            }
        }
        __syncthreads();
    }
#undef PREFETCH

#pragma unroll
    for (int mi = 0; mi < 2; mi++) {
#pragma unroll
        for (int half = 0; half < 2; half++) {
            const int m = m_base + wm + mi * 16 + g + half * 8;
#pragma unroll
            for (int nj = 0; nj < 8; nj++) {
                const int col = n_base + wn + nj * 8 + t4 * 2;
#pragma unroll
                for (int e = 0; e < 2; e++) {
                    const float v = acc[mi][nj][half * 2 + e];
                    const int cc = col + e;
                    const float pre = v + bias[cc];
                    const size_t o = (size_t)m * HID + cc;
                    if (MODE == 0) {
                        split_h(sp_f(pre), g_h1h[o], g_h1l[o]);
                        g_sig1[o] = sg_f(pre);
                    } else {
                        split_h(sp_f(pre), g_X2h[o], g_X2l[o]);
                        g_sig2[o] = sg_f(pre);
                    }
                }
            }
        }
    }
}

// ---------------- tan64: 1-term fp16 GEMM, 128x64 tile, 3-stage, 3 CTA/SM ------
// MODE 1: D0 @ W1^T * sig1 -> D1
// MODE 3: D1 @ W2^T * sig2 -> T2
// MODE 5: T2 @ WHh^T -> Yh (tangent head rows)
#define TA 10240u            // A bytes per stage (128*40*2)
#define TB 5120u             // B bytes per stage (64*40*2)
#define TSTG2 (TA + TB)      // 15360

template <int MODE>
__global__ __launch_bounds__(256, 3) void tan64()
{
    __shared__ __align__(16) fp16 sm[3 * TSTG2 / 2];
    const uint32_t smb = smem_u32(sm);

    const int tid  = threadIdx.x;
    const int warp = tid >> 5, lane = tid & 31;
    const int wm = (warp >> 1) * 32;    // 4 warps along M
    const int wn = (warp & 1) * 32;     // 2 warps along N
    const int g  = lane >> 2, t4 = lane & 3;
    const size_t m_base = (size_t)blockIdx.y * 128;
    const int    n_base = blockIdx.x * 64;

    const fp16* Dp = (MODE == 1) ? g_D0h : (MODE == 3) ? g_D1h : g_T2;
    const fp16* Wp = (MODE == 1) ? g_W1h : (MODE == 3) ? g_W2h : g_WHh;

    const uint32_t a_off = (uint32_t)(((wm + (lane & 15)) * SMS) + ((lane >> 4) << 3)) * 2;
    const uint32_t b_off = (uint32_t)(((wn + ((lane >> 4) << 3) + (lane & 7)) * SMS)
                                      + (((lane >> 3) & 1) << 3)) * 2;

    float acc[2][4][4];
#pragma unroll
    for (int a = 0; a < 2; a++)
#pragma unroll
        for (int b = 0; b < 4; b++)
#pragma unroll
            for (int c = 0; c < 4; c++) acc[a][b][c] = 0.0f;

#define TP(STAGE, KT)                                                           \
    {                                                                           \
        const uint32_t sb = smb + (STAGE) * TSTG2;                              \
        {   const int u = tid;                                                  \
            cpa16(sb + (uint32_t)((u >> 2) * 80 + (u & 3) * 16),                \
                  Dp + (m_base + (u >> 2)) * HID + (KT) + (u & 3) * 8); }       \
        {   const int u = tid + 256;                                            \
            cpa16(sb + (uint32_t)((u >> 2) * 80 + (u & 3) * 16),                \
                  Dp + (m_base + (u >> 2)) * HID + (KT) + (u & 3) * 8); }       \
        {   const int u = tid;                                                  \
            cpa16(sb + TA + (uint32_t)((u >> 2) * 80 + (u & 3) * 16),           \
                  Wp + (size_t)(n_base + (u >> 2)) * HID + (KT) + (u & 3) * 8); } \
        asm volatile("cp.async.commit_group;");                                 \
    }

    TP(0, 0)
    TP(1, 32)

#pragma unroll
    for (int it = 0; it < 8; it++) {
        if (it < 7) asm volatile("cp.async.wait_group 1;");
        else        asm volatile("cp.async.wait_group 0;");
        __syncthreads();
        if (it + 2 < 8) {
            const int st = (it + 2) % 3;
            TP(st, (it + 2) * 32)
        }

        const uint32_t sb = smb + (it % 3) * TSTG2;
#pragma unroll
        for (int ks = 0; ks < 2; ks++) {
            const uint32_t kso = ks * 32;
            uint32_t ah[2][4];
            ldsm4(ah[0], sb + a_off + kso);
            ldsm4(ah[1], sb + a_off + kso + 16 * SMS * 2);
#pragma unroll
            for (int njp = 0; njp < 2; njp++) {
                uint32_t bh[4];
                ldsm4(bh, sb + TA + b_off + njp * (16 * SMS * 2) + kso);
#pragma unroll
                for (int mi = 0; mi < 2; mi++) {
#pragma unroll
                    for (int s = 0; s < 2; s++)
                        mma16816(acc[mi][njp * 2 + s], ah[mi],
                                 bh[2 * s], bh[2 * s + 1]);
                }
            }
        }
    }
#undef TP

#pragma unroll
    for (int mi = 0; mi < 2; mi++) {
#pragma unroll
        for (int half = 0; half < 2; half++) {
            const size_t m = m_base + wm + mi * 16 + g + half * 8;
            const size_t mb = m / 7;
            const int    mt = (int)(m - mb * 7);
#pragma unroll
            for (int nj = 0; nj < 4; nj++) {
                const int col = wn + nj * 8 + t4 * 2;
#pragma unroll
                for (int e = 0; e < 2; e++) {
                    const float v = acc[mi][nj][half * 2 + e];
                    if (MODE == 1) {
                        const int cc = n_base + col + e;
                        g_D1h[m * HID + cc] =
                            __float2half_rn(v * g_sig1[mb * HID + cc]);
                    } else if (MODE == 3) {
                        const int cc = n_base + col + e;
                        g_T2[m * HID + cc] =
                            __float2half_rn(v * g_sig2[mb * HID + cc]);
                    } else {
                        const int r = col + e;
                        if (r < NHEAD)
                            g_Yh[mb * (8 * NHEAD) + (1 + mt) * NHEAD + r] = v;
                    }
                }
            }
        }
    }
}

// ---------------- value heads (3-term): Yv[B,35] = X2 @ WH^T -------------------
#define HA 10240u              // A array bytes (128*40*2)
#define HB 5120u               // B array bytes (64*40*2)
#define HSTG (2 * HA + 2 * HB) // 30720
#define HSM (2 * HSTG)         // 61440 dynamic

__global__ __launch_bounds__(256, 2) void vheads_mma()
{
    extern __shared__ __align__(16) fp16 smh[];
    const uint32_t smb = smem_u32(smh);

    const int tid  = threadIdx.x;
    const int warp = tid >> 5, lane = tid & 31;
    const int wm = (warp >> 1) * 32;
    const int wn = (warp & 1) * 32;
    const int g  = lane >> 2, t4 = lane & 3;
    const size_t m_base = (size_t)blockIdx.x * 128;

    const uint32_t a_off = (uint32_t)(((wm + (lane & 15)) * SMS) + ((lane >> 4) << 3)) * 2;
    const uint32_t b_off = (uint32_t)(((wn + ((lane >> 4) << 3) + (lane & 7)) * SMS)
                                      + (((lane >> 3) & 1) << 3)) * 2;

    float acc[2][4][4];
#pragma unroll
    for (int a = 0; a < 2; a++)
#pragma unroll
        for (int b = 0; b < 4; b++)
#pragma unroll
            for (int c = 0; c < 4; c++) acc[a][b][c] = 0.0f;

#define HPREF(STAGE, KT)                                                        \
    {                                                                           \
        const uint32_t sb = smb + (STAGE) * HSTG;                               \
        _Pragma("unroll")                                                       \
        for (int kk = 0; kk < 2; kk++) {                                        \
            const int u = tid + kk * 256;                                       \
            const int r = u >> 2, qq = u & 3;                                   \
            const uint32_t d = sb + (uint32_t)(r * 80 + qq * 16);               \
            const size_t so = (m_base + r) * HID + (KT) + qq * 8;               \
            cpa16(d,      g_X2h + so);                                          \
            cpa16(d + HA, g_X2l + so);                                          \
        }                                                                       \
        {                                                                       \
            const int r = tid >> 2, qq = tid & 3;                               \
            const uint32_t d = sb + 2 * HA + (uint32_t)(r * 80 + qq * 16);      \
            const size_t so = (size_t)r * HID + (KT) + qq * 8;                  \
            cpa16(d,      g_WHh + so);                                          \
            cpa16(d + HB, g_WHl + so);                                          \
        }                                                                       \
        asm volatile("cp.async.commit_group;");                                 \
    }

    HPREF(0, 0)

#pragma unroll
    for (int it = 0; it < 8; it++) {
        if (it < 7) {
            HPREF((it + 1) & 1, (it + 1) * 32)
            asm volatile("cp.async.wait_group 1;");
        } else {
            asm volatile("cp.async.wait_group 0;");
        }
        __syncthreads();

        const uint32_t sb = smb + (it & 1) * HSTG;
#pragma unroll
        for (int ks = 0; ks < 2; ks++) {
            const uint32_t kso = ks * 32;
            uint32_t ah[2][4], al[2][4];
            ldsm4(ah[0], sb + a_off + kso);
            ldsm4(ah[1], sb + a_off + kso + 16 * SMS * 2);
            ldsm4(al[0], sb + HA + a_off + kso);
            ldsm4(al[1], sb + HA + a_off + kso + 16 * SMS * 2);
#pragma unroll
            for (int njp = 0; njp < 2; njp++) {
                uint32_t bh[4], bl[4];
                ldsm4(bh, sb + 2 * HA + b_off + njp * (16 * SMS * 2) + kso);
                ldsm4(bl, sb + 2 * HA + HB + b_off + njp * (16 * SMS * 2) + kso);
#pragma unroll
                for (int mi = 0; mi < 2; mi++) {
#pragma unroll
                    for (int s = 0; s < 2; s++) {
                        float* C = acc[mi][njp * 2 + s];
                        mma16816(C, ah[mi], bh[2 * s], bh[2 * s + 1]);
                        mma16816(C, al[mi], bh[2 * s], bh[2 * s + 1]);
                        mma16816(C, ah[mi], bl[2 * s], bl[2 * s + 1]);
                    }
                }
            }
        }
        __syncthreads();
    }
#undef HPREF

#pragma unroll
    for (int mi = 0; mi < 2; mi++) {
#pragma unroll
        for (int half = 0; half < 2; half++) {
            const size_t m = m_base + wm + mi * 16 + g + half * 8;   // sample
#pragma unroll
            for (int nj = 0; nj < 4; nj++) {
                const int col = wn + nj * 8 + t4 * 2;
#pragma unroll
                for (int e = 0; e < 2; e++) {
                    const int r = col + e;
                    if (r < NHEAD)
                        g_Yh[m * (8 * NHEAD) + r] =
                            acc[mi][nj][half * 2 + e] + g_bH[r];
                }
            }
        }
    }
}

// ---------------- K8: per-sample dynamics (flat triangular) --------------------
#define POS(i, j) ((i) * ((i) + 1) / 2 + (j))

__global__ __launch_bounds__(128) void k_dyn(const float* __restrict__ qd_g,
                                             const float* __restrict__ qdd_g,
                                             const float* __restrict__ fd,
                                             const float* __restrict__ fc,
                                             const float* __restrict__ fs,
                                             const float* __restrict__ fv,
                                             float* __restrict__ out)
{
    const int b = blockIdx.x * 128 + threadIdx.x;
    if (b >= BATCH) return;
    const int R[21]  = {1,2,2,3,3,3,4,4,4,4,5,5,5,5,5,6,6,6,6,6,6};
    const int Cc[21] = {0,0,1,0,1,2,0,1,2,3,0,1,2,3,4,0,1,2,3,4,5};

    const float* Y = g_Yh + (size_t)b * 8 * NHEAD;
    float qd[7], qdd[7], gv[7], ldr[7], sigd[7];
#pragma unroll
    for (int i = 0; i < 7; i++) {
        qd[i]  = qd_g [b * 7 + i];
        qdd[i] = qdd_g[b * 7 + i];
        gv[i]  = Y[i];
        ldr[i] = Y[7 + i];
    }

    float Lf[28];
#pragma unroll
    for (int i = 0; i < 7; i++) {
        Lf[POS(i, i)] = sp_f(ldr[i]) + 1e-3f;
        sigd[i] = sg_f(ldr[i]);
    }
#pragma unroll
    for (int p = 0; p < 21; p++) Lf[POS(R[p], Cc[p])] = Y[14 + p];

    float a[7];
#pragma unroll
    for (int j = 0; j < 7; j++) {
        float s = 0.0f;
#pragma unroll
        for (int i = 0; i < 7; i++) if (i >= j) s = fmaf(Lf[POS(i, j)], qd[i], s);
        a[j] = s;
    }

    float Ldt[28];
#pragma unroll
    for (int f = 0; f < 28; f++) Ldt[f] = 0.0f;

    float svec[7];
#pragma unroll
    for (int c = 0; c < 7; c++) {
        const float* Yc = Y + (c + 1) * NHEAD;
        float dLf[28];
#pragma unroll
        for (int i = 0; i < 7; i++) dLf[POS(i, i)] = sigd[i] * Yc[7 + i];
#pragma unroll
        for (int p = 0; p < 21; p++) dLf[POS(R[p], Cc[p])] = Yc[14 + p];
#pragma unroll
        for (int f = 0; f < 28; f++) Ldt[f] = fmaf(qd[c], dLf[f], Ldt[f]);
        float sc = 0.0f;
#pragma unroll
        for (int j = 0; j < 7; j++) {
            float v = 0.0f;
#pragma unroll
            for (int i = 0; i < 7; i++) if (i >= j) v = fmaf(qd[i], dLf[POS(i, j)], v);
            sc = fmaf(v, a[j], sc);
        }
        svec[c] = 2.0f * sc;
    }

    float b2[7];
#pragma unroll
    for (int j = 0; j < 7; j++) {
        float s = 0.0f;
#pragma unroll
        for (int i = 0; i < 7; i++) if (i >= j) s = fmaf(Ldt[POS(i, j)], qd[i], s);
        b2[j] = s;
    }

    float cor[7];
#pragma unroll
    for (int i = 0; i < 7; i++) {
        float s = 0.0f;
#pragma unroll
        for (int j = 0; j < 7; j++) if (j <= i) s = fmaf(Lf[POS(i, j)], b2[j], s);
#pragma unroll
        for (int j = 0; j < 7; j++) if (j <= i) s = fmaf(Ldt[POS(i, j)], a[j], s);
        cor[i] = s - 0.5f * svec[i];
    }

    float Hmf[28];
#pragma unroll
    for (int i = 0; i < 7; i++)
#pragma unroll
        for (int k = 0; k < 7; k++) if (k <= i) {
            float s = 0.0f;
#pragma unroll
            for (int j = 0; j < 7; j++) if (j <= k)
                s = fmaf(Lf[POS(i, j)], Lf[POS(k, j)], s);
            Hmf[POS(i, k)] = s;
        }

    float fric[7];
#pragma unroll
    for (int i = 0; i < 7; i++) {
        const float fvc = fmaxf(fv[i], 1e-3f);
        fric[i] = (fc[i] + fs[i] * expf(-qd[i] * qd[i] / fvc)) *
                      tanhf(100.0f * qd[i]) + fd[i] * qd[i];
    }

    float tau[7];
#pragma unroll
    for (int i = 0; i < 7; i++) {
        float s = 0.0f;
#pragma unroll
        for (int k = 0; k < 7; k++) {
            const float h = (k <= i) ? Hmf[POS(i, k)] : Hmf[POS(k, i)];
            s = fmaf(h, qdd[k], s);
        }
        tau[i] = s + cor[i] + gv[i] + fric[i];
    }

    const int Bc = BATCH;
#pragma unroll
    for (int i = 0; i < 7; i++) out[b * 7 + i] = tau[i];
#pragma unroll
    for (int i = 0; i < 7; i++)
#pragma unroll
        for (int k = 0; k < 7; k++)
            out[7 * Bc + b * 49 + i * 7 + k] =
                (k <= i) ? Hmf[POS(i, k)] : Hmf[POS(k, i)];
#pragma unroll
    for (int i = 0; i < 7; i++) out[56 * Bc + b * 7 + i] = cor[i];
#pragma unroll
    for (int i = 0; i < 7; i++) out[63 * Bc + b * 7 + i] = gv[i];
#pragma unroll
    for (int i = 0; i < 7; i++) out[70 * Bc + b * 7 + i] = fric[i];
#pragma unroll
    for (int i = 0; i < 7; i++) out[77 * Bc + b * 7 + i] = ldr[i];
}

// ---------------- launch --------------------------------------------------------
extern "C" void kernel_launch(void* const* d_in, const int* in_sizes, int n_in,
                              void* d_out, int out_size)
{
    (void)in_sizes; (void)n_in; (void)out_size;
    const float* q   = (const float*)d_in[0];
    const float* qd  = (const float*)d_in[1];
    const float* qdd = (const float*)d_in[2];
    const float* W0  = (const float*)d_in[3];
    const float* b0  = (const float*)d_in[4];
    const float* W1  = (const float*)d_in[5];
    const float* b1  = (const float*)d_in[6];
    const float* W2  = (const float*)d_in[7];
    const float* b2  = (const float*)d_in[8];
    const float* Wg  = (const float*)d_in[9];
    const float* bg  = (const float*)d_in[10];
    const float* Wld = (const float*)d_in[11];
    const float* bld = (const float*)d_in[12];
    const float* Wlt = (const float*)d_in[13];
    const float* blt = (const float*)d_in[14];
    const float* fd  = (const float*)d_in[15];
    const float* fc  = (const float*)d_in[16];
    const float* fs  = (const float*)d_in[17];
    const float* fv  = (const float*)d_in[18];
    float* out = (float*)d_out;

    cudaFuncSetAttribute(mma_gemm<0>, cudaFuncAttributeMaxDynamicSharedMemorySize, SMEM_TOT);
    cudaFuncSetAttribute(mma_gemm<2>, cudaFuncAttributeMaxDynamicSharedMemorySize, SMEM_TOT);
    cudaFuncSetAttribute(vheads_mma, cudaFuncAttributeMaxDynamicSharedMemorySize, HSM);

    k_wsplit<<<HID * HID / 256, 256>>>(W1, W2);
    k_whead<<<64, 256>>>(Wg, bg, Wld, bld, Wlt, blt);
    k_layer0<<<BATCH / 32, 256>>>(q, W0, b0);                        // h0 + D0
    mma_gemm<0><<<dim3(2, BATCH / 128), 256, SMEM_TOT>>>(b1);        // h1, sig1
    tan64<1><<<dim3(4, (BATCH * 7) / 128), 256>>>();                 // D1
    mma_gemm<2><<<dim3(2, BATCH / 128), 256, SMEM_TOT>>>(b2);        // X2, sig2
    tan64<3><<<dim3(4, (BATCH * 7) / 128), 256>>>();                 // T2
    vheads_mma<<<BATCH / 128, 256, HSM>>>();                         // value Yh
    tan64<5><<<dim3(1, (BATCH * 7) / 128), 256>>>();                 // tangent Yh
    k_dyn<<<(BATCH + 127) / 128, 128>>>(qd, qdd, fd, fc, fs, fv, out);
}

// round 10
// speedup vs baseline: 4.1861x; 1.1142x over previous
#include <cuda_runtime.h>
#include <cuda_fp16.h>
#include <math.h>
#include <stdint.h>

#define BATCH 32768
#define HID 256
#define NDOF 7
#define NTRIL 21
#define NHEAD 35   // 7 g + 7 Ld + 21 Lt

typedef __half fp16;

// ---------------- scratch (device globals; no allocation allowed) -------------
__device__ fp16  g_h0h [BATCH * HID];
__device__ fp16  g_h1h [BATCH * HID];
__device__ fp16  g_D0h [(size_t)BATCH * 7 * HID];
__device__ fp16  g_D1h [(size_t)BATCH * 7 * HID];
__device__ fp16  g_T2  [(size_t)BATCH * 7 * HID];
__device__ float g_sig1[BATCH * HID];
__device__ float g_sig2[BATCH * HID];
__device__ fp16  g_X2h [BATCH * HID];
__device__ float g_Yh  [(size_t)8 * NHEAD * BATCH];   // TRANSPOSED: [(vec*35+r)*B + b]
__device__ fp16  g_W1h[HID * HID];
__device__ fp16  g_W1l[HID * HID];
__device__ fp16  g_W2h[HID * HID];
__device__ fp16  g_W2l[HID * HID];
__device__ fp16  g_WHh[64 * HID];
__device__ fp16  g_WHl[64 * HID];
__device__ float g_bH [64];

// ---------------- helpers ------------------------------------------------------
__device__ __forceinline__ float sp_f(float x) {
    return fmaxf(x, 0.0f) + log1pf(expf(-fabsf(x)));
}
__device__ __forceinline__ float sg_f(float x) {
    return 1.0f / (1.0f + expf(-x));
}
__device__ __forceinline__ void split_h(float x, fp16& h, fp16& l) {
    h = __float2half_rn(x);
    l = __float2half_rn(x - __half2float(h));
}
__device__ __forceinline__ void mma16816(float c[4], const uint32_t a[4],
                                         uint32_t b0, uint32_t b1) {
    asm volatile(
        "mma.sync.aligned.m16n8k16.row.col.f32.f16.f16.f32 "
        "{%0,%1,%2,%3}, {%4,%5,%6,%7}, {%8,%9}, {%0,%1,%2,%3};"
        : "+f"(c[0]), "+f"(c[1]), "+f"(c[2]), "+f"(c[3])
        : "r"(a[0]), "r"(a[1]), "r"(a[2]), "r"(a[3]), "r"(b0), "r"(b1));
}
__device__ __forceinline__ void ldsm4(uint32_t r[4], uint32_t addr) {
    asm volatile("ldmatrix.sync.aligned.m8n8.x4.shared.b16 {%0,%1,%2,%3}, [%4];"
                 : "=r"(r[0]), "=r"(r[1]), "=r"(r[2]), "=r"(r[3]) : "r"(addr));
}
__device__ __forceinline__ uint32_t smem_u32(const void* p) {
    uint32_t a;
    asm("{ .reg .u64 t; cvta.to.shared.u64 t, %1; cvt.u32.u64 %0, t; }"
        : "=r"(a) : "l"(p));
    return a;
}
__device__ __forceinline__ void cpa16(uint32_t s, const void* g) {
    asm volatile("cp.async.cg.shared.global [%0], [%1], 16;" :: "r"(s), "l"(g));
}

#define SMS 40

// ---------------- K0a: W1/W2 hi/lo split ---------------------------------------
__global__ __launch_bounds__(256) void k_wsplit(const float* __restrict__ W1,
                                                const float* __restrict__ W2)
{
    const int i = blockIdx.x * 256 + threadIdx.x;
    split_h(W1[i], g_W1h[i], g_W1l[i]);
    split_h(W2[i], g_W2h[i], g_W2l[i]);
}

// ---------------- K0b: padded head weights + bias ------------------------------
__global__ __launch_bounds__(256) void k_whead(const float* __restrict__ Wg,
                                               const float* __restrict__ bg,
                                               const float* __restrict__ Wld,
                                               const float* __restrict__ bld,
                                               const float* __restrict__ Wlt,
                                               const float* __restrict__ blt)
{
    const int i = blockIdx.x * 256 + threadIdx.x;   // 0..16383
    const int r = i >> 8, k = i & 255;
    float v = 0.0f;
    if      (r < 7)  v = Wg [r * HID + k];
    else if (r < 14) v = Wld[(r - 7) * HID + k];
    else if (r < 35) v = Wlt[(r - 14) * HID + k];
    split_h(v, g_WHh[i], g_WHl[i]);
    if (i < 64) {
        float b = 0.0f;
        if      (i < 7)  b = bg [i];
        else if (i < 14) b = bld[i - 7];
        else if (i < 35) b = blt[i - 14];
        g_bH[i] = b;
    }
}

// ---------------- K1: layer0 values + tangent seeds (fused) --------------------
__global__ __launch_bounds__(256) void k_layer0(const float* __restrict__ q,
                                                const float* __restrict__ W0,
                                                const float* __restrict__ b0)
{
    __shared__ float qs[32][8];
    const int j  = threadIdx.x;
    const int s0 = blockIdx.x * 32;
    for (int idx = threadIdx.x; idx < 32 * 7; idx += 256)
        qs[idx / 7][idx % 7] = q[(s0 + idx / 7) * 7 + idx % 7];
    float w[7];
#pragma unroll
    for (int i = 0; i < 7; i++) w[i] = W0[j * 7 + i];
    const float bb = b0[j];
    __syncthreads();
    for (int s = 0; s < 32; s++) {
        float pre = bb;
#pragma unroll
        for (int i = 0; i < 7; i++) pre = fmaf(w[i], qs[s][i], pre);
        const int b = s0 + s;
        g_h0h[b * HID + j] = __float2half_rn(sp_f(pre));
        const float sg = sg_f(pre);
#pragma unroll
        for (int t = 0; t < 7; t++)
            g_D0h[(size_t)(b * 7 + t) * HID + j] = __float2half_rn(sg * w[t]);
    }
}

// ---------------- val64: 2-term fp16 GEMM (A-hi x (Bh+Bl)), 128x64, 3 CTA/SM ---
// MODE 0: h0 @ W1^T + b1 -> h1 (hi), sig1
// MODE 2: h1 @ W2^T + b2 -> X2 (hi), sig2
// MODE 4: X2 @ WH^T + bH -> Yh value rows (transposed)
#define VA 10240u
#define VB 5120u
#define VSTG (VA + 2 * VB)    // 20480
#define VSM  (3 * VSTG)       // 61440 dynamic

template <int MODE>
__global__ __launch_bounds__(256, 3) void val64(const float* __restrict__ bias)
{
    extern __shared__ __align__(16) fp16 smv[];
    const uint32_t smb = smem_u32(smv);

    const int tid  = threadIdx.x;
    const int warp = tid >> 5, lane = tid & 31;
    const int wm = (warp >> 1) * 32;
    const int wn = (warp & 1) * 32;
    const int g  = lane >> 2, t4 = lane & 3;
    const size_t m_base = (size_t)blockIdx.y * 128;
    const int    n_base = blockIdx.x * 64;

    const fp16 *Ap, *Bh, *Bl;
    if      (MODE == 0) { Ap = g_h0h; Bh = g_W1h; Bl = g_W1l; }
    else if (MODE == 2) { Ap = g_h1h; Bh = g_W2h; Bl = g_W2l; }
    else                { Ap = g_X2h; Bh = g_WHh; Bl = g_WHl; }

    const uint32_t a_off = (uint32_t)(((wm + (lane & 15)) * SMS) + ((lane >> 4) << 3)) * 2;
    const uint32_t b_off = (uint32_t)(((wn + ((lane >> 4) << 3) + (lane & 7)) * SMS)
                                      + (((lane >> 3) & 1) << 3)) * 2;

    float acc[2][4][4];
#pragma unroll
    for (int a = 0; a < 2; a++)
#pragma unroll
        for (int b = 0; b < 4; b++)
#pragma unroll
            for (int c = 0; c < 4; c++) acc[a][b][c] = 0.0f;

#define VP(STAGE, KT)                                                           \
    {                                                                           \
        const uint32_t sb = smb + (STAGE) * VSTG;                               \
        {   const int u = tid;                                                  \
            cpa16(sb + (uint32_t)((u >> 2) * 80 + (u & 3) * 16),                \
                  Ap + (m_base + (u >> 2)) * HID + (KT) + (u & 3) * 8); }       \
        {   const int u = tid + 256;                                            \
            cpa16(sb + (uint32_t)((u >> 2) * 80 + (u & 3) * 16),                \
                  Ap + (m_base + (u >> 2)) * HID + (KT) + (u & 3) * 8); }       \
        {   const int u = tid;                                                  \
            const uint32_t d = sb + VA + (uint32_t)((u >> 2) * 80 + (u & 3) * 16); \
            const size_t so = (size_t)(n_base + (u >> 2)) * HID + (KT) + (u & 3) * 8; \
            cpa16(d,      Bh + so);                                             \
            cpa16(d + VB, Bl + so); }                                           \
        asm volatile("cp.async.commit_group;");                                 \
    }

    VP(0, 0)
    VP(1, 32)

#pragma unroll
    for (int it = 0; it < 8; it++) {
        if (it < 7) asm volatile("cp.async.wait_group 1;");
        else        asm volatile("cp.async.wait_group 0;");
        __syncthreads();
        if (it + 2 < 8) {
            const int st = (it + 2) % 3;
            VP(st, (it + 2) * 32)
        }

        const uint32_t sb = smb + (it % 3) * VSTG;
#pragma unroll
        for (int ks = 0; ks < 2; ks++) {
            const uint32_t kso = ks * 32;
            uint32_t ah[2][4];
            ldsm4(ah[0], sb + a_off + kso);
            ldsm4(ah[1], sb + a_off + kso + 16 * SMS * 2);
#pragma unroll
            for (int njp = 0; njp < 2; njp++) {
                uint32_t bh[4], bl[4];
                ldsm4(bh, sb + VA + b_off + njp * (16 * SMS * 2) + kso);
                ldsm4(bl, sb + VA + VB + b_off + njp * (16 * SMS * 2) + kso);
#pragma unroll
                for (int mi = 0; mi < 2; mi++) {
#pragma unroll
                    for (int s = 0; s < 2; s++) {
                        float* C = acc[mi][njp * 2 + s];
                        mma16816(C, ah[mi], bh[2 * s], bh[2 * s + 1]);
                        mma16816(C, ah[mi], bl[2 * s], bl[2 * s + 1]);
                    }
                }
            }
        }
    }
#undef VP

#pragma unroll
    for (int mi = 0; mi < 2; mi++) {
#pragma unroll
        for (int half = 0; half < 2; half++) {
            const size_t m = m_base + wm + mi * 16 + g + half * 8;
#pragma unroll
            for (int nj = 0; nj < 4; nj++) {
                const int col = n_base + wn + nj * 8 + t4 * 2;
#pragma unroll
                for (int e = 0; e < 2; e++) {
                    const float v = acc[mi][nj][half * 2 + e];
                    const int cc = col + e;
                    if (MODE == 0) {
                        const float pre = v + bias[cc];
                        const size_t o = m * HID + cc;
                        g_h1h[o] = __float2half_rn(sp_f(pre));
                        g_sig1[o] = sg_f(pre);
                    } else if (MODE == 2) {
                        const float pre = v + bias[cc];
                        const size_t o = m * HID + cc;
                        g_X2h[o] = __float2half_rn(sp_f(pre));
                        g_sig2[o] = sg_f(pre);
                    } else {
                        if (cc < NHEAD)
                            g_Yh[(size_t)cc * BATCH + m] = v + g_bH[cc];
                    }
                }
            }
        }
    }
}

// ---------------- tan64: 1-term fp16 GEMM, 128x64 tile, 3-stage, 3 CTA/SM ------
// MODE 1: D0 @ W1^T * sig1 -> D1
// MODE 3: D1 @ W2^T * sig2 -> T2
// MODE 5: T2 @ WHh^T -> Yh tangent rows (transposed)
#define TA 10240u
#define TB 5120u
#define TSTG2 (TA + TB)

template <int MODE>
__global__ __launch_bounds__(256, 3) void tan64()
{
    __shared__ __align__(16) fp16 sm[3 * TSTG2 / 2];
    const uint32_t smb = smem_u32(sm);

    const int tid  = threadIdx.x;
    const int warp = tid >> 5, lane = tid & 31;
    const int wm = (warp >> 1) * 32;
    const int wn = (warp & 1) * 32;
    const int g  = lane >> 2, t4 = lane & 3;
    const size_t m_base = (size_t)blockIdx.y * 128;
    const int    n_base = blockIdx.x * 64;

    const fp16* Dp = (MODE == 1) ? g_D0h : (MODE == 3) ? g_D1h : g_T2;
    const fp16* Wp = (MODE == 1) ? g_W1h : (MODE == 3) ? g_W2h : g_WHh;

    const uint32_t a_off = (uint32_t)(((wm + (lane & 15)) * SMS) + ((lane >> 4) << 3)) * 2;
    const uint32_t b_off = (uint32_t)(((wn + ((lane >> 4) << 3) + (lane & 7)) * SMS)
                                      + (((lane >> 3) & 1) << 3)) * 2;

    float acc[2][4][4];
#pragma unroll
    for (int a = 0; a < 2; a++)
#pragma unroll
        for (int b = 0; b < 4; b++)
#pragma unroll
            for (int c = 0; c < 4; c++) acc[a][b][c] = 0.0f;

#define TP(STAGE, KT)                                                           \
    {                                                                           \
        const uint32_t sb = smb + (STAGE) * TSTG2;                              \
        {   const int u = tid;                                                  \
            cpa16(sb + (uint32_t)((u >> 2) * 80 + (u & 3) * 16),                \
                  Dp + (m_base + (u >> 2)) * HID + (KT) + (u & 3) * 8); }       \
        {   const int u = tid + 256;                                            \
            cpa16(sb + (uint32_t)((u >> 2) * 80 + (u & 3) * 16),                \
                  Dp + (m_base + (u >> 2)) * HID + (KT) + (u & 3) * 8); }       \
        {   const int u = tid;                                                  \
            cpa16(sb + TA + (uint32_t)((u >> 2) * 80 + (u & 3) * 16),           \
                  Wp + (size_t)(n_base + (u >> 2)) * HID + (KT) + (u & 3) * 8); } \
        asm volatile("cp.async.commit_group;");                                 \
    }

    TP(0, 0)
    TP(1, 32)

#pragma unroll
    for (int it = 0; it < 8; it++) {
        if (it < 7) asm volatile("cp.async.wait_group 1;");
        else        asm volatile("cp.async.wait_group 0;");
        __syncthreads();
        if (it + 2 < 8) {
            const int st = (it + 2) % 3;
            TP(st, (it + 2) * 32)
        }

        const uint32_t sb = smb + (it % 3) * TSTG2;
#pragma unroll
        for (int ks = 0; ks < 2; ks++) {
            const uint32_t kso = ks * 32;
            uint32_t ah[2][4];
            ldsm4(ah[0], sb + a_off + kso);
            ldsm4(ah[1], sb + a_off + kso + 16 * SMS * 2);
#pragma unroll
            for (int njp = 0; njp < 2; njp++) {
                uint32_t bh[4];
                ldsm4(bh, sb + TA + b_off + njp * (16 * SMS * 2) + kso);
#pragma unroll
                for (int mi = 0; mi < 2; mi++) {
#pragma unroll
                    for (int s = 0; s < 2; s++)
                        mma16816(acc[mi][njp * 2 + s], ah[mi],
                                 bh[2 * s], bh[2 * s + 1]);
                }
            }
        }
    }
#undef TP

#pragma unroll
    for (int mi = 0; mi < 2; mi++) {
#pragma unroll
        for (int half = 0; half < 2; half++) {
            const size_t m = m_base + wm + mi * 16 + g + half * 8;
            const size_t mb = m / 7;
            const int    mt = (int)(m - mb * 7);
#pragma unroll
            for (int nj = 0; nj < 4; nj++) {
                const int col = wn + nj * 8 + t4 * 2;
#pragma unroll
                for (int e = 0; e < 2; e++) {
                    const float v = acc[mi][nj][half * 2 + e];
                    if (MODE == 1) {
                        const int cc = n_base + col + e;
                        g_D1h[m * HID + cc] =
                            __float2half_rn(v * g_sig1[mb * HID + cc]);
                    } else if (MODE == 3) {
                        const int cc = n_base + col + e;
                        g_T2[m * HID + cc] =
                            __float2half_rn(v * g_sig2[mb * HID + cc]);
                    } else {
                        const int r = col + e;
                        if (r < NHEAD)
                            g_Yh[(size_t)((1 + mt) * NHEAD + r) * BATCH + mb] = v;
                    }
                }
            }
        }
    }
}

// ---------------- K8: per-sample dynamics (flat triangular, coalesced Yh) ------
#define POS(i, j) ((i) * ((i) + 1) / 2 + (j))

__global__ __launch_bounds__(128) void k_dyn(const float* __restrict__ qd_g,
                                             const float* __restrict__ qdd_g,
                                             const float* __restrict__ fd,
                                             const float* __restrict__ fc,
                                             const float* __restrict__ fs,
                                             const float* __restrict__ fv,
                                             float* __restrict__ out)
{
    const int b = blockIdx.x * 128 + threadIdx.x;
    if (b >= BATCH) return;
    const int R[21]  = {1,2,2,3,3,3,4,4,4,4,5,5,5,5,5,6,6,6,6,6,6};
    const int Cc[21] = {0,0,1,0,1,2,0,1,2,3,0,1,2,3,4,0,1,2,3,4,5};

#define YH(row) g_Yh[(size_t)(row) * BATCH + b]

    float qd[7], qdd[7], gv[7], ldr[7], sigd[7];
#pragma unroll
    for (int i = 0; i < 7; i++) {
        qd[i]  = qd_g [b * 7 + i];
        qdd[i] = qdd_g[b * 7 + i];
        gv[i]  = YH(i);
        ldr[i] = YH(7 + i);
    }

    float Lf[28];
#pragma unroll
    for (int i = 0; i < 7; i++) {
        Lf[POS(i, i)] = sp_f(ldr[i]) + 1e-3f;
        sigd[i] = sg_f(ldr[i]);
    }
#pragma unroll
    for (int p = 0; p < 21; p++) Lf[POS(R[p], Cc[p])] = YH(14 + p);

    float a[7];
#pragma unroll
    for (int j = 0; j < 7; j++) {
        float s = 0.0f;
#pragma unroll
        for (int i = 0; i < 7; i++) if (i >= j) s = fmaf(Lf[POS(i, j)], qd[i], s);
        a[j] = s;
    }

    float Ldt[28];
#pragma unroll
    for (int f = 0; f < 28; f++) Ldt[f] = 0.0f;

    float svec[7];
#pragma unroll
    for (int c = 0; c < 7; c++) {
        const int base = (1 + c) * NHEAD;
        float dLf[28];
#pragma unroll
        for (int i = 0; i < 7; i++) dLf[POS(i, i)] = sigd[i] * YH(base + 7 + i);
#pragma unroll
        for (int p = 0; p < 21; p++) dLf[POS(R[p], Cc[p])] = YH(base + 14 + p);
#pragma unroll
        for (int f = 0; f < 28; f++) Ldt[f] = fmaf(qd[c], dLf[f], Ldt[f]);
        float sc = 0.0f;
#pragma unroll
        for (int j = 0; j < 7; j++) {
            float v = 0.0f;
#pragma unroll
            for (int i = 0; i < 7; i++) if (i >= j) v = fmaf(qd[i], dLf[POS(i, j)], v);
            sc = fmaf(v, a[j], sc);
        }
        svec[c] = 2.0f * sc;
    }
#undef YH

    float b2[7];
#pragma unroll
    for (int j = 0; j < 7; j++) {
        float s = 0.0f;
#pragma unroll
        for (int i = 0; i < 7; i++) if (i >= j) s = fmaf(Ldt[POS(i, j)], qd[i], s);
        b2[j] = s;
    }

    float cor[7];
#pragma unroll
    for (int i = 0; i < 7; i++) {
        float s = 0.0f;
#pragma unroll
        for (int j = 0; j < 7; j++) if (j <= i) s = fmaf(Lf[POS(i, j)], b2[j], s);
#pragma unroll
        for (int j = 0; j < 7; j++) if (j <= i) s = fmaf(Ldt[POS(i, j)], a[j], s);
        cor[i] = s - 0.5f * svec[i];
    }

    float Hmf[28];
#pragma unroll
    for (int i = 0; i < 7; i++)
#pragma unroll
        for (int k = 0; k < 7; k++) if (k <= i) {
            float s = 0.0f;
#pragma unroll
            for (int j = 0; j < 7; j++) if (j <= k)
                s = fmaf(Lf[POS(i, j)], Lf[POS(k, j)], s);
            Hmf[POS(i, k)] = s;
        }

    float fric[7];
#pragma unroll
    for (int i = 0; i < 7; i++) {
        const float fvc = fmaxf(fv[i], 1e-3f);
        fric[i] = (fc[i] + fs[i] * expf(-qd[i] * qd[i] / fvc)) *
                      tanhf(100.0f * qd[i]) + fd[i] * qd[i];
    }

    float tau[7];
#pragma unroll
    for (int i = 0; i < 7; i++) {
        float s = 0.0f;
#pragma unroll
        for (int k = 0; k < 7; k++) {
            const float h = (k <= i) ? Hmf[POS(i, k)] : Hmf[POS(k, i)];
            s = fmaf(h, qdd[k], s);
        }
        tau[i] = s + cor[i] + gv[i] + fric[i];
    }

    const int Bc = BATCH;
#pragma unroll
    for (int i = 0; i < 7; i++) out[b * 7 + i] = tau[i];
#pragma unroll
    for (int i = 0; i < 7; i++)
#pragma unroll
        for (int k = 0; k < 7; k++)
            out[7 * Bc + b * 49 + i * 7 + k] =
                (k <= i) ? Hmf[POS(i, k)] : Hmf[POS(k, i)];
#pragma unroll
    for (int i = 0; i < 7; i++) out[56 * Bc + b * 7 + i] = cor[i];
#pragma unroll
    for (int i = 0; i < 7; i++) out[63 * Bc + b * 7 + i] = gv[i];
#pragma unroll
    for (int i = 0; i < 7; i++) out[70 * Bc + b * 7 + i] = fric[i];
#pragma unroll
    for (int i = 0; i < 7; i++) out[77 * Bc + b * 7 + i] = ldr[i];
}

// ---------------- launch --------------------------------------------------------
extern "C" void kernel_launch(void* const* d_in, const int* in_sizes, int n_in,
                              void* d_out, int out_size)
{
    (void)in_sizes; (void)n_in; (void)out_size;
    const float* q   = (const float*)d_in[0];
    const float* qd  = (const float*)d_in[1];
    const float* qdd = (const float*)d_in[2];
    const float* W0  = (const float*)d_in[3];
    const float* b0  = (const float*)d_in[4];
    const float* W1  = (const float*)d_in[5];
    const float* b1  = (const float*)d_in[6];
    const float* W2  = (const float*)d_in[7];
    const float* b2  = (const float*)d_in[8];
    const float* Wg  = (const float*)d_in[9];
    const float* bg  = (const float*)d_in[10];
    const float* Wld = (const float*)d_in[11];
    const float* bld = (const float*)d_in[12];
    const float* Wlt = (const float*)d_in[13];
    const float* blt = (const float*)d_in[14];
    const float* fd  = (const float*)d_in[15];
    const float* fc  = (const float*)d_in[16];
    const float* fs  = (const float*)d_in[17];
    const float* fv  = (const float*)d_in[18];
    float* out = (float*)d_out;

    cudaFuncSetAttribute(val64<0>, cudaFuncAttributeMaxDynamicSharedMemorySize, VSM);
    cudaFuncSetAttribute(val64<2>, cudaFuncAttributeMaxDynamicSharedMemorySize, VSM);
    cudaFuncSetAttribute(val64<4>, cudaFuncAttributeMaxDynamicSharedMemorySize, VSM);

    k_wsplit<<<HID * HID / 256, 256>>>(W1, W2);
    k_whead<<<64, 256>>>(Wg, bg, Wld, bld, Wlt, blt);
    k_layer0<<<BATCH / 32, 256>>>(q, W0, b0);                        // h0 + D0
    val64<0><<<dim3(4, BATCH / 128), 256, VSM>>>(b1);                // h1, sig1
    tan64<1><<<dim3(4, (BATCH * 7) / 128), 256>>>();                 // D1
    val64<2><<<dim3(4, BATCH / 128), 256, VSM>>>(b2);                // X2, sig2
    tan64<3><<<dim3(4, (BATCH * 7) / 128), 256>>>();                 // T2
    val64<4><<<dim3(1, BATCH / 128), 256, VSM>>>(nullptr);           // value Yh
    tan64<5><<<dim3(1, (BATCH * 7) / 128), 256>>>();                 // tangent Yh
    k_dyn<<<(BATCH + 127) / 128, 128>>>(qd, qdd, fd, fc, fs, fv, out);
}